// round 9
// baseline (speedup 1.0000x reference)
#include <cuda_runtime.h>
#include <cuda_bf16.h>
#include <math.h>
#include <stdint.h>

#define BB 8
#define LL 512
#define DD 768
#define HH 12
#define DH 64
#define FF 3072
#define NL 6
#define NC 1
#define MM (BB*LL)   // 4096
#define NQKV 2304

typedef __nv_bfloat16 bf16;

// ---------------- scratch ----------------
__device__ float g_h[MM*DD];
__device__ bf16 g_xnh[MM*DD], g_xnl[MM*DD];
__device__ bf16 g_qkvh[MM*NQKV], g_qkvl[MM*NQKV];
__device__ bf16 g_aoh[MM*DD], g_aol[MM*DD];
__device__ bf16 g_ffh[MM*FF], g_ffl[MM*FF];
__device__ bf16 g_wqkvh[NL*NQKV*DD], g_wqkvl[NL*NQKV*DD];
__device__ bf16 g_woh[NL*DD*DD], g_wol[NL*DD*DD];
__device__ bf16 g_w1h[NL*DD*FF], g_w1l[NL*DD*FF];
__device__ bf16 g_w2h[NL*FF*DD], g_w2l[NL*FF*DD];

// ---------------- PTX helpers ----------------
__device__ __forceinline__ uint32_t smem_to_u32(const void* p) {
    uint32_t a;
    asm("{ .reg .u64 t; cvta.to.shared.u64 t, %1; cvt.u32.u64 %0, t; }" : "=r"(a) : "l"(p));
    return a;
}
__device__ __forceinline__ void cp_async16(uint32_t saddr, const void* gaddr) {
    asm volatile("cp.async.cg.shared.global [%0], [%1], 16;" :: "r"(saddr), "l"(gaddr) : "memory");
}
#define CP_COMMIT() asm volatile("cp.async.commit_group;" ::: "memory")
#define CP_WAIT1()  asm volatile("cp.async.wait_group 1;"  ::: "memory")
__device__ __forceinline__ void ldsm4(uint32_t* r, uint32_t a) {
    asm volatile("ldmatrix.sync.aligned.m8n8.x4.shared.b16 {%0,%1,%2,%3}, [%4];"
        : "=r"(r[0]), "=r"(r[1]), "=r"(r[2]), "=r"(r[3]) : "r"(a));
}
__device__ __forceinline__ void ldsm4t(uint32_t* r, uint32_t a) {
    asm volatile("ldmatrix.sync.aligned.m8n8.x4.trans.shared.b16 {%0,%1,%2,%3}, [%4];"
        : "=r"(r[0]), "=r"(r[1]), "=r"(r[2]), "=r"(r[3]) : "r"(a));
}
__device__ __forceinline__ void mma_bf16(float* c, const uint32_t* a, const uint32_t* b) {
    asm volatile("mma.sync.aligned.m16n8k16.row.col.f32.bf16.bf16.f32 "
        "{%0,%1,%2,%3}, {%4,%5,%6,%7}, {%8,%9}, {%0,%1,%2,%3};"
        : "+f"(c[0]), "+f"(c[1]), "+f"(c[2]), "+f"(c[3])
        : "r"(a[0]), "r"(a[1]), "r"(a[2]), "r"(a[3]), "r"(b[0]), "r"(b[1]));
}
__device__ __forceinline__ uint32_t packbb(bf16 a, bf16 b) {
    __nv_bfloat162 t; t.x = a; t.y = b; return *(uint32_t*)&t;
}

// ---------------- weight transpose + bf16 split (generic) ----------------
__global__ void tsplit_kernel(const float* __restrict__ W, bf16* __restrict__ Th,
                              bf16* __restrict__ Tl, int K, int N,
                              int roff, size_t out_ls) {
    __shared__ float s[32][33];
    int l = blockIdx.z;
    const float* Wl = W + (size_t)l * K * N;
    bf16* Thl = Th + (size_t)l * out_ls;
    bf16* Tll = Tl + (size_t)l * out_ls;
    int n0 = blockIdx.x * 32, k0 = blockIdx.y * 32;
    int tx = threadIdx.x, ty = threadIdx.y;
    #pragma unroll
    for (int j = 0; j < 4; j++)
        s[ty + 8*j][tx] = Wl[(size_t)(k0 + ty + 8*j) * N + n0 + tx];
    __syncthreads();
    #pragma unroll
    for (int j = 0; j < 4; j++) {
        int row = ty + 8*j;
        float v = s[tx][row];
        bf16 hi = __float2bfloat16(v);
        bf16 lo = __float2bfloat16(v - __bfloat162float(hi));
        size_t idx = (size_t)(roff + n0 + row) * K + k0 + tx;
        Thl[idx] = hi; Tll[idx] = lo;
    }
}

// merged QKV tsplit
__global__ void tsplit_qkv(const float* __restrict__ Wq, const float* __restrict__ Wk,
                           const float* __restrict__ Wv,
                           bf16* __restrict__ Th, bf16* __restrict__ Tl) {
    __shared__ float s[32][33];
    int z = blockIdx.z;
    int l = z / 3, which = z % 3;
    const float* W = (which == 0) ? Wq : (which == 1) ? Wk : Wv;
    const float* Wl = W + (size_t)l * DD * DD;
    size_t out_ls = (size_t)NQKV * DD;
    bf16* Thl = Th + (size_t)l * out_ls;
    bf16* Tll = Tl + (size_t)l * out_ls;
    int roff = which * DD;
    int n0 = blockIdx.x * 32, k0 = blockIdx.y * 32;
    int tx = threadIdx.x, ty = threadIdx.y;
    #pragma unroll
    for (int j = 0; j < 4; j++)
        s[ty + 8*j][tx] = Wl[(size_t)(k0 + ty + 8*j) * DD + n0 + tx];
    __syncthreads();
    #pragma unroll
    for (int j = 0; j < 4; j++) {
        int row = ty + 8*j;
        float v = s[tx][row];
        bf16 hi = __float2bfloat16(v);
        bf16 lo = __float2bfloat16(v - __bfloat162float(hi));
        size_t idx = (size_t)(roff + n0 + row) * DD + k0 + tx;
        Thl[idx] = hi; Tll[idx] = lo;
    }
}

// ---------------- embedding + positional encoding ----------------
__global__ void embed_kernel(const int* __restrict__ x, const float* __restrict__ emb,
                             float* __restrict__ out) {
    int r = blockIdx.x;
    int b = r / LL;
    int tok = x[r];
    const float* erow = emb + (size_t)tok * DD;
    float* orow = out + (size_t)r * DD;
    const float neg_log = -logf(10000.0f) / (float)DD;
    for (int j = 0; j < 3; j++) {
        int d = threadIdx.x + j * 256;
        int i2 = (d >> 1) << 1;
        float div = expf((float)i2 * neg_log);
        float ang = (float)b * div;
        float pe = (d & 1) ? cosf(ang) : sinf(ang);
        orow[d] = erow[d] + pe;
    }
}

// ---------------- layernorm -> bf16 hi/lo ----------------
__global__ void ln_kernel(const float* __restrict__ in, const float* __restrict__ g,
                          const float* __restrict__ be,
                          bf16* __restrict__ oh, bf16* __restrict__ ol) {
    __shared__ float red[256];
    int r = blockIdx.x;
    int t = threadIdx.x;
    const float* xr = in + (size_t)r * DD;
    float v0 = xr[t], v1 = xr[t + 256], v2 = xr[t + 512];
    red[t] = v0 + v1 + v2;
    __syncthreads();
    for (int o = 128; o > 0; o >>= 1) { if (t < o) red[t] += red[t + o]; __syncthreads(); }
    float mean = red[0] * (1.0f / (float)DD);
    __syncthreads();
    float d0 = v0 - mean, d1 = v1 - mean, d2 = v2 - mean;
    red[t] = d0 * d0 + d1 * d1 + d2 * d2;
    __syncthreads();
    for (int o = 128; o > 0; o >>= 1) { if (t < o) red[t] += red[t + o]; __syncthreads(); }
    float var = red[0] * (1.0f / (float)DD);
    float rs = rsqrtf(var + 1e-5f);
    size_t base = (size_t)r * DD;
    float outs[3] = { d0 * rs * g[t] + be[t],
                      d1 * rs * g[t + 256] + be[t + 256],
                      d2 * rs * g[t + 512] + be[t + 512] };
    #pragma unroll
    for (int j = 0; j < 3; j++) {
        float v = outs[j];
        bf16 hi = __float2bfloat16(v);
        oh[base + t + 256*j] = hi;
        ol[base + t + 256*j] = __float2bfloat16(v - __bfloat162float(hi));
    }
}

// ---------------- HMMA GEMM: 128x64 CTA tile, 3-stage, early loads + full fragment preload ----------------
// op: 0 = store fp32 (+bias), 1 = GELU -> bf16 hi/lo, 2 = residual add fp32, 3 = store bf16 hi/lo
#define STG_BYTES 30720
#define AL_OFF 10240
#define BH_OFF 20480
#define BL_OFF 25600
#define NSTG 3
#define GEMM_SMEM (NSTG*STG_BYTES)

__global__ __launch_bounds__(256, 2) void gemm_mma(
    const bf16* __restrict__ Ah, const bf16* __restrict__ Al,
    const bf16* __restrict__ Bh, const bf16* __restrict__ Bl,
    const float* __restrict__ bias0, const float* __restrict__ bias1,
    const float* __restrict__ bias2,
    float* __restrict__ C, bf16* __restrict__ Oh, bf16* __restrict__ Ol,
    int Ntot, int Ktot, int op)
{
    extern __shared__ char dsmem[];
    uint32_t smem_u = smem_to_u32(dsmem);
    int tid = threadIdx.x;
    int lane = tid & 31;
    int wid = tid >> 5;
    int wm = wid & 3;
    int wn = wid >> 2;
    int bm = blockIdx.y * 128, bn = blockIdx.x * 64;

    uint32_t a_off = (uint32_t)((wm*32 + (lane & 15)) * 80 + 16 * (lane >> 4));
    uint32_t b_off = (uint32_t)((wn*32 + 8*((lane >> 4) & 1) + (lane & 7)) * 80
                                + 16 * ((lane >> 3) & 1));

    int arow0 = tid >> 2,         ac0 = (tid & 3);
    int arow1 = (tid + 256) >> 2, ac1 = ((tid + 256) & 3);
    int brow  = tid >> 2,         bc  = (tid & 3);

    float acc[2][4][4];
    #pragma unroll
    for (int i = 0; i < 2; i++)
        #pragma unroll
        for (int j = 0; j < 4; j++)
            #pragma unroll
            for (int q = 0; q < 4; q++) acc[i][j][q] = 0.0f;

    int iters = Ktot >> 5;

    #define LOAD_STAGE(it, buf) do { \
        int k0 = (it) << 5; \
        uint32_t sb = smem_u + (buf) * STG_BYTES; \
        cp_async16(sb + arow0*80 + ac0*16,           Ah + (size_t)(bm + arow0) * Ktot + k0 + ac0*8); \
        cp_async16(sb + AL_OFF + arow0*80 + ac0*16,  Al + (size_t)(bm + arow0) * Ktot + k0 + ac0*8); \
        cp_async16(sb + arow1*80 + ac1*16,           Ah + (size_t)(bm + arow1) * Ktot + k0 + ac1*8); \
        cp_async16(sb + AL_OFF + arow1*80 + ac1*16,  Al + (size_t)(bm + arow1) * Ktot + k0 + ac1*8); \
        cp_async16(sb + BH_OFF + brow*80 + bc*16,    Bh + (size_t)(bn + brow) * Ktot + k0 + bc*8); \
        cp_async16(sb + BL_OFF + brow*80 + bc*16,    Bl + (size_t)(bn + brow) * Ktot + k0 + bc*8); \
    } while (0)

    LOAD_STAGE(0, 0); CP_COMMIT();
    LOAD_STAGE(1, 1); CP_COMMIT();

    int buf = 0;
    for (int it = 0; it < iters; it++) {
        CP_WAIT1();
        __syncthreads();
        // (1) issue next-stage loads FIRST — target buffer's readers were fenced by the sync above
        int ldbuf = buf + 2; if (ldbuf >= NSTG) ldbuf -= NSTG;
        if (it + 2 < iters) LOAD_STAGE(it + 2, ldbuf);
        CP_COMMIT();

        uint32_t sA  = smem_u + buf * STG_BYTES;
        uint32_t sAl = sA + AL_OFF;
        uint32_t sBh = sA + BH_OFF;
        uint32_t sBl = sA + BL_OFF;

        // (2) preload fragments for BOTH k-steps, then run MMAs — ks=1 LDSM latency
        // hides under ks=0 MMA work.
        uint32_t ah[2][2][4], al[2][2][4], bh[2][2][4], bl[2][2][4];
        #pragma unroll
        for (int ks = 0; ks < 2; ks++) {
            #pragma unroll
            for (int tm = 0; tm < 2; tm++) {
                ldsm4(ah[ks][tm], sA  + a_off + tm*1280 + ks*32);
                ldsm4(al[ks][tm], sAl + a_off + tm*1280 + ks*32);
            }
            #pragma unroll
            for (int p = 0; p < 2; p++) {
                ldsm4(bh[ks][p], sBh + b_off + p*1280 + ks*32);
                ldsm4(bl[ks][p], sBl + b_off + p*1280 + ks*32);
            }
        }
        #pragma unroll
        for (int ks = 0; ks < 2; ks++) {
            #pragma unroll
            for (int tm = 0; tm < 2; tm++)
                #pragma unroll
                for (int p = 0; p < 2; p++) {
                    mma_bf16(acc[tm][2*p],   ah[ks][tm], &bh[ks][p][0]);
                    mma_bf16(acc[tm][2*p+1], ah[ks][tm], &bh[ks][p][2]);
                }
            #pragma unroll
            for (int tm = 0; tm < 2; tm++)
                #pragma unroll
                for (int p = 0; p < 2; p++) {
                    mma_bf16(acc[tm][2*p],   ah[ks][tm], &bl[ks][p][0]);
                    mma_bf16(acc[tm][2*p+1], ah[ks][tm], &bl[ks][p][2]);
                }
            #pragma unroll
            for (int tm = 0; tm < 2; tm++)
                #pragma unroll
                for (int p = 0; p < 2; p++) {
                    mma_bf16(acc[tm][2*p],   al[ks][tm], &bh[ks][p][0]);
                    mma_bf16(acc[tm][2*p+1], al[ks][tm], &bh[ks][p][2]);
                }
        }
        buf = (buf + 1 == NSTG) ? 0 : buf + 1;
    }
    #undef LOAD_STAGE

    // segmented bias (QKV fused projection)
    const float* beff = bias0;
    int boff = 0;
    if (bias1 != nullptr) {
        if (bn >= 1536)      { beff = bias2; boff = 1536; }
        else if (bn >= 768)  { beff = bias1; boff = 768;  }
    }

    int m_base = bm + wm*32 + (lane >> 2);
    int n_base = bn + wn*32 + (lane & 3)*2;
    #pragma unroll
    for (int tm = 0; tm < 2; tm++) {
        #pragma unroll
        for (int tn = 0; tn < 4; tn++) {
            #pragma unroll
            for (int half = 0; half < 2; half++) {
                int m = m_base + tm*16 + half*8;
                int n = n_base + tn*8;
                float v0 = acc[tm][tn][2*half]     + beff[n - boff];
                float v1 = acc[tm][tn][2*half + 1] + beff[n + 1 - boff];
                size_t idx = (size_t)m * Ntot + n;
                if (op == 1) {
                    float gv0 = 0.5f * v0 * (1.0f + erff(v0 * 0.70710678118654752f));
                    float gv1 = 0.5f * v1 * (1.0f + erff(v1 * 0.70710678118654752f));
                    bf16 h0 = __float2bfloat16(gv0), h1 = __float2bfloat16(gv1);
                    *(uint32_t*)(Oh + idx) = packbb(h0, h1);
                    *(uint32_t*)(Ol + idx) = packbb(
                        __float2bfloat16(gv0 - __bfloat162float(h0)),
                        __float2bfloat16(gv1 - __bfloat162float(h1)));
                } else if (op == 2) {
                    C[idx]     += v0;
                    C[idx + 1] += v1;
                } else if (op == 3) {
                    bf16 h0 = __float2bfloat16(v0), h1 = __float2bfloat16(v1);
                    *(uint32_t*)(Oh + idx) = packbb(h0, h1);
                    *(uint32_t*)(Ol + idx) = packbb(
                        __float2bfloat16(v0 - __bfloat162float(h0)),
                        __float2bfloat16(v1 - __bfloat162float(h1)));
                } else {
                    C[idx]     = v0;
                    C[idx + 1] = v1;
                }
            }
        }
    }
}

// ---------------- tensor-core fused attention ----------------
#define SSTR 520
#define OFF_Q  (64*SSTR*4)
#define OFF_QL (OFF_Q + 9216)
#define OFF_K  (OFF_QL + 9216)
#define OFF_KL (OFF_K + 18432)
#define ATTN_SMEM (OFF_KL + 18432)

__global__ __launch_bounds__(256) void attn_tc(
    const bf16* __restrict__ QKVh, const bf16* __restrict__ QKVl,
    const int* __restrict__ mask, float* __restrict__ attn_out,
    bf16* __restrict__ aoh, bf16* __restrict__ aol)
{
    extern __shared__ char sm[];
    float* S = (float*)sm;
    uint32_t su = smem_to_u32(sm);
    int tid = threadIdx.x, lane = tid & 31, wid = tid >> 5;
    int q0 = blockIdx.x * 64;
    int h = blockIdx.y, b = blockIdx.z;

    {
        int r = tid >> 2, c = tid & 3;
        size_t g = ((size_t)(b*LL + q0 + r)) * NQKV + h*DH;
        const uint4* gh = (const uint4*)(QKVh + g);
        const uint4* gl = (const uint4*)(QKVl + g);
        *(uint4*)(sm + OFF_Q  + r*144 + c*16)     = gh[c];
        *(uint4*)(sm + OFF_Q  + r*144 + (c+4)*16) = gh[c+4];
        *(uint4*)(sm + OFF_QL + r*144 + c*16)     = gl[c];
        *(uint4*)(sm + OFF_QL + r*144 + (c+4)*16) = gl[c+4];
    }

    int wm = wid & 1, wn = wid >> 1;

    for (int kc = 0; kc < 4; kc++) {
        {
            int r = tid >> 1, c0 = (tid & 1) * 4;
            size_t g = ((size_t)(b*LL + kc*128 + r)) * NQKV + 768 + h*DH;
            const uint4* gh = (const uint4*)(QKVh + g);
            const uint4* gl = (const uint4*)(QKVl + g);
            #pragma unroll
            for (int c = 0; c < 4; c++) {
                *(uint4*)(sm + OFF_K  + r*144 + (c0+c)*16) = gh[c0+c];
                *(uint4*)(sm + OFF_KL + r*144 + (c0+c)*16) = gl[c0+c];
            }
        }
        __syncthreads();
        float acc[2][4][4];
        #pragma unroll
        for (int i = 0; i < 2; i++)
            #pragma unroll
            for (int j = 0; j < 4; j++)
                #pragma unroll
                for (int q = 0; q < 4; q++) acc[i][j][q] = 0.0f;
        uint32_t aoff = (uint32_t)((wm*32 + (lane & 15)) * 144 + 16 * (lane >> 4));
        uint32_t boff = (uint32_t)((wn*32 + 8*((lane >> 4) & 1) + (lane & 7)) * 144
                                   + 16 * ((lane >> 3) & 1));
        #pragma unroll
        for (int ki = 0; ki < 4; ki++) {
            uint32_t ah[2][4], al[2][4], bh[2][4], bl[2][4];
            #pragma unroll
            for (int tm = 0; tm < 2; tm++) {
                ldsm4(ah[tm], su + OFF_Q  + aoff + tm*2304 + ki*32);
                ldsm4(al[tm], su + OFF_QL + aoff + tm*2304 + ki*32);
            }
            #pragma unroll
            for (int p = 0; p < 2; p++) {
                ldsm4(bh[p], su + OFF_K  + boff + p*2304 + ki*32);
                ldsm4(bl[p], su + OFF_KL + boff + p*2304 + ki*32);
            }
            #pragma unroll
            for (int tm = 0; tm < 2; tm++)
                #pragma unroll
                for (int p = 0; p < 2; p++) {
                    mma_bf16(acc[tm][2*p],   ah[tm], &bh[p][0]);
                    mma_bf16(acc[tm][2*p+1], ah[tm], &bh[p][2]);
                }
            #pragma unroll
            for (int tm = 0; tm < 2; tm++)
                #pragma unroll
                for (int p = 0; p < 2; p++) {
                    mma_bf16(acc[tm][2*p],   ah[tm], &bl[p][0]);
                    mma_bf16(acc[tm][2*p+1], ah[tm], &bl[p][2]);
                }
            #pragma unroll
            for (int tm = 0; tm < 2; tm++)
                #pragma unroll
                for (int p = 0; p < 2; p++) {
                    mma_bf16(acc[tm][2*p],   al[tm], &bh[p][0]);
                    mma_bf16(acc[tm][2*p+1], al[tm], &bh[p][2]);
                }
        }
        #pragma unroll
        for (int tm = 0; tm < 2; tm++) {
            #pragma unroll
            for (int tn = 0; tn < 4; tn++) {
                int row = wm*32 + tm*16 + (lane >> 2);
                int col = kc*128 + wn*32 + tn*8 + (lane & 3)*2;
                int m0 = mask[b*LL + col], m1 = mask[b*LL + col + 1];
                #pragma unroll
                for (int half = 0; half < 2; half++) {
                    int rr = row + half*8;
                    float v0 = acc[tm][tn][2*half]   * 0.125f - 0.01f * (float)((q0 + rr) - col);
                    float v1 = acc[tm][tn][2*half+1] * 0.125f - 0.01f * (float)((q0 + rr) - (col+1));
                    if (m0 == 0) v0 = -INFINITY;
                    if (m1 == 0) v1 = -INFINITY;
                    S[rr*SSTR + col]     = v0;
                    S[rr*SSTR + col + 1] = v1;
                }
            }
        }
        __syncthreads();
    }

    {
        size_t gbase0 = ((size_t)(b*HH + h) * LL + q0) * LL;
        #pragma unroll
        for (int j = 0; j < 8; j++) {
            int r = wid*8 + j;
            float4 e[4];
            #pragma unroll
            for (int i = 0; i < 4; i++) e[i] = *(float4*)&S[r*SSTR + i*128 + lane*4];
            float mx = -1e30f;
            #pragma unroll
            for (int i = 0; i < 4; i++)
                mx = fmaxf(mx, fmaxf(fmaxf(e[i].x, e[i].y), fmaxf(e[i].z, e[i].w)));
            #pragma unroll
            for (int o = 16; o > 0; o >>= 1) mx = fmaxf(mx, __shfl_xor_sync(0xFFFFFFFFu, mx, o));
            float sum = 0.0f;
            #pragma unroll
            for (int i = 0; i < 4; i++) {
                e[i].x = __expf(e[i].x - mx); e[i].y = __expf(e[i].y - mx);
                e[i].z = __expf(e[i].z - mx); e[i].w = __expf(e[i].w - mx);
                sum += e[i].x + e[i].y + e[i].z + e[i].w;
            }
            #pragma unroll
            for (int o = 16; o > 0; o >>= 1) sum += __shfl_xor_sync(0xFFFFFFFFu, sum, o);
            float inv = 1.0f / sum;
            float* gp = attn_out + gbase0 + (size_t)r * LL;
            #pragma unroll
            for (int i = 0; i < 4; i++) {
                e[i].x *= inv; e[i].y *= inv; e[i].z *= inv; e[i].w *= inv;
                *(float4*)&S[r*SSTR + i*128 + lane*4] = e[i];
                *(float4*)(gp + i*128 + lane*4) = e[i];
            }
        }
    }
    __syncthreads();

    float oa[2][2][4];
    #pragma unroll
    for (int i = 0; i < 2; i++)
        #pragma unroll
        for (int j = 0; j < 2; j++)
            #pragma unroll
            for (int q = 0; q < 4; q++) oa[i][j][q] = 0.0f;

    for (int kc = 0; kc < 8; kc++) {
        {
            int r = tid >> 2, c0 = (tid & 3) * 16;
            #pragma unroll
            for (int jj = 0; jj < 2; jj++) {
                const float* sp = &S[r*SSTR + kc*64 + c0 + jj*8];
                float v[8];
                *(float4*)&v[0] = *(const float4*)sp;
                *(float4*)&v[4] = *(const float4*)(sp + 4);
                uint32_t hw[4], lw[4];
                #pragma unroll
                for (int q = 0; q < 4; q++) {
                    bf16 ha = __float2bfloat16(v[2*q]), hb = __float2bfloat16(v[2*q+1]);
                    hw[q] = packbb(ha, hb);
                    lw[q] = packbb(__float2bfloat16(v[2*q]   - __bfloat162float(ha)),
                                   __float2bfloat16(v[2*q+1] - __bfloat162float(hb)));
                }
                *(uint4*)(sm + OFF_Q  + r*144 + (c0 + jj*8)*2) = *(uint4*)hw;
                *(uint4*)(sm + OFF_QL + r*144 + (c0 + jj*8)*2) = *(uint4*)lw;
            }
        }
        {
            int r = tid >> 2, c = tid & 3;
            size_t g = ((size_t)(b*LL + kc*64 + r)) * NQKV + 1536 + h*DH;
            const uint4* gh = (const uint4*)(QKVh + g);
            const uint4* gl = (const uint4*)(QKVl + g);
            *(uint4*)(sm + OFF_K  + r*144 + c*16)     = gh[c];
            *(uint4*)(sm + OFF_K  + r*144 + (c+4)*16) = gh[c+4];
            *(uint4*)(sm + OFF_KL + r*144 + c*16)     = gl[c];
            *(uint4*)(sm + OFF_KL + r*144 + (c+4)*16) = gl[c+4];
        }
        __syncthreads();
        uint32_t poff = (uint32_t)((wm*32 + (lane & 15)) * 144 + 16 * (lane >> 4));
        uint32_t voff = (uint32_t)((lane & 15) * 144 + wn*32 + 16 * (lane >> 4));
        #pragma unroll
        for (int ki = 0; ki < 4; ki++) {
            uint32_t ph[2][4], pl[2][4], vh[4], vl[4];
            #pragma unroll
            for (int tm = 0; tm < 2; tm++) {
                ldsm4(ph[tm], su + OFF_Q  + poff + tm*2304 + ki*32);
                ldsm4(pl[tm], su + OFF_QL + poff + tm*2304 + ki*32);
            }
            ldsm4t(vh, su + OFF_K  + voff + ki*2304);
            ldsm4t(vl, su + OFF_KL + voff + ki*2304);
            #pragma unroll
            for (int tm = 0; tm < 2; tm++)
                #pragma unroll
                for (int tn = 0; tn < 2; tn++)
                    mma_bf16(oa[tm][tn], ph[tm], &vh[2*tn]);
            #pragma unroll
            for (int tm = 0; tm < 2; tm++)
                #pragma unroll
                for (int tn = 0; tn < 2; tn++)
                    mma_bf16(oa[tm][tn], ph[tm], &vl[2*tn]);
            #pragma unroll
            for (int tm = 0; tm < 2; tm++)
                #pragma unroll
                for (int tn = 0; tn < 2; tn++)
                    mma_bf16(oa[tm][tn], pl[tm], &vh[2*tn]);
        }
        __syncthreads();
    }

    #pragma unroll
    for (int tm = 0; tm < 2; tm++) {
        #pragma unroll
        for (int tn = 0; tn < 2; tn++) {
            #pragma unroll
            for (int half = 0; half < 2; half++) {
                int row = wm*32 + tm*16 + (lane >> 2) + half*8;
                int col = wn*16 + tn*8 + (lane & 3)*2;
                float v0 = oa[tm][tn][2*half], v1 = oa[tm][tn][2*half+1];
                size_t g = ((size_t)(b*LL + q0 + row)) * DD + h*DH + col;
                bf16 h0 = __float2bfloat16(v0), h1 = __float2bfloat16(v1);
                *(uint32_t*)(aoh + g) = packbb(h0, h1);
                *(uint32_t*)(aol + g) = packbb(
                    __float2bfloat16(v0 - __bfloat162float(h0)),
                    __float2bfloat16(v1 - __bfloat162float(h1)));
            }
        }
    }
}

// ---------------- classifier head ----------------
__global__ void logits_kernel(const float* __restrict__ h, const float* __restrict__ Wc,
                              const float* __restrict__ bc, float* __restrict__ out) {
    __shared__ float red[256];
    int b = blockIdx.x;
    int t = threadIdx.x;
    float s = 0.0f;
    for (int d = t; d < DD; d += 256) s += h[(size_t)b * LL * DD + d] * Wc[d * NC];
    red[t] = s; __syncthreads();
    for (int o = 128; o > 0; o >>= 1) { if (t < o) red[t] += red[t + o]; __syncthreads(); }
    if (t == 0) out[b * NC] = red[0] + bc[0];
}

// ---------------- launcher ----------------
extern "C" void kernel_launch(void* const* d_in, const int* in_sizes, int n_in,
                              void* d_out, int out_size) {
    const int*   x    = (const int*)  d_in[0];
    const int*   mask = (const int*)  d_in[1];
    const float* emb  = (const float*)d_in[2];
    const float* Wq   = (const float*)d_in[3];
    const float* bq   = (const float*)d_in[4];
    const float* Wk   = (const float*)d_in[5];
    const float* bk   = (const float*)d_in[6];
    const float* Wv   = (const float*)d_in[7];
    const float* bv   = (const float*)d_in[8];
    const float* Wo   = (const float*)d_in[9];
    const float* bo   = (const float*)d_in[10];
    const float* W1   = (const float*)d_in[11];
    const float* b1   = (const float*)d_in[12];
    const float* W2   = (const float*)d_in[13];
    const float* b2   = (const float*)d_in[14];
    const float* g1   = (const float*)d_in[15];
    const float* be1  = (const float*)d_in[16];
    const float* g2   = (const float*)d_in[17];
    const float* be2  = (const float*)d_in[18];
    const float* Wc   = (const float*)d_in[19];
    const float* bc   = (const float*)d_in[20];

    float* out = (float*)d_out;
    float* logits = out;
    float* attn_base = out + (size_t)BB * NC;

    static bool attr_set = false;
    if (!attr_set) {
        cudaFuncSetAttribute(gemm_mma, cudaFuncAttributeMaxDynamicSharedMemorySize, GEMM_SMEM);
        cudaFuncSetAttribute(attn_tc, cudaFuncAttributeMaxDynamicSharedMemorySize, ATTN_SMEM);
        attr_set = true;
    }

    float *p_h;
    bf16 *p_xnh, *p_xnl, *p_qkvh, *p_qkvl, *p_aoh, *p_aol, *p_ffh, *p_ffl;
    bf16 *p_wqkvh, *p_wqkvl, *p_woh, *p_wol, *p_w1h, *p_w1l, *p_w2h, *p_w2l;
    cudaGetSymbolAddress((void**)&p_h, g_h);
    cudaGetSymbolAddress((void**)&p_xnh, g_xnh); cudaGetSymbolAddress((void**)&p_xnl, g_xnl);
    cudaGetSymbolAddress((void**)&p_qkvh, g_qkvh); cudaGetSymbolAddress((void**)&p_qkvl, g_qkvl);
    cudaGetSymbolAddress((void**)&p_aoh, g_aoh); cudaGetSymbolAddress((void**)&p_aol, g_aol);
    cudaGetSymbolAddress((void**)&p_ffh, g_ffh); cudaGetSymbolAddress((void**)&p_ffl, g_ffl);
    cudaGetSymbolAddress((void**)&p_wqkvh, g_wqkvh); cudaGetSymbolAddress((void**)&p_wqkvl, g_wqkvl);
    cudaGetSymbolAddress((void**)&p_woh, g_woh); cudaGetSymbolAddress((void**)&p_wol, g_wol);
    cudaGetSymbolAddress((void**)&p_w1h, g_w1h); cudaGetSymbolAddress((void**)&p_w1l, g_w1l);
    cudaGetSymbolAddress((void**)&p_w2h, g_w2h); cudaGetSymbolAddress((void**)&p_w2l, g_w2l);

    dim3 tb(32, 8);
    size_t olsQKV = (size_t)NQKV * DD;

    dim3 gD(DD/64, MM/128);
    dim3 gQKV(NQKV/64, MM/128);
    dim3 gF(FF/64, MM/128);
    dim3 gAttn(LL/64, HH, BB);

    // Launch order: 1 tsplit_qkv, 2 embed, 3 ln, 4 gemm(QKV) <- ncu capture slot
    tsplit_qkv<<<dim3(DD/32, DD/32, NL*3), tb>>>(Wq, Wk, Wv, p_wqkvh, p_wqkvl);
    embed_kernel<<<MM, 256>>>(x, emb, p_h);

    for (int l = 0; l < NL; l++) {
        size_t wD = (size_t)l * DD * DD;
        size_t wF = (size_t)l * DD * FF;
        size_t wQ = (size_t)l * olsQKV;
        ln_kernel<<<MM, 256>>>(p_h, g1 + l*DD, be1 + l*DD, p_xnh, p_xnl);
        gemm_mma<<<gQKV, 256, GEMM_SMEM>>>(p_xnh, p_xnl, p_wqkvh + wQ, p_wqkvl + wQ,
                                           bq + l*DD, bk + l*DD, bv + l*DD,
                                           nullptr, p_qkvh, p_qkvl, NQKV, DD, 3);
        if (l == 0) {
            tsplit_kernel<<<dim3(DD/32, DD/32, NL), tb>>>(Wo, p_woh, p_wol, DD, DD, 0, (size_t)DD*DD);
            tsplit_kernel<<<dim3(FF/32, DD/32, NL), tb>>>(W1, p_w1h, p_w1l, DD, FF, 0, (size_t)DD*FF);
            tsplit_kernel<<<dim3(DD/32, FF/32, NL), tb>>>(W2, p_w2h, p_w2l, FF, DD, 0, (size_t)FF*DD);
        }
        attn_tc<<<gAttn, 256, ATTN_SMEM>>>(p_qkvh, p_qkvl, mask,
                                           attn_base + (size_t)l * BB * HH * LL * LL, p_aoh, p_aol);
        gemm_mma<<<gD, 256, GEMM_SMEM>>>(p_aoh, p_aol, p_woh + wD, p_wol + wD,
                                         bo + l*DD, nullptr, nullptr,
                                         p_h, nullptr, nullptr, DD, DD, 2);
        ln_kernel<<<MM, 256>>>(p_h, g2 + l*DD, be2 + l*DD, p_xnh, p_xnl);
        gemm_mma<<<gF, 256, GEMM_SMEM>>>(p_xnh, p_xnl, p_w1h + wF, p_w1l + wF,
                                         b1 + l*FF, nullptr, nullptr,
                                         nullptr, p_ffh, p_ffl, FF, DD, 1);
        gemm_mma<<<gD, 256, GEMM_SMEM>>>(p_ffh, p_ffl, p_w2h + wF, p_w2l + wF,
                                         b2 + l*DD, nullptr, nullptr,
                                         p_h, nullptr, nullptr, DD, FF, 2);
    }

    logits_kernel<<<BB, 256>>>(p_h, Wc, bc, logits);
}

// round 10
// speedup vs baseline: 1.0132x; 1.0132x over previous
#include <cuda_runtime.h>
#include <cuda_bf16.h>
#include <math.h>
#include <stdint.h>

#define BB 8
#define LL 512
#define DD 768
#define HH 12
#define DH 64
#define FF 3072
#define NL 6
#define NC 1
#define MM (BB*LL)   // 4096
#define NQKV 2304

typedef __nv_bfloat16 bf16;

// ---------------- scratch ----------------
__device__ float g_h[MM*DD];
__device__ bf16 g_xnh[MM*DD], g_xnl[MM*DD];
__device__ bf16 g_qkvh[MM*NQKV], g_qkvl[MM*NQKV];
__device__ bf16 g_aoh[MM*DD], g_aol[MM*DD];
__device__ bf16 g_ffh[MM*FF], g_ffl[MM*FF];
__device__ bf16 g_wqkvh[NL*NQKV*DD], g_wqkvl[NL*NQKV*DD];
__device__ bf16 g_woh[NL*DD*DD], g_wol[NL*DD*DD];
__device__ bf16 g_w1h[NL*DD*FF], g_w1l[NL*DD*FF];
__device__ bf16 g_w2h[NL*FF*DD], g_w2l[NL*FF*DD];

// ---------------- PTX helpers ----------------
__device__ __forceinline__ uint32_t smem_to_u32(const void* p) {
    uint32_t a;
    asm("{ .reg .u64 t; cvta.to.shared.u64 t, %1; cvt.u32.u64 %0, t; }" : "=r"(a) : "l"(p));
    return a;
}
__device__ __forceinline__ void cp_async16(uint32_t saddr, const void* gaddr) {
    asm volatile("cp.async.cg.shared.global [%0], [%1], 16;" :: "r"(saddr), "l"(gaddr) : "memory");
}
#define CP_COMMIT() asm volatile("cp.async.commit_group;" ::: "memory")
#define CP_WAIT1()  asm volatile("cp.async.wait_group 1;"  ::: "memory")
__device__ __forceinline__ void ldsm4(uint32_t* r, uint32_t a) {
    asm volatile("ldmatrix.sync.aligned.m8n8.x4.shared.b16 {%0,%1,%2,%3}, [%4];"
        : "=r"(r[0]), "=r"(r[1]), "=r"(r[2]), "=r"(r[3]) : "r"(a));
}
__device__ __forceinline__ void ldsm4t(uint32_t* r, uint32_t a) {
    asm volatile("ldmatrix.sync.aligned.m8n8.x4.trans.shared.b16 {%0,%1,%2,%3}, [%4];"
        : "=r"(r[0]), "=r"(r[1]), "=r"(r[2]), "=r"(r[3]) : "r"(a));
}
__device__ __forceinline__ void mma_bf16(float* c, const uint32_t* a, const uint32_t* b) {
    asm volatile("mma.sync.aligned.m16n8k16.row.col.f32.bf16.bf16.f32 "
        "{%0,%1,%2,%3}, {%4,%5,%6,%7}, {%8,%9}, {%0,%1,%2,%3};"
        : "+f"(c[0]), "+f"(c[1]), "+f"(c[2]), "+f"(c[3])
        : "r"(a[0]), "r"(a[1]), "r"(a[2]), "r"(a[3]), "r"(b[0]), "r"(b[1]));
}
__device__ __forceinline__ uint32_t packbb(bf16 a, bf16 b) {
    __nv_bfloat162 t; t.x = a; t.y = b; return *(uint32_t*)&t;
}

// ---------------- weight transpose + bf16 split (generic) ----------------
__global__ void tsplit_kernel(const float* __restrict__ W, bf16* __restrict__ Th,
                              bf16* __restrict__ Tl, int K, int N,
                              int roff, size_t out_ls) {
    __shared__ float s[32][33];
    int l = blockIdx.z;
    const float* Wl = W + (size_t)l * K * N;
    bf16* Thl = Th + (size_t)l * out_ls;
    bf16* Tll = Tl + (size_t)l * out_ls;
    int n0 = blockIdx.x * 32, k0 = blockIdx.y * 32;
    int tx = threadIdx.x, ty = threadIdx.y;
    #pragma unroll
    for (int j = 0; j < 4; j++)
        s[ty + 8*j][tx] = Wl[(size_t)(k0 + ty + 8*j) * N + n0 + tx];
    __syncthreads();
    #pragma unroll
    for (int j = 0; j < 4; j++) {
        int row = ty + 8*j;
        float v = s[tx][row];
        bf16 hi = __float2bfloat16(v);
        bf16 lo = __float2bfloat16(v - __bfloat162float(hi));
        size_t idx = (size_t)(roff + n0 + row) * K + k0 + tx;
        Thl[idx] = hi; Tll[idx] = lo;
    }
}

// merged QKV tsplit
__global__ void tsplit_qkv(const float* __restrict__ Wq, const float* __restrict__ Wk,
                           const float* __restrict__ Wv,
                           bf16* __restrict__ Th, bf16* __restrict__ Tl) {
    __shared__ float s[32][33];
    int z = blockIdx.z;
    int l = z / 3, which = z % 3;
    const float* W = (which == 0) ? Wq : (which == 1) ? Wk : Wv;
    const float* Wl = W + (size_t)l * DD * DD;
    size_t out_ls = (size_t)NQKV * DD;
    bf16* Thl = Th + (size_t)l * out_ls;
    bf16* Tll = Tl + (size_t)l * out_ls;
    int roff = which * DD;
    int n0 = blockIdx.x * 32, k0 = blockIdx.y * 32;
    int tx = threadIdx.x, ty = threadIdx.y;
    #pragma unroll
    for (int j = 0; j < 4; j++)
        s[ty + 8*j][tx] = Wl[(size_t)(k0 + ty + 8*j) * DD + n0 + tx];
    __syncthreads();
    #pragma unroll
    for (int j = 0; j < 4; j++) {
        int row = ty + 8*j;
        float v = s[tx][row];
        bf16 hi = __float2bfloat16(v);
        bf16 lo = __float2bfloat16(v - __bfloat162float(hi));
        size_t idx = (size_t)(roff + n0 + row) * DD + k0 + tx;
        Thl[idx] = hi; Tll[idx] = lo;
    }
}

// ---------------- embedding + positional encoding ----------------
__global__ void embed_kernel(const int* __restrict__ x, const float* __restrict__ emb,
                             float* __restrict__ out) {
    int r = blockIdx.x;
    int b = r / LL;
    int tok = x[r];
    const float* erow = emb + (size_t)tok * DD;
    float* orow = out + (size_t)r * DD;
    const float neg_log = -logf(10000.0f) / (float)DD;
    for (int j = 0; j < 3; j++) {
        int d = threadIdx.x + j * 256;
        int i2 = (d >> 1) << 1;
        float div = expf((float)i2 * neg_log);
        float ang = (float)b * div;
        float pe = (d & 1) ? cosf(ang) : sinf(ang);
        orow[d] = erow[d] + pe;
    }
}

// ---------------- layernorm -> bf16 hi/lo ----------------
__global__ void ln_kernel(const float* __restrict__ in, const float* __restrict__ g,
                          const float* __restrict__ be,
                          bf16* __restrict__ oh, bf16* __restrict__ ol) {
    __shared__ float red[256];
    int r = blockIdx.x;
    int t = threadIdx.x;
    const float* xr = in + (size_t)r * DD;
    float v0 = xr[t], v1 = xr[t + 256], v2 = xr[t + 512];
    red[t] = v0 + v1 + v2;
    __syncthreads();
    for (int o = 128; o > 0; o >>= 1) { if (t < o) red[t] += red[t + o]; __syncthreads(); }
    float mean = red[0] * (1.0f / (float)DD);
    __syncthreads();
    float d0 = v0 - mean, d1 = v1 - mean, d2 = v2 - mean;
    red[t] = d0 * d0 + d1 * d1 + d2 * d2;
    __syncthreads();
    for (int o = 128; o > 0; o >>= 1) { if (t < o) red[t] += red[t + o]; __syncthreads(); }
    float var = red[0] * (1.0f / (float)DD);
    float rs = rsqrtf(var + 1e-5f);
    size_t base = (size_t)r * DD;
    float outs[3] = { d0 * rs * g[t] + be[t],
                      d1 * rs * g[t + 256] + be[t + 256],
                      d2 * rs * g[t + 512] + be[t + 512] };
    #pragma unroll
    for (int j = 0; j < 3; j++) {
        float v = outs[j];
        bf16 hi = __float2bfloat16(v);
        oh[base + t + 256*j] = hi;
        ol[base + t + 256*j] = __float2bfloat16(v - __bfloat162float(hi));
    }
}

// ---------------- HMMA GEMM: 128x64 CTA tile, 2-stage, 3 CTAs/SM ----------------
// op: 0 = store fp32 (+bias), 1 = GELU -> bf16 hi/lo, 2 = residual add fp32, 3 = store bf16 hi/lo
#define STG_BYTES 30720
#define AL_OFF 10240
#define BH_OFF 20480
#define BL_OFF 25600
#define NSTG 2
#define GEMM_SMEM (NSTG*STG_BYTES)

__global__ __launch_bounds__(256, 3) void gemm_mma(
    const bf16* __restrict__ Ah, const bf16* __restrict__ Al,
    const bf16* __restrict__ Bh, const bf16* __restrict__ Bl,
    const float* __restrict__ bias0, const float* __restrict__ bias1,
    const float* __restrict__ bias2,
    float* __restrict__ C, bf16* __restrict__ Oh, bf16* __restrict__ Ol,
    int Ntot, int Ktot, int op)
{
    extern __shared__ char dsmem[];
    uint32_t smem_u = smem_to_u32(dsmem);
    int tid = threadIdx.x;
    int lane = tid & 31;
    int wid = tid >> 5;
    int wm = wid & 3;
    int wn = wid >> 2;
    int bm = blockIdx.y * 128, bn = blockIdx.x * 64;

    uint32_t a_off = (uint32_t)((wm*32 + (lane & 15)) * 80 + 16 * (lane >> 4));
    uint32_t b_off = (uint32_t)((wn*32 + 8*((lane >> 4) & 1) + (lane & 7)) * 80
                                + 16 * ((lane >> 3) & 1));

    int arow0 = tid >> 2,         ac0 = (tid & 3);
    int arow1 = (tid + 256) >> 2, ac1 = ((tid + 256) & 3);
    int brow  = tid >> 2,         bc  = (tid & 3);

    float acc[2][4][4];
    #pragma unroll
    for (int i = 0; i < 2; i++)
        #pragma unroll
        for (int j = 0; j < 4; j++)
            #pragma unroll
            for (int q = 0; q < 4; q++) acc[i][j][q] = 0.0f;

    int iters = Ktot >> 5;

    #define LOAD_STAGE(it, buf) do { \
        int k0 = (it) << 5; \
        uint32_t sb = smem_u + (buf) * STG_BYTES; \
        cp_async16(sb + arow0*80 + ac0*16,           Ah + (size_t)(bm + arow0) * Ktot + k0 + ac0*8); \
        cp_async16(sb + AL_OFF + arow0*80 + ac0*16,  Al + (size_t)(bm + arow0) * Ktot + k0 + ac0*8); \
        cp_async16(sb + arow1*80 + ac1*16,           Ah + (size_t)(bm + arow1) * Ktot + k0 + ac1*8); \
        cp_async16(sb + AL_OFF + arow1*80 + ac1*16,  Al + (size_t)(bm + arow1) * Ktot + k0 + ac1*8); \
        cp_async16(sb + BH_OFF + brow*80 + bc*16,    Bh + (size_t)(bn + brow) * Ktot + k0 + bc*8); \
        cp_async16(sb + BL_OFF + brow*80 + bc*16,    Bl + (size_t)(bn + brow) * Ktot + k0 + bc*8); \
    } while (0)

    LOAD_STAGE(0, 0); CP_COMMIT();
    LOAD_STAGE(1, 1); CP_COMMIT();

    for (int it = 0; it < iters; it++) {
        CP_WAIT1();
        __syncthreads();
        int buf = it & 1;
        uint32_t sA  = smem_u + buf * STG_BYTES;
        uint32_t sAl = sA + AL_OFF;
        uint32_t sBh = sA + BH_OFF;
        uint32_t sBl = sA + BL_OFF;
        #pragma unroll
        for (int ks = 0; ks < 2; ks++) {
            uint32_t ah[2][4], al[2][4], bh[2][4], bl[2][4];
            #pragma unroll
            for (int tm = 0; tm < 2; tm++) {
                ldsm4(ah[tm], sA  + a_off + tm*1280 + ks*32);
                ldsm4(al[tm], sAl + a_off + tm*1280 + ks*32);
            }
            #pragma unroll
            for (int p = 0; p < 2; p++) {
                ldsm4(bh[p], sBh + b_off + p*1280 + ks*32);
                ldsm4(bl[p], sBl + b_off + p*1280 + ks*32);
            }
            // pass 1: Ah*Bh
            #pragma unroll
            for (int tm = 0; tm < 2; tm++)
                #pragma unroll
                for (int p = 0; p < 2; p++) {
                    mma_bf16(acc[tm][2*p],   ah[tm], &bh[p][0]);
                    mma_bf16(acc[tm][2*p+1], ah[tm], &bh[p][2]);
                }
            // pass 2: Ah*Bl
            #pragma unroll
            for (int tm = 0; tm < 2; tm++)
                #pragma unroll
                for (int p = 0; p < 2; p++) {
                    mma_bf16(acc[tm][2*p],   ah[tm], &bl[p][0]);
                    mma_bf16(acc[tm][2*p+1], ah[tm], &bl[p][2]);
                }
            // pass 3: Al*Bh
            #pragma unroll
            for (int tm = 0; tm < 2; tm++)
                #pragma unroll
                for (int p = 0; p < 2; p++) {
                    mma_bf16(acc[tm][2*p],   al[tm], &bh[p][0]);
                    mma_bf16(acc[tm][2*p+1], al[tm], &bh[p][2]);
                }
        }
        __syncthreads();
        if (it + 2 < iters) LOAD_STAGE(it + 2, buf);
        CP_COMMIT();
    }
    #undef LOAD_STAGE

    // segmented bias (QKV fused projection)
    const float* beff = bias0;
    int boff = 0;
    if (bias1 != nullptr) {
        if (bn >= 1536)      { beff = bias2; boff = 1536; }
        else if (bn >= 768)  { beff = bias1; boff = 768;  }
    }

    int m_base = bm + wm*32 + (lane >> 2);
    int n_base = bn + wn*32 + (lane & 3)*2;
    #pragma unroll
    for (int tm = 0; tm < 2; tm++) {
        #pragma unroll
        for (int tn = 0; tn < 4; tn++) {
            #pragma unroll
            for (int half = 0; half < 2; half++) {
                int m = m_base + tm*16 + half*8;
                int n = n_base + tn*8;
                float v0 = acc[tm][tn][2*half]     + beff[n - boff];
                float v1 = acc[tm][tn][2*half + 1] + beff[n + 1 - boff];
                size_t idx = (size_t)m * Ntot + n;
                if (op == 1) {
                    float gv0 = 0.5f * v0 * (1.0f + erff(v0 * 0.70710678118654752f));
                    float gv1 = 0.5f * v1 * (1.0f + erff(v1 * 0.70710678118654752f));
                    bf16 h0 = __float2bfloat16(gv0), h1 = __float2bfloat16(gv1);
                    *(uint32_t*)(Oh + idx) = packbb(h0, h1);
                    *(uint32_t*)(Ol + idx) = packbb(
                        __float2bfloat16(gv0 - __bfloat162float(h0)),
                        __float2bfloat16(gv1 - __bfloat162float(h1)));
                } else if (op == 2) {
                    C[idx]     += v0;
                    C[idx + 1] += v1;
                } else if (op == 3) {
                    bf16 h0 = __float2bfloat16(v0), h1 = __float2bfloat16(v1);
                    *(uint32_t*)(Oh + idx) = packbb(h0, h1);
                    *(uint32_t*)(Ol + idx) = packbb(
                        __float2bfloat16(v0 - __bfloat162float(h0)),
                        __float2bfloat16(v1 - __bfloat162float(h1)));
                } else {
                    C[idx]     = v0;
                    C[idx + 1] = v1;
                }
            }
        }
    }
}

// ---------------- tensor-core fused attention ----------------
#define SSTR 520
#define OFF_Q  (64*SSTR*4)
#define OFF_QL (OFF_Q + 9216)
#define OFF_K  (OFF_QL + 9216)
#define OFF_KL (OFF_K + 18432)
#define ATTN_SMEM (OFF_KL + 18432)

__global__ __launch_bounds__(256) void attn_tc(
    const bf16* __restrict__ QKVh, const bf16* __restrict__ QKVl,
    const int* __restrict__ mask, float* __restrict__ attn_out,
    bf16* __restrict__ aoh, bf16* __restrict__ aol)
{
    extern __shared__ char sm[];
    float* S = (float*)sm;
    uint32_t su = smem_to_u32(sm);
    int tid = threadIdx.x, lane = tid & 31, wid = tid >> 5;
    int q0 = blockIdx.x * 64;
    int h = blockIdx.y, b = blockIdx.z;

    {
        int r = tid >> 2, c = tid & 3;
        size_t g = ((size_t)(b*LL + q0 + r)) * NQKV + h*DH;
        const uint4* gh = (const uint4*)(QKVh + g);
        const uint4* gl = (const uint4*)(QKVl + g);
        *(uint4*)(sm + OFF_Q  + r*144 + c*16)     = gh[c];
        *(uint4*)(sm + OFF_Q  + r*144 + (c+4)*16) = gh[c+4];
        *(uint4*)(sm + OFF_QL + r*144 + c*16)     = gl[c];
        *(uint4*)(sm + OFF_QL + r*144 + (c+4)*16) = gl[c+4];
    }

    int wm = wid & 1, wn = wid >> 1;

    for (int kc = 0; kc < 4; kc++) {
        {
            int r = tid >> 1, c0 = (tid & 1) * 4;
            size_t g = ((size_t)(b*LL + kc*128 + r)) * NQKV + 768 + h*DH;
            const uint4* gh = (const uint4*)(QKVh + g);
            const uint4* gl = (const uint4*)(QKVl + g);
            #pragma unroll
            for (int c = 0; c < 4; c++) {
                *(uint4*)(sm + OFF_K  + r*144 + (c0+c)*16) = gh[c0+c];
                *(uint4*)(sm + OFF_KL + r*144 + (c0+c)*16) = gl[c0+c];
            }
        }
        __syncthreads();
        float acc[2][4][4];
        #pragma unroll
        for (int i = 0; i < 2; i++)
            #pragma unroll
            for (int j = 0; j < 4; j++)
                #pragma unroll
                for (int q = 0; q < 4; q++) acc[i][j][q] = 0.0f;
        uint32_t aoff = (uint32_t)((wm*32 + (lane & 15)) * 144 + 16 * (lane >> 4));
        uint32_t boff = (uint32_t)((wn*32 + 8*((lane >> 4) & 1) + (lane & 7)) * 144
                                   + 16 * ((lane >> 3) & 1));
        #pragma unroll
        for (int ki = 0; ki < 4; ki++) {
            uint32_t ah[2][4], al[2][4], bh[2][4], bl[2][4];
            #pragma unroll
            for (int tm = 0; tm < 2; tm++) {
                ldsm4(ah[tm], su + OFF_Q  + aoff + tm*2304 + ki*32);
                ldsm4(al[tm], su + OFF_QL + aoff + tm*2304 + ki*32);
            }
            #pragma unroll
            for (int p = 0; p < 2; p++) {
                ldsm4(bh[p], su + OFF_K  + boff + p*2304 + ki*32);
                ldsm4(bl[p], su + OFF_KL + boff + p*2304 + ki*32);
            }
            #pragma unroll
            for (int tm = 0; tm < 2; tm++)
                #pragma unroll
                for (int p = 0; p < 2; p++) {
                    mma_bf16(acc[tm][2*p],   ah[tm], &bh[p][0]);
                    mma_bf16(acc[tm][2*p+1], ah[tm], &bh[p][2]);
                }
            #pragma unroll
            for (int tm = 0; tm < 2; tm++)
                #pragma unroll
                for (int p = 0; p < 2; p++) {
                    mma_bf16(acc[tm][2*p],   ah[tm], &bl[p][0]);
                    mma_bf16(acc[tm][2*p+1], ah[tm], &bl[p][2]);
                }
            #pragma unroll
            for (int tm = 0; tm < 2; tm++)
                #pragma unroll
                for (int p = 0; p < 2; p++) {
                    mma_bf16(acc[tm][2*p],   al[tm], &bh[p][0]);
                    mma_bf16(acc[tm][2*p+1], al[tm], &bh[p][2]);
                }
        }
        #pragma unroll
        for (int tm = 0; tm < 2; tm++) {
            #pragma unroll
            for (int tn = 0; tn < 4; tn++) {
                int row = wm*32 + tm*16 + (lane >> 2);
                int col = kc*128 + wn*32 + tn*8 + (lane & 3)*2;
                int m0 = mask[b*LL + col], m1 = mask[b*LL + col + 1];
                #pragma unroll
                for (int half = 0; half < 2; half++) {
                    int rr = row + half*8;
                    float v0 = acc[tm][tn][2*half]   * 0.125f - 0.01f * (float)((q0 + rr) - col);
                    float v1 = acc[tm][tn][2*half+1] * 0.125f - 0.01f * (float)((q0 + rr) - (col+1));
                    if (m0 == 0) v0 = -INFINITY;
                    if (m1 == 0) v1 = -INFINITY;
                    S[rr*SSTR + col]     = v0;
                    S[rr*SSTR + col + 1] = v1;
                }
            }
        }
        __syncthreads();
    }

    {
        size_t gbase0 = ((size_t)(b*HH + h) * LL + q0) * LL;
        #pragma unroll
        for (int j = 0; j < 8; j++) {
            int r = wid*8 + j;
            float4 e[4];
            #pragma unroll
            for (int i = 0; i < 4; i++) e[i] = *(float4*)&S[r*SSTR + i*128 + lane*4];
            float mx = -1e30f;
            #pragma unroll
            for (int i = 0; i < 4; i++)
                mx = fmaxf(mx, fmaxf(fmaxf(e[i].x, e[i].y), fmaxf(e[i].z, e[i].w)));
            #pragma unroll
            for (int o = 16; o > 0; o >>= 1) mx = fmaxf(mx, __shfl_xor_sync(0xFFFFFFFFu, mx, o));
            float sum = 0.0f;
            #pragma unroll
            for (int i = 0; i < 4; i++) {
                e[i].x = __expf(e[i].x - mx); e[i].y = __expf(e[i].y - mx);
                e[i].z = __expf(e[i].z - mx); e[i].w = __expf(e[i].w - mx);
                sum += e[i].x + e[i].y + e[i].z + e[i].w;
            }
            #pragma unroll
            for (int o = 16; o > 0; o >>= 1) sum += __shfl_xor_sync(0xFFFFFFFFu, sum, o);
            float inv = 1.0f / sum;
            float* gp = attn_out + gbase0 + (size_t)r * LL;
            #pragma unroll
            for (int i = 0; i < 4; i++) {
                e[i].x *= inv; e[i].y *= inv; e[i].z *= inv; e[i].w *= inv;
                *(float4*)&S[r*SSTR + i*128 + lane*4] = e[i];
                *(float4*)(gp + i*128 + lane*4) = e[i];
            }
        }
    }
    __syncthreads();

    float oa[2][2][4];
    #pragma unroll
    for (int i = 0; i < 2; i++)
        #pragma unroll
        for (int j = 0; j < 2; j++)
            #pragma unroll
            for (int q = 0; q < 4; q++) oa[i][j][q] = 0.0f;

    for (int kc = 0; kc < 8; kc++) {
        {
            int r = tid >> 2, c0 = (tid & 3) * 16;
            #pragma unroll
            for (int jj = 0; jj < 2; jj++) {
                const float* sp = &S[r*SSTR + kc*64 + c0 + jj*8];
                float v[8];
                *(float4*)&v[0] = *(const float4*)sp;
                *(float4*)&v[4] = *(const float4*)(sp + 4);
                uint32_t hw[4], lw[4];
                #pragma unroll
                for (int q = 0; q < 4; q++) {
                    bf16 ha = __float2bfloat16(v[2*q]), hb = __float2bfloat16(v[2*q+1]);
                    hw[q] = packbb(ha, hb);
                    lw[q] = packbb(__float2bfloat16(v[2*q]   - __bfloat162float(ha)),
                                   __float2bfloat16(v[2*q+1] - __bfloat162float(hb)));
                }
                *(uint4*)(sm + OFF_Q  + r*144 + (c0 + jj*8)*2) = *(uint4*)hw;
                *(uint4*)(sm + OFF_QL + r*144 + (c0 + jj*8)*2) = *(uint4*)lw;
            }
        }
        {
            int r = tid >> 2, c = tid & 3;
            size_t g = ((size_t)(b*LL + kc*64 + r)) * NQKV + 1536 + h*DH;
            const uint4* gh = (const uint4*)(QKVh + g);
            const uint4* gl = (const uint4*)(QKVl + g);
            *(uint4*)(sm + OFF_K  + r*144 + c*16)     = gh[c];
            *(uint4*)(sm + OFF_K  + r*144 + (c+4)*16) = gh[c+4];
            *(uint4*)(sm + OFF_KL + r*144 + c*16)     = gl[c];
            *(uint4*)(sm + OFF_KL + r*144 + (c+4)*16) = gl[c+4];
        }
        __syncthreads();
        uint32_t poff = (uint32_t)((wm*32 + (lane & 15)) * 144 + 16 * (lane >> 4));
        uint32_t voff = (uint32_t)((lane & 15) * 144 + wn*32 + 16 * (lane >> 4));
        #pragma unroll
        for (int ki = 0; ki < 4; ki++) {
            uint32_t ph[2][4], pl[2][4], vh[4], vl[4];
            #pragma unroll
            for (int tm = 0; tm < 2; tm++) {
                ldsm4(ph[tm], su + OFF_Q  + poff + tm*2304 + ki*32);
                ldsm4(pl[tm], su + OFF_QL + poff + tm*2304 + ki*32);
            }
            ldsm4t(vh, su + OFF_K  + voff + ki*2304);
            ldsm4t(vl, su + OFF_KL + voff + ki*2304);
            #pragma unroll
            for (int tm = 0; tm < 2; tm++)
                #pragma unroll
                for (int tn = 0; tn < 2; tn++)
                    mma_bf16(oa[tm][tn], ph[tm], &vh[2*tn]);
            #pragma unroll
            for (int tm = 0; tm < 2; tm++)
                #pragma unroll
                for (int tn = 0; tn < 2; tn++)
                    mma_bf16(oa[tm][tn], ph[tm], &vl[2*tn]);
            #pragma unroll
            for (int tm = 0; tm < 2; tm++)
                #pragma unroll
                for (int tn = 0; tn < 2; tn++)
                    mma_bf16(oa[tm][tn], pl[tm], &vh[2*tn]);
        }
        __syncthreads();
    }

    #pragma unroll
    for (int tm = 0; tm < 2; tm++) {
        #pragma unroll
        for (int tn = 0; tn < 2; tn++) {
            #pragma unroll
            for (int half = 0; half < 2; half++) {
                int row = wm*32 + tm*16 + (lane >> 2) + half*8;
                int col = wn*16 + tn*8 + (lane & 3)*2;
                float v0 = oa[tm][tn][2*half], v1 = oa[tm][tn][2*half+1];
                size_t g = ((size_t)(b*LL + q0 + row)) * DD + h*DH + col;
                bf16 h0 = __float2bfloat16(v0), h1 = __float2bfloat16(v1);
                *(uint32_t*)(aoh + g) = packbb(h0, h1);
                *(uint32_t*)(aol + g) = packbb(
                    __float2bfloat16(v0 - __bfloat162float(h0)),
                    __float2bfloat16(v1 - __bfloat162float(h1)));
            }
        }
    }
}

// ---------------- classifier head ----------------
__global__ void logits_kernel(const float* __restrict__ h, const float* __restrict__ Wc,
                              const float* __restrict__ bc, float* __restrict__ out) {
    __shared__ float red[256];
    int b = blockIdx.x;
    int t = threadIdx.x;
    float s = 0.0f;
    for (int d = t; d < DD; d += 256) s += h[(size_t)b * LL * DD + d] * Wc[d * NC];
    red[t] = s; __syncthreads();
    for (int o = 128; o > 0; o >>= 1) { if (t < o) red[t] += red[t + o]; __syncthreads(); }
    if (t == 0) out[b * NC] = red[0] + bc[0];
}

// ---------------- launcher ----------------
extern "C" void kernel_launch(void* const* d_in, const int* in_sizes, int n_in,
                              void* d_out, int out_size) {
    const int*   x    = (const int*)  d_in[0];
    const int*   mask = (const int*)  d_in[1];
    const float* emb  = (const float*)d_in[2];
    const float* Wq   = (const float*)d_in[3];
    const float* bq   = (const float*)d_in[4];
    const float* Wk   = (const float*)d_in[5];
    const float* bk   = (const float*)d_in[6];
    const float* Wv   = (const float*)d_in[7];
    const float* bv   = (const float*)d_in[8];
    const float* Wo   = (const float*)d_in[9];
    const float* bo   = (const float*)d_in[10];
    const float* W1   = (const float*)d_in[11];
    const float* b1   = (const float*)d_in[12];
    const float* W2   = (const float*)d_in[13];
    const float* b2   = (const float*)d_in[14];
    const float* g1   = (const float*)d_in[15];
    const float* be1  = (const float*)d_in[16];
    const float* g2   = (const float*)d_in[17];
    const float* be2  = (const float*)d_in[18];
    const float* Wc   = (const float*)d_in[19];
    const float* bc   = (const float*)d_in[20];

    float* out = (float*)d_out;
    float* logits = out;
    float* attn_base = out + (size_t)BB * NC;

    static bool attr_set = false;
    if (!attr_set) {
        cudaFuncSetAttribute(gemm_mma, cudaFuncAttributeMaxDynamicSharedMemorySize, GEMM_SMEM);
        cudaFuncSetAttribute(attn_tc, cudaFuncAttributeMaxDynamicSharedMemorySize, ATTN_SMEM);
        attr_set = true;
    }

    float *p_h;
    bf16 *p_xnh, *p_xnl, *p_qkvh, *p_qkvl, *p_aoh, *p_aol, *p_ffh, *p_ffl;
    bf16 *p_wqkvh, *p_wqkvl, *p_woh, *p_wol, *p_w1h, *p_w1l, *p_w2h, *p_w2l;
    cudaGetSymbolAddress((void**)&p_h, g_h);
    cudaGetSymbolAddress((void**)&p_xnh, g_xnh); cudaGetSymbolAddress((void**)&p_xnl, g_xnl);
    cudaGetSymbolAddress((void**)&p_qkvh, g_qkvh); cudaGetSymbolAddress((void**)&p_qkvl, g_qkvl);
    cudaGetSymbolAddress((void**)&p_aoh, g_aoh); cudaGetSymbolAddress((void**)&p_aol, g_aol);
    cudaGetSymbolAddress((void**)&p_ffh, g_ffh); cudaGetSymbolAddress((void**)&p_ffl, g_ffl);
    cudaGetSymbolAddress((void**)&p_wqkvh, g_wqkvh); cudaGetSymbolAddress((void**)&p_wqkvl, g_wqkvl);
    cudaGetSymbolAddress((void**)&p_woh, g_woh); cudaGetSymbolAddress((void**)&p_wol, g_wol);
    cudaGetSymbolAddress((void**)&p_w1h, g_w1h); cudaGetSymbolAddress((void**)&p_w1l, g_w1l);
    cudaGetSymbolAddress((void**)&p_w2h, g_w2h); cudaGetSymbolAddress((void**)&p_w2l, g_w2l);

    dim3 tb(32, 8);
    size_t olsQKV = (size_t)NQKV * DD;

    dim3 gD(DD/64, MM/128);
    dim3 gQKV(NQKV/64, MM/128);
    dim3 gF(FF/64, MM/128);
    dim3 gAttn(LL/64, HH, BB);

    // Launch order: 1 tsplit_qkv, 2 embed, 3 ln, 4 gemm(QKV) <- ncu capture slot
    tsplit_qkv<<<dim3(DD/32, DD/32, NL*3), tb>>>(Wq, Wk, Wv, p_wqkvh, p_wqkvl);
    embed_kernel<<<MM, 256>>>(x, emb, p_h);

    for (int l = 0; l < NL; l++) {
        size_t wD = (size_t)l * DD * DD;
        size_t wF = (size_t)l * DD * FF;
        size_t wQ = (size_t)l * olsQKV;
        ln_kernel<<<MM, 256>>>(p_h, g1 + l*DD, be1 + l*DD, p_xnh, p_xnl);
        gemm_mma<<<gQKV, 256, GEMM_SMEM>>>(p_xnh, p_xnl, p_wqkvh + wQ, p_wqkvl + wQ,
                                           bq + l*DD, bk + l*DD, bv + l*DD,
                                           nullptr, p_qkvh, p_qkvl, NQKV, DD, 3);
        if (l == 0) {
            tsplit_kernel<<<dim3(DD/32, DD/32, NL), tb>>>(Wo, p_woh, p_wol, DD, DD, 0, (size_t)DD*DD);
            tsplit_kernel<<<dim3(FF/32, DD/32, NL), tb>>>(W1, p_w1h, p_w1l, DD, FF, 0, (size_t)DD*FF);
            tsplit_kernel<<<dim3(DD/32, FF/32, NL), tb>>>(W2, p_w2h, p_w2l, FF, DD, 0, (size_t)FF*DD);
        }
        attn_tc<<<gAttn, 256, ATTN_SMEM>>>(p_qkvh, p_qkvl, mask,
                                           attn_base + (size_t)l * BB * HH * LL * LL, p_aoh, p_aol);
        gemm_mma<<<gD, 256, GEMM_SMEM>>>(p_aoh, p_aol, p_woh + wD, p_wol + wD,
                                         bo + l*DD, nullptr, nullptr,
                                         p_h, nullptr, nullptr, DD, DD, 2);
        ln_kernel<<<MM, 256>>>(p_h, g2 + l*DD, be2 + l*DD, p_xnh, p_xnl);
        gemm_mma<<<gF, 256, GEMM_SMEM>>>(p_xnh, p_xnl, p_w1h + wF, p_w1l + wF,
                                         b1 + l*FF, nullptr, nullptr,
                                         nullptr, p_ffh, p_ffl, FF, DD, 1);
        gemm_mma<<<gD, 256, GEMM_SMEM>>>(p_ffh, p_ffl, p_w2h + wF, p_w2l + wF,
                                         b2 + l*DD, nullptr, nullptr,
                                         p_h, nullptr, nullptr, DD, FF, 2);
    }

    logits_kernel<<<BB, 256>>>(p_h, Wc, bc, logits);
}

// round 11
// speedup vs baseline: 1.3671x; 1.3493x over previous
#include <cuda_runtime.h>
#include <cuda_fp16.h>
#include <math.h>
#include <stdint.h>

#define BB 8
#define LL 512
#define DD 768
#define HH 12
#define DH 64
#define FF 3072
#define NL 6
#define NC 1
#define MM (BB*LL)   // 4096
#define NQKV 2304

typedef __half fp16;

// ---------------- scratch ----------------
__device__ float g_h[MM*DD];
__device__ fp16 g_xn[MM*DD];
__device__ fp16 g_qkvh[MM*NQKV], g_qkvl[MM*NQKV];
__device__ fp16 g_ao[MM*DD];
__device__ fp16 g_ff[MM*FF];
__device__ fp16 g_wqkvh[NL*NQKV*DD], g_wqkvl[NL*NQKV*DD];
__device__ fp16 g_woh[NL*DD*DD], g_wol[NL*DD*DD];
__device__ fp16 g_w1h[NL*DD*FF], g_w1l[NL*DD*FF];
__device__ fp16 g_w2h[NL*FF*DD], g_w2l[NL*FF*DD];

// ---------------- PTX helpers ----------------
__device__ __forceinline__ uint32_t smem_to_u32(const void* p) {
    uint32_t a;
    asm("{ .reg .u64 t; cvta.to.shared.u64 t, %1; cvt.u32.u64 %0, t; }" : "=r"(a) : "l"(p));
    return a;
}
__device__ __forceinline__ void cp_async16(uint32_t saddr, const void* gaddr) {
    asm volatile("cp.async.cg.shared.global [%0], [%1], 16;" :: "r"(saddr), "l"(gaddr) : "memory");
}
#define CP_COMMIT() asm volatile("cp.async.commit_group;" ::: "memory")
#define CP_WAIT1()  asm volatile("cp.async.wait_group 1;"  ::: "memory")
__device__ __forceinline__ void ldsm4(uint32_t* r, uint32_t a) {
    asm volatile("ldmatrix.sync.aligned.m8n8.x4.shared.b16 {%0,%1,%2,%3}, [%4];"
        : "=r"(r[0]), "=r"(r[1]), "=r"(r[2]), "=r"(r[3]) : "r"(a));
}
__device__ __forceinline__ void ldsm4t(uint32_t* r, uint32_t a) {
    asm volatile("ldmatrix.sync.aligned.m8n8.x4.trans.shared.b16 {%0,%1,%2,%3}, [%4];"
        : "=r"(r[0]), "=r"(r[1]), "=r"(r[2]), "=r"(r[3]) : "r"(a));
}
__device__ __forceinline__ void mma_f16(float* c, const uint32_t* a, const uint32_t* b) {
    asm volatile("mma.sync.aligned.m16n8k16.row.col.f32.f16.f16.f32 "
        "{%0,%1,%2,%3}, {%4,%5,%6,%7}, {%8,%9}, {%0,%1,%2,%3};"
        : "+f"(c[0]), "+f"(c[1]), "+f"(c[2]), "+f"(c[3])
        : "r"(a[0]), "r"(a[1]), "r"(a[2]), "r"(a[3]), "r"(b[0]), "r"(b[1]));
}
__device__ __forceinline__ uint32_t packh(fp16 a, fp16 b) {
    __half2 t; t.x = a; t.y = b; return *(uint32_t*)&t;
}

// ---------------- weight transpose + fp16 hi/lo split (generic) ----------------
__global__ void tsplit_kernel(const float* __restrict__ W, fp16* __restrict__ Th,
                              fp16* __restrict__ Tl, int K, int N,
                              int roff, size_t out_ls) {
    __shared__ float s[32][33];
    int l = blockIdx.z;
    const float* Wl = W + (size_t)l * K * N;
    fp16* Thl = Th + (size_t)l * out_ls;
    fp16* Tll = Tl + (size_t)l * out_ls;
    int n0 = blockIdx.x * 32, k0 = blockIdx.y * 32;
    int tx = threadIdx.x, ty = threadIdx.y;
    #pragma unroll
    for (int j = 0; j < 4; j++)
        s[ty + 8*j][tx] = Wl[(size_t)(k0 + ty + 8*j) * N + n0 + tx];
    __syncthreads();
    #pragma unroll
    for (int j = 0; j < 4; j++) {
        int row = ty + 8*j;
        float v = s[tx][row];
        fp16 hi = __float2half_rn(v);
        fp16 lo = __float2half_rn(v - __half2float(hi));
        size_t idx = (size_t)(roff + n0 + row) * K + k0 + tx;
        Thl[idx] = hi; Tll[idx] = lo;
    }
}

// merged QKV tsplit
__global__ void tsplit_qkv(const float* __restrict__ Wq, const float* __restrict__ Wk,
                           const float* __restrict__ Wv,
                           fp16* __restrict__ Th, fp16* __restrict__ Tl) {
    __shared__ float s[32][33];
    int z = blockIdx.z;
    int l = z / 3, which = z % 3;
    const float* W = (which == 0) ? Wq : (which == 1) ? Wk : Wv;
    const float* Wl = W + (size_t)l * DD * DD;
    size_t out_ls = (size_t)NQKV * DD;
    fp16* Thl = Th + (size_t)l * out_ls;
    fp16* Tll = Tl + (size_t)l * out_ls;
    int roff = which * DD;
    int n0 = blockIdx.x * 32, k0 = blockIdx.y * 32;
    int tx = threadIdx.x, ty = threadIdx.y;
    #pragma unroll
    for (int j = 0; j < 4; j++)
        s[ty + 8*j][tx] = Wl[(size_t)(k0 + ty + 8*j) * DD + n0 + tx];
    __syncthreads();
    #pragma unroll
    for (int j = 0; j < 4; j++) {
        int row = ty + 8*j;
        float v = s[tx][row];
        fp16 hi = __float2half_rn(v);
        fp16 lo = __float2half_rn(v - __half2float(hi));
        size_t idx = (size_t)(roff + n0 + row) * DD + k0 + tx;
        Thl[idx] = hi; Tll[idx] = lo;
    }
}

// ---------------- embedding + positional encoding ----------------
__global__ void embed_kernel(const int* __restrict__ x, const float* __restrict__ emb,
                             float* __restrict__ out) {
    int r = blockIdx.x;
    int b = r / LL;
    int tok = x[r];
    const float* erow = emb + (size_t)tok * DD;
    float* orow = out + (size_t)r * DD;
    const float neg_log = -logf(10000.0f) / (float)DD;
    for (int j = 0; j < 3; j++) {
        int d = threadIdx.x + j * 256;
        int i2 = (d >> 1) << 1;
        float div = expf((float)i2 * neg_log);
        float ang = (float)b * div;
        float pe = (d & 1) ? cosf(ang) : sinf(ang);
        orow[d] = erow[d] + pe;
    }
}

// ---------------- layernorm -> fp16 single ----------------
__global__ void ln_kernel(const float* __restrict__ in, const float* __restrict__ g,
                          const float* __restrict__ be, fp16* __restrict__ o) {
    __shared__ float red[256];
    int r = blockIdx.x;
    int t = threadIdx.x;
    const float* xr = in + (size_t)r * DD;
    float v0 = xr[t], v1 = xr[t + 256], v2 = xr[t + 512];
    red[t] = v0 + v1 + v2;
    __syncthreads();
    for (int oo = 128; oo > 0; oo >>= 1) { if (t < oo) red[t] += red[t + oo]; __syncthreads(); }
    float mean = red[0] * (1.0f / (float)DD);
    __syncthreads();
    float d0 = v0 - mean, d1 = v1 - mean, d2 = v2 - mean;
    red[t] = d0 * d0 + d1 * d1 + d2 * d2;
    __syncthreads();
    for (int oo = 128; oo > 0; oo >>= 1) { if (t < oo) red[t] += red[t + oo]; __syncthreads(); }
    float var = red[0] * (1.0f / (float)DD);
    float rs = rsqrtf(var + 1e-5f);
    size_t base = (size_t)r * DD;
    o[base + t]       = __float2half(d0 * rs * g[t]       + be[t]);
    o[base + t + 256] = __float2half(d1 * rs * g[t + 256] + be[t + 256]);
    o[base + t + 512] = __float2half(d2 * rs * g[t + 512] + be[t + 512]);
}

// ---------------- HMMA GEMM: 128x64 tile, A single fp16, B fp16 hi/lo, 2 MMA passes ----------------
// op: 1 = GELU -> fp16 single, 2 = residual add fp32, 3 = store fp16 hi/lo
#define A_OFF 0
#define BH_OFF 10240
#define BL_OFF 15360
#define STG_BYTES 20480
#define NSTG 3
#define GEMM_SMEM (NSTG*STG_BYTES)

__global__ __launch_bounds__(256, 3) void gemm_mma(
    const fp16* __restrict__ A,
    const fp16* __restrict__ Bh, const fp16* __restrict__ Bl,
    const float* __restrict__ bias0, const float* __restrict__ bias1,
    const float* __restrict__ bias2,
    float* __restrict__ C, fp16* __restrict__ Oh, fp16* __restrict__ Ol,
    int Ntot, int Ktot, int op)
{
    extern __shared__ char dsmem[];
    uint32_t smem_u = smem_to_u32(dsmem);
    int tid = threadIdx.x;
    int lane = tid & 31;
    int wid = tid >> 5;
    int wm = wid & 3;
    int wn = wid >> 2;
    int bm = blockIdx.y * 128, bn = blockIdx.x * 64;

    uint32_t a_off = (uint32_t)((wm*32 + (lane & 15)) * 80 + 16 * (lane >> 4));
    uint32_t b_off = (uint32_t)((wn*32 + 8*((lane >> 4) & 1) + (lane & 7)) * 80
                                + 16 * ((lane >> 3) & 1));

    int brow = tid >> 2, bc = tid & 3;

    float acc[2][4][4];
    #pragma unroll
    for (int i = 0; i < 2; i++)
        #pragma unroll
        for (int j = 0; j < 4; j++)
            #pragma unroll
            for (int q = 0; q < 4; q++) acc[i][j][q] = 0.0f;

    int iters = Ktot >> 5;

    #define LOAD_STAGE(it, buf) do { \
        int k0 = (it) << 5; \
        uint32_t sb = smem_u + (buf) * STG_BYTES; \
        _Pragma("unroll") \
        for (int j = 0; j < 2; j++) { \
            int ci = 2*tid + j; \
            int row = ci >> 2, col = ci & 3; \
            cp_async16(sb + A_OFF + row*80 + col*16, A + (size_t)(bm + row) * Ktot + k0 + col*8); \
        } \
        cp_async16(sb + BH_OFF + brow*80 + bc*16, Bh + (size_t)(bn + brow) * Ktot + k0 + bc*8); \
        cp_async16(sb + BL_OFF + brow*80 + bc*16, Bl + (size_t)(bn + brow) * Ktot + k0 + bc*8); \
    } while (0)

    LOAD_STAGE(0, 0); CP_COMMIT();
    LOAD_STAGE(1, 1); CP_COMMIT();

    int buf = 0;
    for (int it = 0; it < iters; it++) {
        CP_WAIT1();
        __syncthreads();
        uint32_t sA  = smem_u + buf * STG_BYTES + A_OFF;
        uint32_t sBh = smem_u + buf * STG_BYTES + BH_OFF;
        uint32_t sBl = smem_u + buf * STG_BYTES + BL_OFF;
        #pragma unroll
        for (int ks = 0; ks < 2; ks++) {
            uint32_t a[2][4], bh[2][4], bl[2][4];
            #pragma unroll
            for (int tm = 0; tm < 2; tm++)
                ldsm4(a[tm], sA + a_off + tm*1280 + ks*32);
            #pragma unroll
            for (int p = 0; p < 2; p++) {
                ldsm4(bh[p], sBh + b_off + p*1280 + ks*32);
                ldsm4(bl[p], sBl + b_off + p*1280 + ks*32);
            }
            // pass 1: A*Bh
            #pragma unroll
            for (int tm = 0; tm < 2; tm++)
                #pragma unroll
                for (int p = 0; p < 2; p++) {
                    mma_f16(acc[tm][2*p],   a[tm], &bh[p][0]);
                    mma_f16(acc[tm][2*p+1], a[tm], &bh[p][2]);
                }
            // pass 2: A*Bl
            #pragma unroll
            for (int tm = 0; tm < 2; tm++)
                #pragma unroll
                for (int p = 0; p < 2; p++) {
                    mma_f16(acc[tm][2*p],   a[tm], &bl[p][0]);
                    mma_f16(acc[tm][2*p+1], a[tm], &bl[p][2]);
                }
        }
        int ldbuf = buf + 2; if (ldbuf >= NSTG) ldbuf -= NSTG;
        if (it + 2 < iters) LOAD_STAGE(it + 2, ldbuf);
        CP_COMMIT();
        buf = (buf + 1 == NSTG) ? 0 : buf + 1;
    }
    #undef LOAD_STAGE

    // segmented bias (QKV fused projection)
    const float* beff = bias0;
    int boff = 0;
    if (bias1 != nullptr) {
        if (bn >= 1536)      { beff = bias2; boff = 1536; }
        else if (bn >= 768)  { beff = bias1; boff = 768;  }
    }

    int m_base = bm + wm*32 + (lane >> 2);
    int n_base = bn + wn*32 + (lane & 3)*2;
    #pragma unroll
    for (int tm = 0; tm < 2; tm++) {
        #pragma unroll
        for (int tn = 0; tn < 4; tn++) {
            #pragma unroll
            for (int half = 0; half < 2; half++) {
                int m = m_base + tm*16 + half*8;
                int n = n_base + tn*8;
                float v0 = acc[tm][tn][2*half]     + beff[n - boff];
                float v1 = acc[tm][tn][2*half + 1] + beff[n + 1 - boff];
                size_t idx = (size_t)m * Ntot + n;
                if (op == 1) {
                    float gv0 = 0.5f * v0 * (1.0f + erff(v0 * 0.70710678118654752f));
                    float gv1 = 0.5f * v1 * (1.0f + erff(v1 * 0.70710678118654752f));
                    *(uint32_t*)(Oh + idx) = packh(__float2half(gv0), __float2half(gv1));
                } else if (op == 2) {
                    C[idx]     += v0;
                    C[idx + 1] += v1;
                } else {  // op == 3
                    fp16 h0 = __float2half_rn(v0), h1 = __float2half_rn(v1);
                    *(uint32_t*)(Oh + idx) = packh(h0, h1);
                    *(uint32_t*)(Ol + idx) = packh(
                        __float2half_rn(v0 - __half2float(h0)),
                        __float2half_rn(v1 - __half2float(h1)));
                }
            }
        }
    }
}

// ---------------- tensor-core fused attention (fp16 hi/lo, 3-pass) ----------------
#define SSTR 520
#define OFF_Q  (64*SSTR*4)
#define OFF_QL (OFF_Q + 9216)
#define OFF_K  (OFF_QL + 9216)
#define OFF_KL (OFF_K + 18432)
#define ATTN_SMEM (OFF_KL + 18432)

__global__ __launch_bounds__(256) void attn_tc(
    const fp16* __restrict__ QKVh, const fp16* __restrict__ QKVl,
    const int* __restrict__ mask, float* __restrict__ attn_out,
    fp16* __restrict__ ao)
{
    extern __shared__ char sm[];
    float* S = (float*)sm;
    uint32_t su = smem_to_u32(sm);
    int tid = threadIdx.x, lane = tid & 31, wid = tid >> 5;
    int q0 = blockIdx.x * 64;
    int h = blockIdx.y, b = blockIdx.z;

    {
        int r = tid >> 2, c = tid & 3;
        size_t g = ((size_t)(b*LL + q0 + r)) * NQKV + h*DH;
        const uint4* gh = (const uint4*)(QKVh + g);
        const uint4* gl = (const uint4*)(QKVl + g);
        *(uint4*)(sm + OFF_Q  + r*144 + c*16)     = gh[c];
        *(uint4*)(sm + OFF_Q  + r*144 + (c+4)*16) = gh[c+4];
        *(uint4*)(sm + OFF_QL + r*144 + c*16)     = gl[c];
        *(uint4*)(sm + OFF_QL + r*144 + (c+4)*16) = gl[c+4];
    }

    int wm = wid & 1, wn = wid >> 1;

    for (int kc = 0; kc < 4; kc++) {
        {
            int r = tid >> 1, c0 = (tid & 1) * 4;
            size_t g = ((size_t)(b*LL + kc*128 + r)) * NQKV + 768 + h*DH;
            const uint4* gh = (const uint4*)(QKVh + g);
            const uint4* gl = (const uint4*)(QKVl + g);
            #pragma unroll
            for (int c = 0; c < 4; c++) {
                *(uint4*)(sm + OFF_K  + r*144 + (c0+c)*16) = gh[c0+c];
                *(uint4*)(sm + OFF_KL + r*144 + (c0+c)*16) = gl[c0+c];
            }
        }
        __syncthreads();
        float acc[2][4][4];
        #pragma unroll
        for (int i = 0; i < 2; i++)
            #pragma unroll
            for (int j = 0; j < 4; j++)
                #pragma unroll
                for (int q = 0; q < 4; q++) acc[i][j][q] = 0.0f;
        uint32_t aoff = (uint32_t)((wm*32 + (lane & 15)) * 144 + 16 * (lane >> 4));
        uint32_t boff = (uint32_t)((wn*32 + 8*((lane >> 4) & 1) + (lane & 7)) * 144
                                   + 16 * ((lane >> 3) & 1));
        #pragma unroll
        for (int ki = 0; ki < 4; ki++) {
            uint32_t ah[2][4], al[2][4], bh[2][4], bl[2][4];
            #pragma unroll
            for (int tm = 0; tm < 2; tm++) {
                ldsm4(ah[tm], su + OFF_Q  + aoff + tm*2304 + ki*32);
                ldsm4(al[tm], su + OFF_QL + aoff + tm*2304 + ki*32);
            }
            #pragma unroll
            for (int p = 0; p < 2; p++) {
                ldsm4(bh[p], su + OFF_K  + boff + p*2304 + ki*32);
                ldsm4(bl[p], su + OFF_KL + boff + p*2304 + ki*32);
            }
            #pragma unroll
            for (int tm = 0; tm < 2; tm++)
                #pragma unroll
                for (int p = 0; p < 2; p++) {
                    mma_f16(acc[tm][2*p],   ah[tm], &bh[p][0]);
                    mma_f16(acc[tm][2*p+1], ah[tm], &bh[p][2]);
                }
            #pragma unroll
            for (int tm = 0; tm < 2; tm++)
                #pragma unroll
                for (int p = 0; p < 2; p++) {
                    mma_f16(acc[tm][2*p],   ah[tm], &bl[p][0]);
                    mma_f16(acc[tm][2*p+1], ah[tm], &bl[p][2]);
                }
            #pragma unroll
            for (int tm = 0; tm < 2; tm++)
                #pragma unroll
                for (int p = 0; p < 2; p++) {
                    mma_f16(acc[tm][2*p],   al[tm], &bh[p][0]);
                    mma_f16(acc[tm][2*p+1], al[tm], &bh[p][2]);
                }
        }
        #pragma unroll
        for (int tm = 0; tm < 2; tm++) {
            #pragma unroll
            for (int tn = 0; tn < 4; tn++) {
                int row = wm*32 + tm*16 + (lane >> 2);
                int col = kc*128 + wn*32 + tn*8 + (lane & 3)*2;
                int m0 = mask[b*LL + col], m1 = mask[b*LL + col + 1];
                #pragma unroll
                for (int half = 0; half < 2; half++) {
                    int rr = row + half*8;
                    float v0 = acc[tm][tn][2*half]   * 0.125f - 0.01f * (float)((q0 + rr) - col);
                    float v1 = acc[tm][tn][2*half+1] * 0.125f - 0.01f * (float)((q0 + rr) - (col+1));
                    if (m0 == 0) v0 = -INFINITY;
                    if (m1 == 0) v1 = -INFINITY;
                    S[rr*SSTR + col]     = v0;
                    S[rr*SSTR + col + 1] = v1;
                }
            }
        }
        __syncthreads();
    }

    {
        size_t gbase0 = ((size_t)(b*HH + h) * LL + q0) * LL;
        #pragma unroll
        for (int j = 0; j < 8; j++) {
            int r = wid*8 + j;
            float4 e[4];
            #pragma unroll
            for (int i = 0; i < 4; i++) e[i] = *(float4*)&S[r*SSTR + i*128 + lane*4];
            float mx = -1e30f;
            #pragma unroll
            for (int i = 0; i < 4; i++)
                mx = fmaxf(mx, fmaxf(fmaxf(e[i].x, e[i].y), fmaxf(e[i].z, e[i].w)));
            #pragma unroll
            for (int o = 16; o > 0; o >>= 1) mx = fmaxf(mx, __shfl_xor_sync(0xFFFFFFFFu, mx, o));
            float sum = 0.0f;
            #pragma unroll
            for (int i = 0; i < 4; i++) {
                e[i].x = __expf(e[i].x - mx); e[i].y = __expf(e[i].y - mx);
                e[i].z = __expf(e[i].z - mx); e[i].w = __expf(e[i].w - mx);
                sum += e[i].x + e[i].y + e[i].z + e[i].w;
            }
            #pragma unroll
            for (int o = 16; o > 0; o >>= 1) sum += __shfl_xor_sync(0xFFFFFFFFu, sum, o);
            float inv = 1.0f / sum;
            float* gp = attn_out + gbase0 + (size_t)r * LL;
            #pragma unroll
            for (int i = 0; i < 4; i++) {
                e[i].x *= inv; e[i].y *= inv; e[i].z *= inv; e[i].w *= inv;
                *(float4*)&S[r*SSTR + i*128 + lane*4] = e[i];
                *(float4*)(gp + i*128 + lane*4) = e[i];
            }
        }
    }
    __syncthreads();

    float oa[2][2][4];
    #pragma unroll
    for (int i = 0; i < 2; i++)
        #pragma unroll
        for (int j = 0; j < 2; j++)
            #pragma unroll
            for (int q = 0; q < 4; q++) oa[i][j][q] = 0.0f;

    for (int kc = 0; kc < 8; kc++) {
        {
            int r = tid >> 2, c0 = (tid & 3) * 16;
            #pragma unroll
            for (int jj = 0; jj < 2; jj++) {
                const float* sp = &S[r*SSTR + kc*64 + c0 + jj*8];
                float v[8];
                *(float4*)&v[0] = *(const float4*)sp;
                *(float4*)&v[4] = *(const float4*)(sp + 4);
                uint32_t hw[4], lw[4];
                #pragma unroll
                for (int q = 0; q < 4; q++) {
                    fp16 ha = __float2half_rn(v[2*q]), hb = __float2half_rn(v[2*q+1]);
                    hw[q] = packh(ha, hb);
                    lw[q] = packh(__float2half_rn(v[2*q]   - __half2float(ha)),
                                  __float2half_rn(v[2*q+1] - __half2float(hb)));
                }
                *(uint4*)(sm + OFF_Q  + r*144 + (c0 + jj*8)*2) = *(uint4*)hw;
                *(uint4*)(sm + OFF_QL + r*144 + (c0 + jj*8)*2) = *(uint4*)lw;
            }
        }
        {
            int r = tid >> 2, c = tid & 3;
            size_t g = ((size_t)(b*LL + kc*64 + r)) * NQKV + 1536 + h*DH;
            const uint4* gh = (const uint4*)(QKVh + g);
            const uint4* gl = (const uint4*)(QKVl + g);
            *(uint4*)(sm + OFF_K  + r*144 + c*16)     = gh[c];
            *(uint4*)(sm + OFF_K  + r*144 + (c+4)*16) = gh[c+4];
            *(uint4*)(sm + OFF_KL + r*144 + c*16)     = gl[c];
            *(uint4*)(sm + OFF_KL + r*144 + (c+4)*16) = gl[c+4];
        }
        __syncthreads();
        uint32_t poff = (uint32_t)((wm*32 + (lane & 15)) * 144 + 16 * (lane >> 4));
        uint32_t voff = (uint32_t)((lane & 15) * 144 + wn*32 + 16 * (lane >> 4));
        #pragma unroll
        for (int ki = 0; ki < 4; ki++) {
            uint32_t ph[2][4], pl[2][4], vh[4], vl[4];
            #pragma unroll
            for (int tm = 0; tm < 2; tm++) {
                ldsm4(ph[tm], su + OFF_Q  + poff + tm*2304 + ki*32);
                ldsm4(pl[tm], su + OFF_QL + poff + tm*2304 + ki*32);
            }
            ldsm4t(vh, su + OFF_K  + voff + ki*2304);
            ldsm4t(vl, su + OFF_KL + voff + ki*2304);
            #pragma unroll
            for (int tm = 0; tm < 2; tm++)
                #pragma unroll
                for (int tn = 0; tn < 2; tn++)
                    mma_f16(oa[tm][tn], ph[tm], &vh[2*tn]);
            #pragma unroll
            for (int tm = 0; tm < 2; tm++)
                #pragma unroll
                for (int tn = 0; tn < 2; tn++)
                    mma_f16(oa[tm][tn], ph[tm], &vl[2*tn]);
            #pragma unroll
            for (int tm = 0; tm < 2; tm++)
                #pragma unroll
                for (int tn = 0; tn < 2; tn++)
                    mma_f16(oa[tm][tn], pl[tm], &vh[2*tn]);
        }
        __syncthreads();
    }

    #pragma unroll
    for (int tm = 0; tm < 2; tm++) {
        #pragma unroll
        for (int tn = 0; tn < 2; tn++) {
            #pragma unroll
            for (int half = 0; half < 2; half++) {
                int row = wm*32 + tm*16 + (lane >> 2) + half*8;
                int col = wn*16 + tn*8 + (lane & 3)*2;
                float v0 = oa[tm][tn][2*half], v1 = oa[tm][tn][2*half+1];
                size_t g = ((size_t)(b*LL + q0 + row)) * DD + h*DH + col;
                *(uint32_t*)(ao + g) = packh(__float2half(v0), __float2half(v1));
            }
        }
    }
}

// ---------------- classifier head ----------------
__global__ void logits_kernel(const float* __restrict__ h, const float* __restrict__ Wc,
                              const float* __restrict__ bc, float* __restrict__ out) {
    __shared__ float red[256];
    int b = blockIdx.x;
    int t = threadIdx.x;
    float s = 0.0f;
    for (int d = t; d < DD; d += 256) s += h[(size_t)b * LL * DD + d] * Wc[d * NC];
    red[t] = s; __syncthreads();
    for (int o = 128; o > 0; o >>= 1) { if (t < o) red[t] += red[t + o]; __syncthreads(); }
    if (t == 0) out[b * NC] = red[0] + bc[0];
}

// ---------------- launcher ----------------
extern "C" void kernel_launch(void* const* d_in, const int* in_sizes, int n_in,
                              void* d_out, int out_size) {
    const int*   x    = (const int*)  d_in[0];
    const int*   mask = (const int*)  d_in[1];
    const float* emb  = (const float*)d_in[2];
    const float* Wq   = (const float*)d_in[3];
    const float* bq   = (const float*)d_in[4];
    const float* Wk   = (const float*)d_in[5];
    const float* bk   = (const float*)d_in[6];
    const float* Wv   = (const float*)d_in[7];
    const float* bv   = (const float*)d_in[8];
    const float* Wo   = (const float*)d_in[9];
    const float* bo   = (const float*)d_in[10];
    const float* W1   = (const float*)d_in[11];
    const float* b1   = (const float*)d_in[12];
    const float* W2   = (const float*)d_in[13];
    const float* b2   = (const float*)d_in[14];
    const float* g1   = (const float*)d_in[15];
    const float* be1  = (const float*)d_in[16];
    const float* g2   = (const float*)d_in[17];
    const float* be2  = (const float*)d_in[18];
    const float* Wc   = (const float*)d_in[19];
    const float* bc   = (const float*)d_in[20];

    float* out = (float*)d_out;
    float* logits = out;
    float* attn_base = out + (size_t)BB * NC;

    static bool attr_set = false;
    if (!attr_set) {
        cudaFuncSetAttribute(gemm_mma, cudaFuncAttributeMaxDynamicSharedMemorySize, GEMM_SMEM);
        cudaFuncSetAttribute(attn_tc, cudaFuncAttributeMaxDynamicSharedMemorySize, ATTN_SMEM);
        attr_set = true;
    }

    float *p_h;
    fp16 *p_xn, *p_qkvh, *p_qkvl, *p_ao, *p_ff;
    fp16 *p_wqkvh, *p_wqkvl, *p_woh, *p_wol, *p_w1h, *p_w1l, *p_w2h, *p_w2l;
    cudaGetSymbolAddress((void**)&p_h, g_h);
    cudaGetSymbolAddress((void**)&p_xn, g_xn);
    cudaGetSymbolAddress((void**)&p_qkvh, g_qkvh); cudaGetSymbolAddress((void**)&p_qkvl, g_qkvl);
    cudaGetSymbolAddress((void**)&p_ao, g_ao);
    cudaGetSymbolAddress((void**)&p_ff, g_ff);
    cudaGetSymbolAddress((void**)&p_wqkvh, g_wqkvh); cudaGetSymbolAddress((void**)&p_wqkvl, g_wqkvl);
    cudaGetSymbolAddress((void**)&p_woh, g_woh); cudaGetSymbolAddress((void**)&p_wol, g_wol);
    cudaGetSymbolAddress((void**)&p_w1h, g_w1h); cudaGetSymbolAddress((void**)&p_w1l, g_w1l);
    cudaGetSymbolAddress((void**)&p_w2h, g_w2h); cudaGetSymbolAddress((void**)&p_w2l, g_w2l);

    dim3 tb(32, 8);
    size_t olsQKV = (size_t)NQKV * DD;

    dim3 gD(DD/64, MM/128);
    dim3 gQKV(NQKV/64, MM/128);
    dim3 gF(FF/64, MM/128);
    dim3 gAttn(LL/64, HH, BB);

    // Launch order: 1 tsplit_qkv, 2 embed, 3 ln, 4 gemm(QKV) <- ncu capture slot
    tsplit_qkv<<<dim3(DD/32, DD/32, NL*3), tb>>>(Wq, Wk, Wv, p_wqkvh, p_wqkvl);
    embed_kernel<<<MM, 256>>>(x, emb, p_h);

    for (int l = 0; l < NL; l++) {
        size_t wD = (size_t)l * DD * DD;
        size_t wF = (size_t)l * DD * FF;
        size_t wQ = (size_t)l * olsQKV;
        ln_kernel<<<MM, 256>>>(p_h, g1 + l*DD, be1 + l*DD, p_xn);
        gemm_mma<<<gQKV, 256, GEMM_SMEM>>>(p_xn, p_wqkvh + wQ, p_wqkvl + wQ,
                                           bq + l*DD, bk + l*DD, bv + l*DD,
                                           nullptr, p_qkvh, p_qkvl, NQKV, DD, 3);
        if (l == 0) {
            tsplit_kernel<<<dim3(DD/32, DD/32, NL), tb>>>(Wo, p_woh, p_wol, DD, DD, 0, (size_t)DD*DD);
            tsplit_kernel<<<dim3(FF/32, DD/32, NL), tb>>>(W1, p_w1h, p_w1l, DD, FF, 0, (size_t)DD*FF);
            tsplit_kernel<<<dim3(DD/32, FF/32, NL), tb>>>(W2, p_w2h, p_w2l, FF, DD, 0, (size_t)FF*DD);
        }
        attn_tc<<<gAttn, 256, ATTN_SMEM>>>(p_qkvh, p_qkvl, mask,
                                           attn_base + (size_t)l * BB * HH * LL * LL, p_ao);
        gemm_mma<<<gD, 256, GEMM_SMEM>>>(p_ao, p_woh + wD, p_wol + wD,
                                         bo + l*DD, nullptr, nullptr,
                                         p_h, nullptr, nullptr, DD, DD, 2);
        ln_kernel<<<MM, 256>>>(p_h, g2 + l*DD, be2 + l*DD, p_xn);
        gemm_mma<<<gF, 256, GEMM_SMEM>>>(p_xn, p_w1h + wF, p_w1l + wF,
                                         b1 + l*FF, nullptr, nullptr,
                                         nullptr, p_ff, nullptr, FF, DD, 1);
        gemm_mma<<<gD, 256, GEMM_SMEM>>>(p_ff, p_w2h + wF, p_w2l + wF,
                                         b2 + l*DD, nullptr, nullptr,
                                         p_h, nullptr, nullptr, DD, FF, 2);
    }

    logits_kernel<<<BB, 256>>>(p_h, Wc, bc, logits);
}

// round 12
// speedup vs baseline: 1.8131x; 1.3262x over previous
#include <cuda_runtime.h>
#include <cuda_fp16.h>
#include <math.h>
#include <stdint.h>

#define BB 8
#define LL 512
#define DD 768
#define HH 12
#define DH 64
#define FF 3072
#define NL 6
#define NC 1
#define MM (BB*LL)   // 4096
#define NQKV 2304

typedef __half fp16;

// ---------------- scratch ----------------
__device__ float g_h[MM*DD];
__device__ fp16 g_xn[MM*DD];
__device__ fp16 g_qkv[MM*NQKV];
__device__ fp16 g_ao[MM*DD];
__device__ fp16 g_ff[MM*FF];
__device__ fp16 g_wqkv[NL*NQKV*DD];
__device__ fp16 g_wo[NL*DD*DD];
__device__ fp16 g_w1[NL*DD*FF];
__device__ fp16 g_w2[NL*FF*DD];

// ---------------- PTX helpers ----------------
__device__ __forceinline__ uint32_t smem_to_u32(const void* p) {
    uint32_t a;
    asm("{ .reg .u64 t; cvta.to.shared.u64 t, %1; cvt.u32.u64 %0, t; }" : "=r"(a) : "l"(p));
    return a;
}
__device__ __forceinline__ void cp_async16(uint32_t saddr, const void* gaddr) {
    asm volatile("cp.async.cg.shared.global [%0], [%1], 16;" :: "r"(saddr), "l"(gaddr) : "memory");
}
#define CP_COMMIT() asm volatile("cp.async.commit_group;" ::: "memory")
#define CP_WAIT1()  asm volatile("cp.async.wait_group 1;"  ::: "memory")
__device__ __forceinline__ void ldsm4(uint32_t* r, uint32_t a) {
    asm volatile("ldmatrix.sync.aligned.m8n8.x4.shared.b16 {%0,%1,%2,%3}, [%4];"
        : "=r"(r[0]), "=r"(r[1]), "=r"(r[2]), "=r"(r[3]) : "r"(a));
}
__device__ __forceinline__ void ldsm4t(uint32_t* r, uint32_t a) {
    asm volatile("ldmatrix.sync.aligned.m8n8.x4.trans.shared.b16 {%0,%1,%2,%3}, [%4];"
        : "=r"(r[0]), "=r"(r[1]), "=r"(r[2]), "=r"(r[3]) : "r"(a));
}
__device__ __forceinline__ void mma_f16(float* c, const uint32_t* a, const uint32_t* b) {
    asm volatile("mma.sync.aligned.m16n8k16.row.col.f32.f16.f16.f32 "
        "{%0,%1,%2,%3}, {%4,%5,%6,%7}, {%8,%9}, {%0,%1,%2,%3};"
        : "+f"(c[0]), "+f"(c[1]), "+f"(c[2]), "+f"(c[3])
        : "r"(a[0]), "r"(a[1]), "r"(a[2]), "r"(a[3]), "r"(b[0]), "r"(b[1]));
}
__device__ __forceinline__ uint32_t packh(fp16 a, fp16 b) {
    __half2 t; t.x = a; t.y = b; return *(uint32_t*)&t;
}

// ---------------- weight transpose -> fp16 (generic) ----------------
__global__ void tsplit_kernel(const float* __restrict__ W, fp16* __restrict__ T,
                              int K, int N, int roff, size_t out_ls) {
    __shared__ float s[32][33];
    int l = blockIdx.z;
    const float* Wl = W + (size_t)l * K * N;
    fp16* Tl = T + (size_t)l * out_ls;
    int n0 = blockIdx.x * 32, k0 = blockIdx.y * 32;
    int tx = threadIdx.x, ty = threadIdx.y;
    #pragma unroll
    for (int j = 0; j < 4; j++)
        s[ty + 8*j][tx] = Wl[(size_t)(k0 + ty + 8*j) * N + n0 + tx];
    __syncthreads();
    #pragma unroll
    for (int j = 0; j < 4; j++) {
        int row = ty + 8*j;
        Tl[(size_t)(roff + n0 + row) * K + k0 + tx] = __float2half_rn(s[tx][row]);
    }
}

// merged QKV transpose
__global__ void tsplit_qkv(const float* __restrict__ Wq, const float* __restrict__ Wk,
                           const float* __restrict__ Wv, fp16* __restrict__ T) {
    __shared__ float s[32][33];
    int z = blockIdx.z;
    int l = z / 3, which = z % 3;
    const float* W = (which == 0) ? Wq : (which == 1) ? Wk : Wv;
    const float* Wl = W + (size_t)l * DD * DD;
    fp16* Tl = T + (size_t)l * NQKV * DD;
    int roff = which * DD;
    int n0 = blockIdx.x * 32, k0 = blockIdx.y * 32;
    int tx = threadIdx.x, ty = threadIdx.y;
    #pragma unroll
    for (int j = 0; j < 4; j++)
        s[ty + 8*j][tx] = Wl[(size_t)(k0 + ty + 8*j) * DD + n0 + tx];
    __syncthreads();
    #pragma unroll
    for (int j = 0; j < 4; j++) {
        int row = ty + 8*j;
        Tl[(size_t)(roff + n0 + row) * DD + k0 + tx] = __float2half_rn(s[tx][row]);
    }
}

// ---------------- embedding + positional encoding ----------------
__global__ void embed_kernel(const int* __restrict__ x, const float* __restrict__ emb,
                             float* __restrict__ out) {
    int r = blockIdx.x;
    int b = r / LL;
    int tok = x[r];
    const float* erow = emb + (size_t)tok * DD;
    float* orow = out + (size_t)r * DD;
    const float neg_log = -logf(10000.0f) / (float)DD;
    for (int j = 0; j < 3; j++) {
        int d = threadIdx.x + j * 256;
        int i2 = (d >> 1) << 1;
        float div = expf((float)i2 * neg_log);
        float ang = (float)b * div;
        float pe = (d & 1) ? cosf(ang) : sinf(ang);
        orow[d] = erow[d] + pe;
    }
}

// ---------------- layernorm -> fp16 ----------------
__global__ void ln_kernel(const float* __restrict__ in, const float* __restrict__ g,
                          const float* __restrict__ be, fp16* __restrict__ o) {
    __shared__ float red[256];
    int r = blockIdx.x;
    int t = threadIdx.x;
    const float* xr = in + (size_t)r * DD;
    float v0 = xr[t], v1 = xr[t + 256], v2 = xr[t + 512];
    red[t] = v0 + v1 + v2;
    __syncthreads();
    for (int oo = 128; oo > 0; oo >>= 1) { if (t < oo) red[t] += red[t + oo]; __syncthreads(); }
    float mean = red[0] * (1.0f / (float)DD);
    __syncthreads();
    float d0 = v0 - mean, d1 = v1 - mean, d2 = v2 - mean;
    red[t] = d0 * d0 + d1 * d1 + d2 * d2;
    __syncthreads();
    for (int oo = 128; oo > 0; oo >>= 1) { if (t < oo) red[t] += red[t + oo]; __syncthreads(); }
    float var = red[0] * (1.0f / (float)DD);
    float rs = rsqrtf(var + 1e-5f);
    size_t base = (size_t)r * DD;
    o[base + t]       = __float2half(d0 * rs * g[t]       + be[t]);
    o[base + t + 256] = __float2half(d1 * rs * g[t + 256] + be[t + 256]);
    o[base + t + 512] = __float2half(d2 * rs * g[t + 512] + be[t + 512]);
}

// ---------------- HMMA GEMM: 128x64 tile, fp16 single, 1 MMA pass ----------------
// op: 1 = GELU -> fp16, 2 = residual add fp32, 3 = store fp16
#define A_OFF 0
#define B_OFF 10240
#define STG_BYTES 15360
#define NSTG 3
#define GEMM_SMEM (NSTG*STG_BYTES)

__global__ __launch_bounds__(256, 3) void gemm_mma(
    const fp16* __restrict__ A, const fp16* __restrict__ B,
    const float* __restrict__ bias0, const float* __restrict__ bias1,
    const float* __restrict__ bias2,
    float* __restrict__ C, fp16* __restrict__ O,
    int Ntot, int Ktot, int op)
{
    extern __shared__ char dsmem[];
    uint32_t smem_u = smem_to_u32(dsmem);
    int tid = threadIdx.x;
    int lane = tid & 31;
    int wid = tid >> 5;
    int wm = wid & 3;
    int wn = wid >> 2;
    int bm = blockIdx.y * 128, bn = blockIdx.x * 64;

    uint32_t a_off = (uint32_t)((wm*32 + (lane & 15)) * 80 + 16 * (lane >> 4));
    uint32_t b_off = (uint32_t)((wn*32 + 8*((lane >> 4) & 1) + (lane & 7)) * 80
                                + 16 * ((lane >> 3) & 1));

    int brow = tid >> 2, bc = tid & 3;

    float acc[2][4][4];
    #pragma unroll
    for (int i = 0; i < 2; i++)
        #pragma unroll
        for (int j = 0; j < 4; j++)
            #pragma unroll
            for (int q = 0; q < 4; q++) acc[i][j][q] = 0.0f;

    int iters = Ktot >> 5;

    #define LOAD_STAGE(it, buf) do { \
        int k0 = (it) << 5; \
        uint32_t sb = smem_u + (buf) * STG_BYTES; \
        _Pragma("unroll") \
        for (int j = 0; j < 2; j++) { \
            int ci = 2*tid + j; \
            int row = ci >> 2, col = ci & 3; \
            cp_async16(sb + A_OFF + row*80 + col*16, A + (size_t)(bm + row) * Ktot + k0 + col*8); \
        } \
        cp_async16(sb + B_OFF + brow*80 + bc*16, B + (size_t)(bn + brow) * Ktot + k0 + bc*8); \
    } while (0)

    LOAD_STAGE(0, 0); CP_COMMIT();
    LOAD_STAGE(1, 1); CP_COMMIT();

    int buf = 0;
    for (int it = 0; it < iters; it++) {
        CP_WAIT1();
        __syncthreads();
        uint32_t sA = smem_u + buf * STG_BYTES + A_OFF;
        uint32_t sB = smem_u + buf * STG_BYTES + B_OFF;
        #pragma unroll
        for (int ks = 0; ks < 2; ks++) {
            uint32_t a[2][4], b[2][4];
            #pragma unroll
            for (int tm = 0; tm < 2; tm++)
                ldsm4(a[tm], sA + a_off + tm*1280 + ks*32);
            #pragma unroll
            for (int p = 0; p < 2; p++)
                ldsm4(b[p], sB + b_off + p*1280 + ks*32);
            #pragma unroll
            for (int tm = 0; tm < 2; tm++)
                #pragma unroll
                for (int p = 0; p < 2; p++) {
                    mma_f16(acc[tm][2*p],   a[tm], &b[p][0]);
                    mma_f16(acc[tm][2*p+1], a[tm], &b[p][2]);
                }
        }
        int ldbuf = buf + 2; if (ldbuf >= NSTG) ldbuf -= NSTG;
        if (it + 2 < iters) LOAD_STAGE(it + 2, ldbuf);
        CP_COMMIT();
        buf = (buf + 1 == NSTG) ? 0 : buf + 1;
    }
    #undef LOAD_STAGE

    // segmented bias (QKV fused projection)
    const float* beff = bias0;
    int boff = 0;
    if (bias1 != nullptr) {
        if (bn >= 1536)      { beff = bias2; boff = 1536; }
        else if (bn >= 768)  { beff = bias1; boff = 768;  }
    }

    int m_base = bm + wm*32 + (lane >> 2);
    int n_base = bn + wn*32 + (lane & 3)*2;
    #pragma unroll
    for (int tm = 0; tm < 2; tm++) {
        #pragma unroll
        for (int tn = 0; tn < 4; tn++) {
            #pragma unroll
            for (int half = 0; half < 2; half++) {
                int m = m_base + tm*16 + half*8;
                int n = n_base + tn*8;
                float v0 = acc[tm][tn][2*half]     + beff[n - boff];
                float v1 = acc[tm][tn][2*half + 1] + beff[n + 1 - boff];
                size_t idx = (size_t)m * Ntot + n;
                if (op == 1) {
                    float gv0 = 0.5f * v0 * (1.0f + erff(v0 * 0.70710678118654752f));
                    float gv1 = 0.5f * v1 * (1.0f + erff(v1 * 0.70710678118654752f));
                    *(uint32_t*)(O + idx) = packh(__float2half(gv0), __float2half(gv1));
                } else if (op == 2) {
                    C[idx]     += v0;
                    C[idx + 1] += v1;
                } else {  // op == 3
                    *(uint32_t*)(O + idx) = packh(__float2half(v0), __float2half(v1));
                }
            }
        }
    }
}

// ---------------- tensor-core fused attention (fp16 single, 1-pass) ----------------
#define SSTR 520
#define OFF_Q  (64*SSTR*4)          // 133120
#define OFF_K  (OFF_Q + 9216)       // 142336
#define ATTN_SMEM (OFF_K + 18432)   // 160768

__global__ __launch_bounds__(256) void attn_tc(
    const fp16* __restrict__ QKV, const int* __restrict__ mask,
    float* __restrict__ attn_out, fp16* __restrict__ ao)
{
    extern __shared__ char sm[];
    float* S = (float*)sm;
    uint32_t su = smem_to_u32(sm);
    int tid = threadIdx.x, lane = tid & 31, wid = tid >> 5;
    int q0 = blockIdx.x * 64;
    int h = blockIdx.y, b = blockIdx.z;

    // load Q tile (64 rows x 64 fp16)
    {
        int r = tid >> 2, c = tid & 3;
        size_t g = ((size_t)(b*LL + q0 + r)) * NQKV + h*DH;
        const uint4* gq = (const uint4*)(QKV + g);
        *(uint4*)(sm + OFF_Q + r*144 + c*16)     = gq[c];
        *(uint4*)(sm + OFF_Q + r*144 + (c+4)*16) = gq[c+4];
    }

    int wm = wid & 1, wn = wid >> 1;

    // ---- scores ----
    for (int kc = 0; kc < 4; kc++) {
        {
            int r = tid >> 1, c0 = (tid & 1) * 4;
            size_t g = ((size_t)(b*LL + kc*128 + r)) * NQKV + 768 + h*DH;
            const uint4* gk = (const uint4*)(QKV + g);
            #pragma unroll
            for (int c = 0; c < 4; c++)
                *(uint4*)(sm + OFF_K + r*144 + (c0+c)*16) = gk[c0+c];
        }
        __syncthreads();
        float acc[2][4][4];
        #pragma unroll
        for (int i = 0; i < 2; i++)
            #pragma unroll
            for (int j = 0; j < 4; j++)
                #pragma unroll
                for (int q = 0; q < 4; q++) acc[i][j][q] = 0.0f;
        uint32_t aoff = (uint32_t)((wm*32 + (lane & 15)) * 144 + 16 * (lane >> 4));
        uint32_t boff = (uint32_t)((wn*32 + 8*((lane >> 4) & 1) + (lane & 7)) * 144
                                   + 16 * ((lane >> 3) & 1));
        #pragma unroll
        for (int ki = 0; ki < 4; ki++) {
            uint32_t a[2][4], bmat[2][4];
            #pragma unroll
            for (int tm = 0; tm < 2; tm++)
                ldsm4(a[tm], su + OFF_Q + aoff + tm*2304 + ki*32);
            #pragma unroll
            for (int p = 0; p < 2; p++)
                ldsm4(bmat[p], su + OFF_K + boff + p*2304 + ki*32);
            #pragma unroll
            for (int tm = 0; tm < 2; tm++)
                #pragma unroll
                for (int p = 0; p < 2; p++) {
                    mma_f16(acc[tm][2*p],   a[tm], &bmat[p][0]);
                    mma_f16(acc[tm][2*p+1], a[tm], &bmat[p][2]);
                }
        }
        #pragma unroll
        for (int tm = 0; tm < 2; tm++) {
            #pragma unroll
            for (int tn = 0; tn < 4; tn++) {
                int row = wm*32 + tm*16 + (lane >> 2);
                int col = kc*128 + wn*32 + tn*8 + (lane & 3)*2;
                int m0 = mask[b*LL + col], m1 = mask[b*LL + col + 1];
                #pragma unroll
                for (int half = 0; half < 2; half++) {
                    int rr = row + half*8;
                    float v0 = acc[tm][tn][2*half]   * 0.125f - 0.01f * (float)((q0 + rr) - col);
                    float v1 = acc[tm][tn][2*half+1] * 0.125f - 0.01f * (float)((q0 + rr) - (col+1));
                    if (m0 == 0) v0 = -INFINITY;
                    if (m1 == 0) v1 = -INFINITY;
                    S[rr*SSTR + col]     = v0;
                    S[rr*SSTR + col + 1] = v1;
                }
            }
        }
        __syncthreads();
    }

    // ---- softmax + P writeout ----
    {
        size_t gbase0 = ((size_t)(b*HH + h) * LL + q0) * LL;
        #pragma unroll
        for (int j = 0; j < 8; j++) {
            int r = wid*8 + j;
            float4 e[4];
            #pragma unroll
            for (int i = 0; i < 4; i++) e[i] = *(float4*)&S[r*SSTR + i*128 + lane*4];
            float mx = -1e30f;
            #pragma unroll
            for (int i = 0; i < 4; i++)
                mx = fmaxf(mx, fmaxf(fmaxf(e[i].x, e[i].y), fmaxf(e[i].z, e[i].w)));
            #pragma unroll
            for (int o = 16; o > 0; o >>= 1) mx = fmaxf(mx, __shfl_xor_sync(0xFFFFFFFFu, mx, o));
            float sum = 0.0f;
            #pragma unroll
            for (int i = 0; i < 4; i++) {
                e[i].x = __expf(e[i].x - mx); e[i].y = __expf(e[i].y - mx);
                e[i].z = __expf(e[i].z - mx); e[i].w = __expf(e[i].w - mx);
                sum += e[i].x + e[i].y + e[i].z + e[i].w;
            }
            #pragma unroll
            for (int o = 16; o > 0; o >>= 1) sum += __shfl_xor_sync(0xFFFFFFFFu, sum, o);
            float inv = 1.0f / sum;
            float* gp = attn_out + gbase0 + (size_t)r * LL;
            #pragma unroll
            for (int i = 0; i < 4; i++) {
                e[i].x *= inv; e[i].y *= inv; e[i].z *= inv; e[i].w *= inv;
                *(float4*)&S[r*SSTR + i*128 + lane*4] = e[i];
                *(float4*)(gp + i*128 + lane*4) = e[i];
            }
        }
    }
    __syncthreads();

    // ---- AV ----
    float oa[2][2][4];
    #pragma unroll
    for (int i = 0; i < 2; i++)
        #pragma unroll
        for (int j = 0; j < 2; j++)
            #pragma unroll
            for (int q = 0; q < 4; q++) oa[i][j][q] = 0.0f;

    for (int kc = 0; kc < 8; kc++) {
        // convert P chunk (fp32 -> fp16) into Q area
        {
            int r = tid >> 2, c0 = (tid & 3) * 16;
            #pragma unroll
            for (int jj = 0; jj < 2; jj++) {
                const float* sp = &S[r*SSTR + kc*64 + c0 + jj*8];
                float v[8];
                *(float4*)&v[0] = *(const float4*)sp;
                *(float4*)&v[4] = *(const float4*)(sp + 4);
                uint32_t hw[4];
                #pragma unroll
                for (int q = 0; q < 4; q++)
                    hw[q] = packh(__float2half_rn(v[2*q]), __float2half_rn(v[2*q+1]));
                *(uint4*)(sm + OFF_Q + r*144 + (c0 + jj*8)*2) = *(uint4*)hw;
            }
        }
        // load V chunk (64 rows) into K area
        {
            int r = tid >> 2, c = tid & 3;
            size_t g = ((size_t)(b*LL + kc*64 + r)) * NQKV + 1536 + h*DH;
            const uint4* gv = (const uint4*)(QKV + g);
            *(uint4*)(sm + OFF_K + r*144 + c*16)     = gv[c];
            *(uint4*)(sm + OFF_K + r*144 + (c+4)*16) = gv[c+4];
        }
        __syncthreads();
        uint32_t poff = (uint32_t)((wm*32 + (lane & 15)) * 144 + 16 * (lane >> 4));
        uint32_t voff = (uint32_t)((lane & 15) * 144 + wn*32 + 16 * (lane >> 4));
        #pragma unroll
        for (int ki = 0; ki < 4; ki++) {
            uint32_t p[2][4], v[4];
            #pragma unroll
            for (int tm = 0; tm < 2; tm++)
                ldsm4(p[tm], su + OFF_Q + poff + tm*2304 + ki*32);
            ldsm4t(v, su + OFF_K + voff + ki*2304);
            #pragma unroll
            for (int tm = 0; tm < 2; tm++)
                #pragma unroll
                for (int tn = 0; tn < 2; tn++)
                    mma_f16(oa[tm][tn], p[tm], &v[2*tn]);
        }
        __syncthreads();
    }

    #pragma unroll
    for (int tm = 0; tm < 2; tm++) {
        #pragma unroll
        for (int tn = 0; tn < 2; tn++) {
            #pragma unroll
            for (int half = 0; half < 2; half++) {
                int row = wm*32 + tm*16 + (lane >> 2) + half*8;
                int col = wn*16 + tn*8 + (lane & 3)*2;
                float v0 = oa[tm][tn][2*half], v1 = oa[tm][tn][2*half+1];
                size_t g = ((size_t)(b*LL + q0 + row)) * DD + h*DH + col;
                *(uint32_t*)(ao + g) = packh(__float2half(v0), __float2half(v1));
            }
        }
    }
}

// ---------------- classifier head ----------------
__global__ void logits_kernel(const float* __restrict__ h, const float* __restrict__ Wc,
                              const float* __restrict__ bc, float* __restrict__ out) {
    __shared__ float red[256];
    int b = blockIdx.x;
    int t = threadIdx.x;
    float s = 0.0f;
    for (int d = t; d < DD; d += 256) s += h[(size_t)b * LL * DD + d] * Wc[d * NC];
    red[t] = s; __syncthreads();
    for (int o = 128; o > 0; o >>= 1) { if (t < o) red[t] += red[t + o]; __syncthreads(); }
    if (t == 0) out[b * NC] = red[0] + bc[0];
}

// ---------------- launcher ----------------
extern "C" void kernel_launch(void* const* d_in, const int* in_sizes, int n_in,
                              void* d_out, int out_size) {
    const int*   x    = (const int*)  d_in[0];
    const int*   mask = (const int*)  d_in[1];
    const float* emb  = (const float*)d_in[2];
    const float* Wq   = (const float*)d_in[3];
    const float* bq   = (const float*)d_in[4];
    const float* Wk   = (const float*)d_in[5];
    const float* bk   = (const float*)d_in[6];
    const float* Wv   = (const float*)d_in[7];
    const float* bv   = (const float*)d_in[8];
    const float* Wo   = (const float*)d_in[9];
    const float* bo   = (const float*)d_in[10];
    const float* W1   = (const float*)d_in[11];
    const float* b1   = (const float*)d_in[12];
    const float* W2   = (const float*)d_in[13];
    const float* b2   = (const float*)d_in[14];
    const float* g1   = (const float*)d_in[15];
    const float* be1  = (const float*)d_in[16];
    const float* g2   = (const float*)d_in[17];
    const float* be2  = (const float*)d_in[18];
    const float* Wc   = (const float*)d_in[19];
    const float* bc   = (const float*)d_in[20];

    float* out = (float*)d_out;
    float* logits = out;
    float* attn_base = out + (size_t)BB * NC;

    static bool attr_set = false;
    if (!attr_set) {
        cudaFuncSetAttribute(gemm_mma, cudaFuncAttributeMaxDynamicSharedMemorySize, GEMM_SMEM);
        cudaFuncSetAttribute(attn_tc, cudaFuncAttributeMaxDynamicSharedMemorySize, ATTN_SMEM);
        attr_set = true;
    }

    float *p_h;
    fp16 *p_xn, *p_qkv, *p_ao, *p_ff, *p_wqkv, *p_wo, *p_w1, *p_w2;
    cudaGetSymbolAddress((void**)&p_h, g_h);
    cudaGetSymbolAddress((void**)&p_xn, g_xn);
    cudaGetSymbolAddress((void**)&p_qkv, g_qkv);
    cudaGetSymbolAddress((void**)&p_ao, g_ao);
    cudaGetSymbolAddress((void**)&p_ff, g_ff);
    cudaGetSymbolAddress((void**)&p_wqkv, g_wqkv);
    cudaGetSymbolAddress((void**)&p_wo, g_wo);
    cudaGetSymbolAddress((void**)&p_w1, g_w1);
    cudaGetSymbolAddress((void**)&p_w2, g_w2);

    dim3 tb(32, 8);
    size_t olsQKV = (size_t)NQKV * DD;

    dim3 gD(DD/64, MM/128);
    dim3 gQKV(NQKV/64, MM/128);
    dim3 gF(FF/64, MM/128);
    dim3 gAttn(LL/64, HH, BB);

    // Launch order: 1 tsplit_qkv, 2 embed, 3 ln, 4 gemm(QKV) <- ncu capture slot
    tsplit_qkv<<<dim3(DD/32, DD/32, NL*3), tb>>>(Wq, Wk, Wv, p_wqkv);
    embed_kernel<<<MM, 256>>>(x, emb, p_h);

    for (int l = 0; l < NL; l++) {
        size_t wD = (size_t)l * DD * DD;
        size_t wF = (size_t)l * DD * FF;
        size_t wQ = (size_t)l * olsQKV;
        ln_kernel<<<MM, 256>>>(p_h, g1 + l*DD, be1 + l*DD, p_xn);
        gemm_mma<<<gQKV, 256, GEMM_SMEM>>>(p_xn, p_wqkv + wQ,
                                           bq + l*DD, bk + l*DD, bv + l*DD,
                                           nullptr, p_qkv, NQKV, DD, 3);
        if (l == 0) {
            tsplit_kernel<<<dim3(DD/32, DD/32, NL), tb>>>(Wo, p_wo, DD, DD, 0, (size_t)DD*DD);
            tsplit_kernel<<<dim3(FF/32, DD/32, NL), tb>>>(W1, p_w1, DD, FF, 0, (size_t)DD*FF);
            tsplit_kernel<<<dim3(DD/32, FF/32, NL), tb>>>(W2, p_w2, FF, DD, 0, (size_t)FF*DD);
        }
        attn_tc<<<gAttn, 256, ATTN_SMEM>>>(p_qkv, mask,
                                           attn_base + (size_t)l * BB * HH * LL * LL, p_ao);
        gemm_mma<<<gD, 256, GEMM_SMEM>>>(p_ao, p_wo + wD,
                                         bo + l*DD, nullptr, nullptr,
                                         p_h, nullptr, DD, DD, 2);
        ln_kernel<<<MM, 256>>>(p_h, g2 + l*DD, be2 + l*DD, p_xn);
        gemm_mma<<<gF, 256, GEMM_SMEM>>>(p_xn, p_w1 + wF,
                                         b1 + l*FF, nullptr, nullptr,
                                         nullptr, p_ff, FF, DD, 1);
        gemm_mma<<<gD, 256, GEMM_SMEM>>>(p_ff, p_w2 + wF,
                                         b2 + l*DD, nullptr, nullptr,
                                         p_h, nullptr, DD, FF, 2);
    }

    logits_kernel<<<BB, 256>>>(p_h, Wc, bc, logits);
}

// round 13
// speedup vs baseline: 2.1075x; 1.1624x over previous
#include <cuda_runtime.h>
#include <cuda_fp16.h>
#include <math.h>
#include <stdint.h>

#define BB 8
#define LL 512
#define DD 768
#define HH 12
#define DH 64
#define FF 3072
#define NL 6
#define NC 1
#define MM (BB*LL)   // 4096
#define NQKV 2304

typedef __half fp16;

// ---------------- scratch ----------------
__device__ float g_h[MM*DD];
__device__ fp16 g_xn[MM*DD];
__device__ fp16 g_qkv[MM*NQKV];
__device__ fp16 g_ao[MM*DD];
__device__ fp16 g_ff[MM*FF];
__device__ fp16 g_wqkv[NL*NQKV*DD];
__device__ fp16 g_wo[NL*DD*DD];
__device__ fp16 g_w1[NL*DD*FF];
__device__ fp16 g_w2[NL*FF*DD];

// ---------------- PTX helpers ----------------
__device__ __forceinline__ uint32_t smem_to_u32(const void* p) {
    uint32_t a;
    asm("{ .reg .u64 t; cvta.to.shared.u64 t, %1; cvt.u32.u64 %0, t; }" : "=r"(a) : "l"(p));
    return a;
}
__device__ __forceinline__ void cp_async16(uint32_t saddr, const void* gaddr) {
    asm volatile("cp.async.cg.shared.global [%0], [%1], 16;" :: "r"(saddr), "l"(gaddr) : "memory");
}
#define CP_COMMIT() asm volatile("cp.async.commit_group;" ::: "memory")
#define CP_WAIT1()  asm volatile("cp.async.wait_group 1;"  ::: "memory")
__device__ __forceinline__ void ldsm4(uint32_t* r, uint32_t a) {
    asm volatile("ldmatrix.sync.aligned.m8n8.x4.shared.b16 {%0,%1,%2,%3}, [%4];"
        : "=r"(r[0]), "=r"(r[1]), "=r"(r[2]), "=r"(r[3]) : "r"(a));
}
__device__ __forceinline__ void ldsm4t(uint32_t* r, uint32_t a) {
    asm volatile("ldmatrix.sync.aligned.m8n8.x4.trans.shared.b16 {%0,%1,%2,%3}, [%4];"
        : "=r"(r[0]), "=r"(r[1]), "=r"(r[2]), "=r"(r[3]) : "r"(a));
}
__device__ __forceinline__ void mma_f16(float* c, const uint32_t* a, const uint32_t* b) {
    asm volatile("mma.sync.aligned.m16n8k16.row.col.f32.f16.f16.f32 "
        "{%0,%1,%2,%3}, {%4,%5,%6,%7}, {%8,%9}, {%0,%1,%2,%3};"
        : "+f"(c[0]), "+f"(c[1]), "+f"(c[2]), "+f"(c[3])
        : "r"(a[0]), "r"(a[1]), "r"(a[2]), "r"(a[3]), "r"(b[0]), "r"(b[1]));
}
__device__ __forceinline__ uint32_t packh(fp16 a, fp16 b) {
    __half2 t; t.x = a; t.y = b; return *(uint32_t*)&t;
}

// ---------------- weight transpose -> fp16 (generic) ----------------
__global__ void tsplit_kernel(const float* __restrict__ W, fp16* __restrict__ T,
                              int K, int N, int roff, size_t out_ls) {
    __shared__ float s[32][33];
    int l = blockIdx.z;
    const float* Wl = W + (size_t)l * K * N;
    fp16* Tl = T + (size_t)l * out_ls;
    int n0 = blockIdx.x * 32, k0 = blockIdx.y * 32;
    int tx = threadIdx.x, ty = threadIdx.y;
    #pragma unroll
    for (int j = 0; j < 4; j++)
        s[ty + 8*j][tx] = Wl[(size_t)(k0 + ty + 8*j) * N + n0 + tx];
    __syncthreads();
    #pragma unroll
    for (int j = 0; j < 4; j++) {
        int row = ty + 8*j;
        Tl[(size_t)(roff + n0 + row) * K + k0 + tx] = __float2half_rn(s[tx][row]);
    }
}

// merged QKV transpose
__global__ void tsplit_qkv(const float* __restrict__ Wq, const float* __restrict__ Wk,
                           const float* __restrict__ Wv, fp16* __restrict__ T) {
    __shared__ float s[32][33];
    int z = blockIdx.z;
    int l = z / 3, which = z % 3;
    const float* W = (which == 0) ? Wq : (which == 1) ? Wk : Wv;
    const float* Wl = W + (size_t)l * DD * DD;
    fp16* Tl = T + (size_t)l * NQKV * DD;
    int roff = which * DD;
    int n0 = blockIdx.x * 32, k0 = blockIdx.y * 32;
    int tx = threadIdx.x, ty = threadIdx.y;
    #pragma unroll
    for (int j = 0; j < 4; j++)
        s[ty + 8*j][tx] = Wl[(size_t)(k0 + ty + 8*j) * DD + n0 + tx];
    __syncthreads();
    #pragma unroll
    for (int j = 0; j < 4; j++) {
        int row = ty + 8*j;
        Tl[(size_t)(roff + n0 + row) * DD + k0 + tx] = __float2half_rn(s[tx][row]);
    }
}

// ---------------- embedding + positional encoding ----------------
__global__ void embed_kernel(const int* __restrict__ x, const float* __restrict__ emb,
                             float* __restrict__ out) {
    int r = blockIdx.x;
    int b = r / LL;
    int tok = x[r];
    const float* erow = emb + (size_t)tok * DD;
    float* orow = out + (size_t)r * DD;
    const float neg_log = -logf(10000.0f) / (float)DD;
    for (int j = 0; j < 3; j++) {
        int d = threadIdx.x + j * 256;
        int i2 = (d >> 1) << 1;
        float div = expf((float)i2 * neg_log);
        float ang = (float)b * div;
        float pe = (d & 1) ? cosf(ang) : sinf(ang);
        orow[d] = erow[d] + pe;
    }
}

// ---------------- layernorm -> fp16 ----------------
__global__ void ln_kernel(const float* __restrict__ in, const float* __restrict__ g,
                          const float* __restrict__ be, fp16* __restrict__ o) {
    __shared__ float red[256];
    int r = blockIdx.x;
    int t = threadIdx.x;
    const float* xr = in + (size_t)r * DD;
    float v0 = xr[t], v1 = xr[t + 256], v2 = xr[t + 512];
    red[t] = v0 + v1 + v2;
    __syncthreads();
    for (int oo = 128; oo > 0; oo >>= 1) { if (t < oo) red[t] += red[t + oo]; __syncthreads(); }
    float mean = red[0] * (1.0f / (float)DD);
    __syncthreads();
    float d0 = v0 - mean, d1 = v1 - mean, d2 = v2 - mean;
    red[t] = d0 * d0 + d1 * d1 + d2 * d2;
    __syncthreads();
    for (int oo = 128; oo > 0; oo >>= 1) { if (t < oo) red[t] += red[t + oo]; __syncthreads(); }
    float var = red[0] * (1.0f / (float)DD);
    float rs = rsqrtf(var + 1e-5f);
    size_t base = (size_t)r * DD;
    o[base + t]       = __float2half(d0 * rs * g[t]       + be[t]);
    o[base + t + 256] = __float2half(d1 * rs * g[t + 256] + be[t + 256]);
    o[base + t + 512] = __float2half(d2 * rs * g[t + 512] + be[t + 512]);
}

// ---------------- HMMA GEMM: 128x64 tile, K=64 per stage, 2-stage, 3 CTAs/SM ----------------
// op: 1 = GELU -> fp16, 2 = residual add fp32, 3 = store fp16
// rows padded to 144B (9x16B, odd stride -> conflict-free ldsm)
#define A_OFF 0
#define B_OFF 18432
#define STG_BYTES 27648
#define NSTG 2
#define GEMM_SMEM (NSTG*STG_BYTES)

__global__ __launch_bounds__(256, 3) void gemm_mma(
    const fp16* __restrict__ A, const fp16* __restrict__ B,
    const float* __restrict__ bias0, const float* __restrict__ bias1,
    const float* __restrict__ bias2,
    float* __restrict__ C, fp16* __restrict__ O,
    int Ntot, int Ktot, int op)
{
    extern __shared__ char dsmem[];
    uint32_t smem_u = smem_to_u32(dsmem);
    int tid = threadIdx.x;
    int lane = tid & 31;
    int wid = tid >> 5;
    int wm = wid & 3;
    int wn = wid >> 2;
    int bm = blockIdx.y * 128, bn = blockIdx.x * 64;

    uint32_t a_off = (uint32_t)((wm*32 + (lane & 15)) * 144 + 16 * (lane >> 4));
    uint32_t b_off = (uint32_t)((wn*32 + 8*((lane >> 4) & 1) + (lane & 7)) * 144
                                + 16 * ((lane >> 3) & 1));

    float acc[2][4][4];
    #pragma unroll
    for (int i = 0; i < 2; i++)
        #pragma unroll
        for (int j = 0; j < 4; j++)
            #pragma unroll
            for (int q = 0; q < 4; q++) acc[i][j][q] = 0.0f;

    int iters = Ktot >> 6;

    // A: 128 rows x 8 chunks = 1024 -> 4/thread; B: 64 rows x 8 = 512 -> 2/thread
    #define LOAD_STAGE(it, buf) do { \
        int k0 = (it) << 6; \
        uint32_t sb = smem_u + (buf) * STG_BYTES; \
        _Pragma("unroll") \
        for (int j = 0; j < 4; j++) { \
            int ci = tid + j * 256; \
            int row = ci >> 3, col = ci & 7; \
            cp_async16(sb + A_OFF + row*144 + col*16, A + (size_t)(bm + row) * Ktot + k0 + col*8); \
        } \
        _Pragma("unroll") \
        for (int j = 0; j < 2; j++) { \
            int ci = tid + j * 256; \
            int row = ci >> 3, col = ci & 7; \
            cp_async16(sb + B_OFF + row*144 + col*16, B + (size_t)(bn + row) * Ktot + k0 + col*8); \
        } \
    } while (0)

    LOAD_STAGE(0, 0); CP_COMMIT();
    if (iters > 1) { LOAD_STAGE(1, 1); } CP_COMMIT();

    for (int it = 0; it < iters; it++) {
        CP_WAIT1();
        __syncthreads();
        int buf = it & 1;
        uint32_t sA = smem_u + buf * STG_BYTES + A_OFF;
        uint32_t sB = smem_u + buf * STG_BYTES + B_OFF;
        #pragma unroll
        for (int ks = 0; ks < 4; ks++) {
            uint32_t a[2][4], b[2][4];
            #pragma unroll
            for (int tm = 0; tm < 2; tm++)
                ldsm4(a[tm], sA + a_off + tm*2304 + ks*32);
            #pragma unroll
            for (int p = 0; p < 2; p++)
                ldsm4(b[p], sB + b_off + p*2304 + ks*32);
            #pragma unroll
            for (int tm = 0; tm < 2; tm++)
                #pragma unroll
                for (int p = 0; p < 2; p++) {
                    mma_f16(acc[tm][2*p],   a[tm], &b[p][0]);
                    mma_f16(acc[tm][2*p+1], a[tm], &b[p][2]);
                }
        }
        __syncthreads();
        if (it + 2 < iters) LOAD_STAGE(it + 2, buf);
        CP_COMMIT();
    }
    #undef LOAD_STAGE

    // segmented bias (QKV fused projection)
    const float* beff = bias0;
    int boff = 0;
    if (bias1 != nullptr) {
        if (bn >= 1536)      { beff = bias2; boff = 1536; }
        else if (bn >= 768)  { beff = bias1; boff = 768;  }
    }

    int m_base = bm + wm*32 + (lane >> 2);
    int n_base = bn + wn*32 + (lane & 3)*2;
    #pragma unroll
    for (int tm = 0; tm < 2; tm++) {
        #pragma unroll
        for (int tn = 0; tn < 4; tn++) {
            #pragma unroll
            for (int half = 0; half < 2; half++) {
                int m = m_base + tm*16 + half*8;
                int n = n_base + tn*8;
                float v0 = acc[tm][tn][2*half]     + beff[n - boff];
                float v1 = acc[tm][tn][2*half + 1] + beff[n + 1 - boff];
                size_t idx = (size_t)m * Ntot + n;
                if (op == 1) {
                    float gv0 = 0.5f * v0 * (1.0f + erff(v0 * 0.70710678118654752f));
                    float gv1 = 0.5f * v1 * (1.0f + erff(v1 * 0.70710678118654752f));
                    *(uint32_t*)(O + idx) = packh(__float2half(gv0), __float2half(gv1));
                } else if (op == 2) {
                    C[idx]     += v0;
                    C[idx + 1] += v1;
                } else {  // op == 3
                    *(uint32_t*)(O + idx) = packh(__float2half(v0), __float2half(v1));
                }
            }
        }
    }
}

// ---------------- tensor-core fused attention (fp16, 1-pass) ----------------
#define SSTR 520
#define OFF_Q  (64*SSTR*4)          // 133120
#define OFF_K  (OFF_Q + 9216)       // 142336
#define ATTN_SMEM (OFF_K + 18432)   // 160768

__global__ __launch_bounds__(256) void attn_tc(
    const fp16* __restrict__ QKV, const int* __restrict__ mask,
    float* __restrict__ attn_out, fp16* __restrict__ ao)
{
    extern __shared__ char sm[];
    float* S = (float*)sm;
    uint32_t su = smem_to_u32(sm);
    int tid = threadIdx.x, lane = tid & 31, wid = tid >> 5;
    int q0 = blockIdx.x * 64;
    int h = blockIdx.y, b = blockIdx.z;

    {
        int r = tid >> 2, c = tid & 3;
        size_t g = ((size_t)(b*LL + q0 + r)) * NQKV + h*DH;
        const uint4* gq = (const uint4*)(QKV + g);
        *(uint4*)(sm + OFF_Q + r*144 + c*16)     = gq[c];
        *(uint4*)(sm + OFF_Q + r*144 + (c+4)*16) = gq[c+4];
    }

    int wm = wid & 1, wn = wid >> 1;

    for (int kc = 0; kc < 4; kc++) {
        {
            int r = tid >> 1, c0 = (tid & 1) * 4;
            size_t g = ((size_t)(b*LL + kc*128 + r)) * NQKV + 768 + h*DH;
            const uint4* gk = (const uint4*)(QKV + g);
            #pragma unroll
            for (int c = 0; c < 4; c++)
                *(uint4*)(sm + OFF_K + r*144 + (c0+c)*16) = gk[c0+c];
        }
        __syncthreads();
        float acc[2][4][4];
        #pragma unroll
        for (int i = 0; i < 2; i++)
            #pragma unroll
            for (int j = 0; j < 4; j++)
                #pragma unroll
                for (int q = 0; q < 4; q++) acc[i][j][q] = 0.0f;
        uint32_t aoff = (uint32_t)((wm*32 + (lane & 15)) * 144 + 16 * (lane >> 4));
        uint32_t boff = (uint32_t)((wn*32 + 8*((lane >> 4) & 1) + (lane & 7)) * 144
                                   + 16 * ((lane >> 3) & 1));
        #pragma unroll
        for (int ki = 0; ki < 4; ki++) {
            uint32_t a[2][4], bmat[2][4];
            #pragma unroll
            for (int tm = 0; tm < 2; tm++)
                ldsm4(a[tm], su + OFF_Q + aoff + tm*2304 + ki*32);
            #pragma unroll
            for (int p = 0; p < 2; p++)
                ldsm4(bmat[p], su + OFF_K + boff + p*2304 + ki*32);
            #pragma unroll
            for (int tm = 0; tm < 2; tm++)
                #pragma unroll
                for (int p = 0; p < 2; p++) {
                    mma_f16(acc[tm][2*p],   a[tm], &bmat[p][0]);
                    mma_f16(acc[tm][2*p+1], a[tm], &bmat[p][2]);
                }
        }
        #pragma unroll
        for (int tm = 0; tm < 2; tm++) {
            #pragma unroll
            for (int tn = 0; tn < 4; tn++) {
                int row = wm*32 + tm*16 + (lane >> 2);
                int col = kc*128 + wn*32 + tn*8 + (lane & 3)*2;
                int m0 = mask[b*LL + col], m1 = mask[b*LL + col + 1];
                #pragma unroll
                for (int half = 0; half < 2; half++) {
                    int rr = row + half*8;
                    float v0 = acc[tm][tn][2*half]   * 0.125f - 0.01f * (float)((q0 + rr) - col);
                    float v1 = acc[tm][tn][2*half+1] * 0.125f - 0.01f * (float)((q0 + rr) - (col+1));
                    if (m0 == 0) v0 = -INFINITY;
                    if (m1 == 0) v1 = -INFINITY;
                    S[rr*SSTR + col]     = v0;
                    S[rr*SSTR + col + 1] = v1;
                }
            }
        }
        __syncthreads();
    }

    {
        size_t gbase0 = ((size_t)(b*HH + h) * LL + q0) * LL;
        #pragma unroll
        for (int j = 0; j < 8; j++) {
            int r = wid*8 + j;
            float4 e[4];
            #pragma unroll
            for (int i = 0; i < 4; i++) e[i] = *(float4*)&S[r*SSTR + i*128 + lane*4];
            float mx = -1e30f;
            #pragma unroll
            for (int i = 0; i < 4; i++)
                mx = fmaxf(mx, fmaxf(fmaxf(e[i].x, e[i].y), fmaxf(e[i].z, e[i].w)));
            #pragma unroll
            for (int o = 16; o > 0; o >>= 1) mx = fmaxf(mx, __shfl_xor_sync(0xFFFFFFFFu, mx, o));
            float sum = 0.0f;
            #pragma unroll
            for (int i = 0; i < 4; i++) {
                e[i].x = __expf(e[i].x - mx); e[i].y = __expf(e[i].y - mx);
                e[i].z = __expf(e[i].z - mx); e[i].w = __expf(e[i].w - mx);
                sum += e[i].x + e[i].y + e[i].z + e[i].w;
            }
            #pragma unroll
            for (int o = 16; o > 0; o >>= 1) sum += __shfl_xor_sync(0xFFFFFFFFu, sum, o);
            float inv = 1.0f / sum;
            float* gp = attn_out + gbase0 + (size_t)r * LL;
            #pragma unroll
            for (int i = 0; i < 4; i++) {
                e[i].x *= inv; e[i].y *= inv; e[i].z *= inv; e[i].w *= inv;
                *(float4*)&S[r*SSTR + i*128 + lane*4] = e[i];
                *(float4*)(gp + i*128 + lane*4) = e[i];
            }
        }
    }
    __syncthreads();

    float oa[2][2][4];
    #pragma unroll
    for (int i = 0; i < 2; i++)
        #pragma unroll
        for (int j = 0; j < 2; j++)
            #pragma unroll
            for (int q = 0; q < 4; q++) oa[i][j][q] = 0.0f;

    for (int kc = 0; kc < 8; kc++) {
        {
            int r = tid >> 2, c0 = (tid & 3) * 16;
            #pragma unroll
            for (int jj = 0; jj < 2; jj++) {
                const float* sp = &S[r*SSTR + kc*64 + c0 + jj*8];
                float v[8];
                *(float4*)&v[0] = *(const float4*)sp;
                *(float4*)&v[4] = *(const float4*)(sp + 4);
                uint32_t hw[4];
                #pragma unroll
                for (int q = 0; q < 4; q++)
                    hw[q] = packh(__float2half_rn(v[2*q]), __float2half_rn(v[2*q+1]));
                *(uint4*)(sm + OFF_Q + r*144 + (c0 + jj*8)*2) = *(uint4*)hw;
            }
        }
        {
            int r = tid >> 2, c = tid & 3;
            size_t g = ((size_t)(b*LL + kc*64 + r)) * NQKV + 1536 + h*DH;
            const uint4* gv = (const uint4*)(QKV + g);
            *(uint4*)(sm + OFF_K + r*144 + c*16)     = gv[c];
            *(uint4*)(sm + OFF_K + r*144 + (c+4)*16) = gv[c+4];
        }
        __syncthreads();
        uint32_t poff = (uint32_t)((wm*32 + (lane & 15)) * 144 + 16 * (lane >> 4));
        uint32_t voff = (uint32_t)((lane & 15) * 144 + wn*32 + 16 * (lane >> 4));
        #pragma unroll
        for (int ki = 0; ki < 4; ki++) {
            uint32_t p[2][4], v[4];
            #pragma unroll
            for (int tm = 0; tm < 2; tm++)
                ldsm4(p[tm], su + OFF_Q + poff + tm*2304 + ki*32);
            ldsm4t(v, su + OFF_K + voff + ki*2304);
            #pragma unroll
            for (int tm = 0; tm < 2; tm++)
                #pragma unroll
                for (int tn = 0; tn < 2; tn++)
                    mma_f16(oa[tm][tn], p[tm], &v[2*tn]);
        }
        __syncthreads();
    }

    #pragma unroll
    for (int tm = 0; tm < 2; tm++) {
        #pragma unroll
        for (int tn = 0; tn < 2; tn++) {
            #pragma unroll
            for (int half = 0; half < 2; half++) {
                int row = wm*32 + tm*16 + (lane >> 2) + half*8;
                int col = wn*16 + tn*8 + (lane & 3)*2;
                float v0 = oa[tm][tn][2*half], v1 = oa[tm][tn][2*half+1];
                size_t g = ((size_t)(b*LL + q0 + row)) * DD + h*DH + col;
                *(uint32_t*)(ao + g) = packh(__float2half(v0), __float2half(v1));
            }
        }
    }
}

// ---------------- classifier head ----------------
__global__ void logits_kernel(const float* __restrict__ h, const float* __restrict__ Wc,
                              const float* __restrict__ bc, float* __restrict__ out) {
    __shared__ float red[256];
    int b = blockIdx.x;
    int t = threadIdx.x;
    float s = 0.0f;
    for (int d = t; d < DD; d += 256) s += h[(size_t)b * LL * DD + d] * Wc[d * NC];
    red[t] = s; __syncthreads();
    for (int o = 128; o > 0; o >>= 1) { if (t < o) red[t] += red[t + o]; __syncthreads(); }
    if (t == 0) out[b * NC] = red[0] + bc[0];
}

// ---------------- launcher ----------------
extern "C" void kernel_launch(void* const* d_in, const int* in_sizes, int n_in,
                              void* d_out, int out_size) {
    const int*   x    = (const int*)  d_in[0];
    const int*   mask = (const int*)  d_in[1];
    const float* emb  = (const float*)d_in[2];
    const float* Wq   = (const float*)d_in[3];
    const float* bq   = (const float*)d_in[4];
    const float* Wk   = (const float*)d_in[5];
    const float* bk   = (const float*)d_in[6];
    const float* Wv   = (const float*)d_in[7];
    const float* bv   = (const float*)d_in[8];
    const float* Wo   = (const float*)d_in[9];
    const float* bo   = (const float*)d_in[10];
    const float* W1   = (const float*)d_in[11];
    const float* b1   = (const float*)d_in[12];
    const float* W2   = (const float*)d_in[13];
    const float* b2   = (const float*)d_in[14];
    const float* g1   = (const float*)d_in[15];
    const float* be1  = (const float*)d_in[16];
    const float* g2   = (const float*)d_in[17];
    const float* be2  = (const float*)d_in[18];
    const float* Wc   = (const float*)d_in[19];
    const float* bc   = (const float*)d_in[20];

    float* out = (float*)d_out;
    float* logits = out;
    float* attn_base = out + (size_t)BB * NC;

    static bool attr_set = false;
    if (!attr_set) {
        cudaFuncSetAttribute(gemm_mma, cudaFuncAttributeMaxDynamicSharedMemorySize, GEMM_SMEM);
        cudaFuncSetAttribute(attn_tc, cudaFuncAttributeMaxDynamicSharedMemorySize, ATTN_SMEM);
        attr_set = true;
    }

    float *p_h;
    fp16 *p_xn, *p_qkv, *p_ao, *p_ff, *p_wqkv, *p_wo, *p_w1, *p_w2;
    cudaGetSymbolAddress((void**)&p_h, g_h);
    cudaGetSymbolAddress((void**)&p_xn, g_xn);
    cudaGetSymbolAddress((void**)&p_qkv, g_qkv);
    cudaGetSymbolAddress((void**)&p_ao, g_ao);
    cudaGetSymbolAddress((void**)&p_ff, g_ff);
    cudaGetSymbolAddress((void**)&p_wqkv, g_wqkv);
    cudaGetSymbolAddress((void**)&p_wo, g_wo);
    cudaGetSymbolAddress((void**)&p_w1, g_w1);
    cudaGetSymbolAddress((void**)&p_w2, g_w2);

    dim3 tb(32, 8);
    size_t olsQKV = (size_t)NQKV * DD;

    dim3 gD(DD/64, MM/128);
    dim3 gQKV(NQKV/64, MM/128);
    dim3 gF(FF/64, MM/128);
    dim3 gAttn(LL/64, HH, BB);

    // Launch order: 1 tsplit_qkv, 2 embed, 3 ln, 4 gemm(QKV) <- ncu capture slot
    tsplit_qkv<<<dim3(DD/32, DD/32, NL*3), tb>>>(Wq, Wk, Wv, p_wqkv);
    embed_kernel<<<MM, 256>>>(x, emb, p_h);

    for (int l = 0; l < NL; l++) {
        size_t wD = (size_t)l * DD * DD;
        size_t wF = (size_t)l * DD * FF;
        size_t wQ = (size_t)l * olsQKV;
        ln_kernel<<<MM, 256>>>(p_h, g1 + l*DD, be1 + l*DD, p_xn);
        gemm_mma<<<gQKV, 256, GEMM_SMEM>>>(p_xn, p_wqkv + wQ,
                                           bq + l*DD, bk + l*DD, bv + l*DD,
                                           nullptr, p_qkv, NQKV, DD, 3);
        if (l == 0) {
            tsplit_kernel<<<dim3(DD/32, DD/32, NL), tb>>>(Wo, p_wo, DD, DD, 0, (size_t)DD*DD);
            tsplit_kernel<<<dim3(FF/32, DD/32, NL), tb>>>(W1, p_w1, DD, FF, 0, (size_t)DD*FF);
            tsplit_kernel<<<dim3(DD/32, FF/32, NL), tb>>>(W2, p_w2, FF, DD, 0, (size_t)FF*DD);
        }
        attn_tc<<<gAttn, 256, ATTN_SMEM>>>(p_qkv, mask,
                                           attn_base + (size_t)l * BB * HH * LL * LL, p_ao);
        gemm_mma<<<gD, 256, GEMM_SMEM>>>(p_ao, p_wo + wD,
                                         bo + l*DD, nullptr, nullptr,
                                         p_h, nullptr, DD, DD, 2);
        ln_kernel<<<MM, 256>>>(p_h, g2 + l*DD, be2 + l*DD, p_xn);
        gemm_mma<<<gF, 256, GEMM_SMEM>>>(p_xn, p_w1 + wF,
                                         b1 + l*FF, nullptr, nullptr,
                                         nullptr, p_ff, FF, DD, 1);
        gemm_mma<<<gD, 256, GEMM_SMEM>>>(p_ff, p_w2 + wF,
                                         b2 + l*DD, nullptr, nullptr,
                                         p_h, nullptr, DD, FF, 2);
    }

    logits_kernel<<<BB, 256>>>(p_h, Wc, bc, logits);
}

// round 14
// speedup vs baseline: 2.2385x; 1.0621x over previous
#include <cuda_runtime.h>
#include <cuda_fp16.h>
#include <math.h>
#include <stdint.h>

#define BB 8
#define LL 512
#define DD 768
#define HH 12
#define DH 64
#define FF 3072
#define NL 6
#define NC 1
#define MM (BB*LL)   // 4096
#define NQKV 2304

typedef __half fp16;

// ---------------- scratch ----------------
__device__ float g_h[MM*DD];
__device__ fp16 g_xn[MM*DD];
__device__ fp16 g_qkv[MM*NQKV];
__device__ fp16 g_ao[MM*DD];
__device__ fp16 g_ff[MM*FF];
__device__ fp16 g_wqkv[NL*NQKV*DD];
__device__ fp16 g_wo[NL*DD*DD];
__device__ fp16 g_w1[NL*DD*FF];
__device__ fp16 g_w2[NL*FF*DD];

// ---------------- PTX helpers ----------------
__device__ __forceinline__ uint32_t smem_to_u32(const void* p) {
    uint32_t a;
    asm("{ .reg .u64 t; cvta.to.shared.u64 t, %1; cvt.u32.u64 %0, t; }" : "=r"(a) : "l"(p));
    return a;
}
__device__ __forceinline__ void cp_async16(uint32_t saddr, const void* gaddr) {
    asm volatile("cp.async.cg.shared.global [%0], [%1], 16;" :: "r"(saddr), "l"(gaddr) : "memory");
}
#define CP_COMMIT() asm volatile("cp.async.commit_group;" ::: "memory")
#define CP_WAIT1()  asm volatile("cp.async.wait_group 1;"  ::: "memory")
__device__ __forceinline__ void ldsm4(uint32_t* r, uint32_t a) {
    asm volatile("ldmatrix.sync.aligned.m8n8.x4.shared.b16 {%0,%1,%2,%3}, [%4];"
        : "=r"(r[0]), "=r"(r[1]), "=r"(r[2]), "=r"(r[3]) : "r"(a));
}
__device__ __forceinline__ void ldsm4t(uint32_t* r, uint32_t a) {
    asm volatile("ldmatrix.sync.aligned.m8n8.x4.trans.shared.b16 {%0,%1,%2,%3}, [%4];"
        : "=r"(r[0]), "=r"(r[1]), "=r"(r[2]), "=r"(r[3]) : "r"(a));
}
__device__ __forceinline__ void mma_f16(float* c, const uint32_t* a, const uint32_t* b) {
    asm volatile("mma.sync.aligned.m16n8k16.row.col.f32.f16.f16.f32 "
        "{%0,%1,%2,%3}, {%4,%5,%6,%7}, {%8,%9}, {%0,%1,%2,%3};"
        : "+f"(c[0]), "+f"(c[1]), "+f"(c[2]), "+f"(c[3])
        : "r"(a[0]), "r"(a[1]), "r"(a[2]), "r"(a[3]), "r"(b[0]), "r"(b[1]));
}
__device__ __forceinline__ uint32_t packh(fp16 a, fp16 b) {
    __half2 t; t.x = a; t.y = b; return *(uint32_t*)&t;
}

// ---------------- weight transpose -> fp16 (generic) ----------------
__global__ void tsplit_kernel(const float* __restrict__ W, fp16* __restrict__ T,
                              int K, int N, int roff, size_t out_ls) {
    __shared__ float s[32][33];
    int l = blockIdx.z;
    const float* Wl = W + (size_t)l * K * N;
    fp16* Tl = T + (size_t)l * out_ls;
    int n0 = blockIdx.x * 32, k0 = blockIdx.y * 32;
    int tx = threadIdx.x, ty = threadIdx.y;
    #pragma unroll
    for (int j = 0; j < 4; j++)
        s[ty + 8*j][tx] = Wl[(size_t)(k0 + ty + 8*j) * N + n0 + tx];
    __syncthreads();
    #pragma unroll
    for (int j = 0; j < 4; j++) {
        int row = ty + 8*j;
        Tl[(size_t)(roff + n0 + row) * K + k0 + tx] = __float2half_rn(s[tx][row]);
    }
}

// merged QKV transpose
__global__ void tsplit_qkv(const float* __restrict__ Wq, const float* __restrict__ Wk,
                           const float* __restrict__ Wv, fp16* __restrict__ T) {
    __shared__ float s[32][33];
    int z = blockIdx.z;
    int l = z / 3, which = z % 3;
    const float* W = (which == 0) ? Wq : (which == 1) ? Wk : Wv;
    const float* Wl = W + (size_t)l * DD * DD;
    fp16* Tl = T + (size_t)l * NQKV * DD;
    int roff = which * DD;
    int n0 = blockIdx.x * 32, k0 = blockIdx.y * 32;
    int tx = threadIdx.x, ty = threadIdx.y;
    #pragma unroll
    for (int j = 0; j < 4; j++)
        s[ty + 8*j][tx] = Wl[(size_t)(k0 + ty + 8*j) * DD + n0 + tx];
    __syncthreads();
    #pragma unroll
    for (int j = 0; j < 4; j++) {
        int row = ty + 8*j;
        Tl[(size_t)(roff + n0 + row) * DD + k0 + tx] = __float2half_rn(s[tx][row]);
    }
}

// ---------------- embedding + positional encoding ----------------
__global__ void embed_kernel(const int* __restrict__ x, const float* __restrict__ emb,
                             float* __restrict__ out) {
    int r = blockIdx.x;
    int b = r / LL;
    int tok = x[r];
    const float* erow = emb + (size_t)tok * DD;
    float* orow = out + (size_t)r * DD;
    const float neg_log = -logf(10000.0f) / (float)DD;
    for (int j = 0; j < 3; j++) {
        int d = threadIdx.x + j * 256;
        int i2 = (d >> 1) << 1;
        float div = expf((float)i2 * neg_log);
        float ang = (float)b * div;
        float pe = (d & 1) ? cosf(ang) : sinf(ang);
        orow[d] = erow[d] + pe;
    }
}

// ---------------- layernorm -> fp16 ----------------
__global__ void ln_kernel(const float* __restrict__ in, const float* __restrict__ g,
                          const float* __restrict__ be, fp16* __restrict__ o) {
    __shared__ float red[256];
    int r = blockIdx.x;
    int t = threadIdx.x;
    const float* xr = in + (size_t)r * DD;
    float v0 = xr[t], v1 = xr[t + 256], v2 = xr[t + 512];
    red[t] = v0 + v1 + v2;
    __syncthreads();
    for (int oo = 128; oo > 0; oo >>= 1) { if (t < oo) red[t] += red[t + oo]; __syncthreads(); }
    float mean = red[0] * (1.0f / (float)DD);
    __syncthreads();
    float d0 = v0 - mean, d1 = v1 - mean, d2 = v2 - mean;
    red[t] = d0 * d0 + d1 * d1 + d2 * d2;
    __syncthreads();
    for (int oo = 128; oo > 0; oo >>= 1) { if (t < oo) red[t] += red[t + oo]; __syncthreads(); }
    float var = red[0] * (1.0f / (float)DD);
    float rs = rsqrtf(var + 1e-5f);
    size_t base = (size_t)r * DD;
    o[base + t]       = __float2half(d0 * rs * g[t]       + be[t]);
    o[base + t + 256] = __float2half(d1 * rs * g[t + 256] + be[t + 256]);
    o[base + t + 512] = __float2half(d2 * rs * g[t + 512] + be[t + 512]);
}

// ---------------- HMMA GEMM: 128x64 tile, K=64 per stage, 2-stage, 3 CTAs/SM ----------------
#define A_OFF 0
#define B_OFF 18432
#define STG_BYTES 27648
#define NSTG 2
#define GEMM_SMEM (NSTG*STG_BYTES)

__global__ __launch_bounds__(256, 3) void gemm_mma(
    const fp16* __restrict__ A, const fp16* __restrict__ B,
    const float* __restrict__ bias0, const float* __restrict__ bias1,
    const float* __restrict__ bias2,
    float* __restrict__ C, fp16* __restrict__ O,
    int Ntot, int Ktot, int op)
{
    extern __shared__ char dsmem[];
    uint32_t smem_u = smem_to_u32(dsmem);
    int tid = threadIdx.x;
    int lane = tid & 31;
    int wid = tid >> 5;
    int wm = wid & 3;
    int wn = wid >> 2;
    int bm = blockIdx.y * 128, bn = blockIdx.x * 64;

    uint32_t a_off = (uint32_t)((wm*32 + (lane & 15)) * 144 + 16 * (lane >> 4));
    uint32_t b_off = (uint32_t)((wn*32 + 8*((lane >> 4) & 1) + (lane & 7)) * 144
                                + 16 * ((lane >> 3) & 1));

    float acc[2][4][4];
    #pragma unroll
    for (int i = 0; i < 2; i++)
        #pragma unroll
        for (int j = 0; j < 4; j++)
            #pragma unroll
            for (int q = 0; q < 4; q++) acc[i][j][q] = 0.0f;

    int iters = Ktot >> 6;

    #define LOAD_STAGE(it, buf) do { \
        int k0 = (it) << 6; \
        uint32_t sb = smem_u + (buf) * STG_BYTES; \
        _Pragma("unroll") \
        for (int j = 0; j < 4; j++) { \
            int ci = tid + j * 256; \
            int row = ci >> 3, col = ci & 7; \
            cp_async16(sb + A_OFF + row*144 + col*16, A + (size_t)(bm + row) * Ktot + k0 + col*8); \
        } \
        _Pragma("unroll") \
        for (int j = 0; j < 2; j++) { \
            int ci = tid + j * 256; \
            int row = ci >> 3, col = ci & 7; \
            cp_async16(sb + B_OFF + row*144 + col*16, B + (size_t)(bn + row) * Ktot + k0 + col*8); \
        } \
    } while (0)

    LOAD_STAGE(0, 0); CP_COMMIT();
    if (iters > 1) { LOAD_STAGE(1, 1); } CP_COMMIT();

    for (int it = 0; it < iters; it++) {
        CP_WAIT1();
        __syncthreads();
        int buf = it & 1;
        uint32_t sA = smem_u + buf * STG_BYTES + A_OFF;
        uint32_t sB = smem_u + buf * STG_BYTES + B_OFF;
        #pragma unroll
        for (int ks = 0; ks < 4; ks++) {
            uint32_t a[2][4], b[2][4];
            #pragma unroll
            for (int tm = 0; tm < 2; tm++)
                ldsm4(a[tm], sA + a_off + tm*2304 + ks*32);
            #pragma unroll
            for (int p = 0; p < 2; p++)
                ldsm4(b[p], sB + b_off + p*2304 + ks*32);
            #pragma unroll
            for (int tm = 0; tm < 2; tm++)
                #pragma unroll
                for (int p = 0; p < 2; p++) {
                    mma_f16(acc[tm][2*p],   a[tm], &b[p][0]);
                    mma_f16(acc[tm][2*p+1], a[tm], &b[p][2]);
                }
        }
        __syncthreads();
        if (it + 2 < iters) LOAD_STAGE(it + 2, buf);
        CP_COMMIT();
    }
    #undef LOAD_STAGE

    const float* beff = bias0;
    int boff = 0;
    if (bias1 != nullptr) {
        if (bn >= 1536)      { beff = bias2; boff = 1536; }
        else if (bn >= 768)  { beff = bias1; boff = 768;  }
    }

    int m_base = bm + wm*32 + (lane >> 2);
    int n_base = bn + wn*32 + (lane & 3)*2;
    #pragma unroll
    for (int tm = 0; tm < 2; tm++) {
        #pragma unroll
        for (int tn = 0; tn < 4; tn++) {
            #pragma unroll
            for (int half = 0; half < 2; half++) {
                int m = m_base + tm*16 + half*8;
                int n = n_base + tn*8;
                float v0 = acc[tm][tn][2*half]     + beff[n - boff];
                float v1 = acc[tm][tn][2*half + 1] + beff[n + 1 - boff];
                size_t idx = (size_t)m * Ntot + n;
                if (op == 1) {
                    float gv0 = 0.5f * v0 * (1.0f + erff(v0 * 0.70710678118654752f));
                    float gv1 = 0.5f * v1 * (1.0f + erff(v1 * 0.70710678118654752f));
                    *(uint32_t*)(O + idx) = packh(__float2half(gv0), __float2half(gv1));
                } else if (op == 2) {
                    C[idx]     += v0;
                    C[idx + 1] += v1;
                } else {
                    *(uint32_t*)(O + idx) = packh(__float2half(v0), __float2half(v1));
                }
            }
        }
    }
}

// ---------------- tensor-core fused attention: 32-row Q tiles, 2 CTAs/SM ----------------
#define SSTR 520
#define OFF_Q  (32*SSTR*4)          // 66560
#define OFF_K  (OFF_Q + 32*144)     // 71168
#define ATTN_SMEM (OFF_K + 128*144) // 89600

__global__ __launch_bounds__(256, 2) void attn_tc(
    const fp16* __restrict__ QKV, const int* __restrict__ mask,
    float* __restrict__ attn_out, fp16* __restrict__ ao)
{
    extern __shared__ char sm[];
    float* S = (float*)sm;
    uint32_t su = smem_to_u32(sm);
    int tid = threadIdx.x, lane = tid & 31, wid = tid >> 5;
    int q0 = blockIdx.x * 32;
    int h = blockIdx.y, b = blockIdx.z;

    // load Q tile (32 rows x 64 fp16)
    {
        int r = tid >> 3, c = tid & 7;
        size_t g = ((size_t)(b*LL + q0 + r)) * NQKV + h*DH;
        *(uint4*)(sm + OFF_Q + r*144 + c*16) = ((const uint4*)(QKV + g))[c];
    }

    // ---- scores: 8 warps x (32 rows x 16 cols) per 128-col chunk ----
    for (int kc = 0; kc < 4; kc++) {
        {
            int r = tid >> 1, c0 = (tid & 1) * 4;
            size_t g = ((size_t)(b*LL + kc*128 + r)) * NQKV + 768 + h*DH;
            const uint4* gk = (const uint4*)(QKV + g);
            #pragma unroll
            for (int c = 0; c < 4; c++)
                *(uint4*)(sm + OFF_K + r*144 + (c0+c)*16) = gk[c0+c];
        }
        __syncthreads();
        float acc[2][2][4];
        #pragma unroll
        for (int i = 0; i < 2; i++)
            #pragma unroll
            for (int j = 0; j < 2; j++)
                #pragma unroll
                for (int q = 0; q < 4; q++) acc[i][j][q] = 0.0f;
        uint32_t aoff = (uint32_t)((lane & 15) * 144 + 16 * (lane >> 4));
        uint32_t boff = (uint32_t)((wid*16 + 8*((lane >> 4) & 1) + (lane & 7)) * 144
                                   + 16 * ((lane >> 3) & 1));
        #pragma unroll
        for (int ki = 0; ki < 4; ki++) {
            uint32_t a[2][4], bmat[4];
            ldsm4(a[0], su + OFF_Q + aoff + ki*32);
            ldsm4(a[1], su + OFF_Q + aoff + 2304 + ki*32);
            ldsm4(bmat, su + OFF_K + boff + ki*32);
            #pragma unroll
            for (int tm = 0; tm < 2; tm++) {
                mma_f16(acc[tm][0], a[tm], &bmat[0]);
                mma_f16(acc[tm][1], a[tm], &bmat[2]);
            }
        }
        #pragma unroll
        for (int tm = 0; tm < 2; tm++) {
            #pragma unroll
            for (int tn = 0; tn < 2; tn++) {
                int row = tm*16 + (lane >> 2);
                int col = kc*128 + wid*16 + tn*8 + (lane & 3)*2;
                int m0 = mask[b*LL + col], m1 = mask[b*LL + col + 1];
                #pragma unroll
                for (int half = 0; half < 2; half++) {
                    int rr = row + half*8;
                    float v0 = acc[tm][tn][2*half]   * 0.125f - 0.01f * (float)((q0 + rr) - col);
                    float v1 = acc[tm][tn][2*half+1] * 0.125f - 0.01f * (float)((q0 + rr) - (col+1));
                    if (m0 == 0) v0 = -INFINITY;
                    if (m1 == 0) v1 = -INFINITY;
                    S[rr*SSTR + col]     = v0;
                    S[rr*SSTR + col + 1] = v1;
                }
            }
        }
        __syncthreads();
    }

    // ---- softmax (4 rows per warp) + P writeout ----
    {
        size_t gbase0 = ((size_t)(b*HH + h) * LL + q0) * LL;
        #pragma unroll
        for (int j = 0; j < 4; j++) {
            int r = wid*4 + j;
            float4 e[4];
            #pragma unroll
            for (int i = 0; i < 4; i++) e[i] = *(float4*)&S[r*SSTR + i*128 + lane*4];
            float mx = -1e30f;
            #pragma unroll
            for (int i = 0; i < 4; i++)
                mx = fmaxf(mx, fmaxf(fmaxf(e[i].x, e[i].y), fmaxf(e[i].z, e[i].w)));
            #pragma unroll
            for (int o = 16; o > 0; o >>= 1) mx = fmaxf(mx, __shfl_xor_sync(0xFFFFFFFFu, mx, o));
            float sum = 0.0f;
            #pragma unroll
            for (int i = 0; i < 4; i++) {
                e[i].x = __expf(e[i].x - mx); e[i].y = __expf(e[i].y - mx);
                e[i].z = __expf(e[i].z - mx); e[i].w = __expf(e[i].w - mx);
                sum += e[i].x + e[i].y + e[i].z + e[i].w;
            }
            #pragma unroll
            for (int o = 16; o > 0; o >>= 1) sum += __shfl_xor_sync(0xFFFFFFFFu, sum, o);
            float inv = 1.0f / sum;
            float* gp = attn_out + gbase0 + (size_t)r * LL;
            #pragma unroll
            for (int i = 0; i < 4; i++) {
                e[i].x *= inv; e[i].y *= inv; e[i].z *= inv; e[i].w *= inv;
                *(float4*)&S[r*SSTR + i*128 + lane*4] = e[i];
                *(float4*)(gp + i*128 + lane*4) = e[i];
            }
        }
    }
    __syncthreads();

    // ---- PV: 4 col-groups (16) x 2 k-halves; oa[2][2][4] per warp ----
    int wn4 = wid & 3, wk2 = wid >> 2;
    float oa[2][2][4];
    #pragma unroll
    for (int i = 0; i < 2; i++)
        #pragma unroll
        for (int j = 0; j < 2; j++)
            #pragma unroll
            for (int q = 0; q < 4; q++) oa[i][j][q] = 0.0f;

    uint32_t poff = (uint32_t)((lane & 15) * 144 + 16 * (lane >> 4));
    uint32_t voff = (uint32_t)((lane & 15) * 144 + wn4*32 + 16 * (lane >> 4));

    for (int kc = 0; kc < 8; kc++) {
        // convert P chunk (32 rows x 64 cols fp32 -> fp16) into Q area
        {
            int r = tid >> 3, c0 = (tid & 7) * 8;
            const float* sp = &S[r*SSTR + kc*64 + c0];
            float v[8];
            *(float4*)&v[0] = *(const float4*)sp;
            *(float4*)&v[4] = *(const float4*)(sp + 4);
            uint32_t hw[4];
            #pragma unroll
            for (int q = 0; q < 4; q++)
                hw[q] = packh(__float2half_rn(v[2*q]), __float2half_rn(v[2*q+1]));
            *(uint4*)(sm + OFF_Q + r*144 + c0*2) = *(uint4*)hw;
        }
        // load V chunk (64 rows x 64 fp16) into K area
        {
            int r = tid >> 2, c = tid & 3;
            size_t g = ((size_t)(b*LL + kc*64 + r)) * NQKV + 1536 + h*DH;
            const uint4* gv = (const uint4*)(QKV + g);
            *(uint4*)(sm + OFF_K + r*144 + c*16)     = gv[c];
            *(uint4*)(sm + OFF_K + r*144 + (c+4)*16) = gv[c+4];
        }
        __syncthreads();
        #pragma unroll
        for (int kj = 0; kj < 2; kj++) {
            int ki = wk2*2 + kj;
            uint32_t p[2][4], v[4];
            ldsm4(p[0], su + OFF_Q + poff + ki*32);
            ldsm4(p[1], su + OFF_Q + poff + 2304 + ki*32);
            ldsm4t(v, su + OFF_K + voff + ki*2304);
            #pragma unroll
            for (int tm = 0; tm < 2; tm++) {
                mma_f16(oa[tm][0], p[tm], &v[0]);
                mma_f16(oa[tm][1], p[tm], &v[2]);
            }
        }
        __syncthreads();
    }

    // cross-k reduction: wk2==0 stages in S, wk2==1 adds + writes
    if (wk2 == 0) {
        #pragma unroll
        for (int tm = 0; tm < 2; tm++)
            #pragma unroll
            for (int tn = 0; tn < 2; tn++)
                #pragma unroll
                for (int half = 0; half < 2; half++) {
                    int row = tm*16 + (lane >> 2) + half*8;
                    int col = wn4*16 + tn*8 + (lane & 3)*2;
                    S[row*64 + col]     = oa[tm][tn][2*half];
                    S[row*64 + col + 1] = oa[tm][tn][2*half+1];
                }
    }
    __syncthreads();
    if (wk2 == 1) {
        #pragma unroll
        for (int tm = 0; tm < 2; tm++)
            #pragma unroll
            for (int tn = 0; tn < 2; tn++)
                #pragma unroll
                for (int half = 0; half < 2; half++) {
                    int row = tm*16 + (lane >> 2) + half*8;
                    int col = wn4*16 + tn*8 + (lane & 3)*2;
                    float v0 = oa[tm][tn][2*half]   + S[row*64 + col];
                    float v1 = oa[tm][tn][2*half+1] + S[row*64 + col + 1];
                    size_t g = ((size_t)(b*LL + q0 + row)) * DD + h*DH + col;
                    *(uint32_t*)(ao + g) = packh(__float2half(v0), __float2half(v1));
                }
    }
}

// ---------------- classifier head ----------------
__global__ void logits_kernel(const float* __restrict__ h, const float* __restrict__ Wc,
                              const float* __restrict__ bc, float* __restrict__ out) {
    __shared__ float red[256];
    int b = blockIdx.x;
    int t = threadIdx.x;
    float s = 0.0f;
    for (int d = t; d < DD; d += 256) s += h[(size_t)b * LL * DD + d] * Wc[d * NC];
    red[t] = s; __syncthreads();
    for (int o = 128; o > 0; o >>= 1) { if (t < o) red[t] += red[t + o]; __syncthreads(); }
    if (t == 0) out[b * NC] = red[0] + bc[0];
}

// ---------------- launcher ----------------
extern "C" void kernel_launch(void* const* d_in, const int* in_sizes, int n_in,
                              void* d_out, int out_size) {
    const int*   x    = (const int*)  d_in[0];
    const int*   mask = (const int*)  d_in[1];
    const float* emb  = (const float*)d_in[2];
    const float* Wq   = (const float*)d_in[3];
    const float* bq   = (const float*)d_in[4];
    const float* Wk   = (const float*)d_in[5];
    const float* bk   = (const float*)d_in[6];
    const float* Wv   = (const float*)d_in[7];
    const float* bv   = (const float*)d_in[8];
    const float* Wo   = (const float*)d_in[9];
    const float* bo   = (const float*)d_in[10];
    const float* W1   = (const float*)d_in[11];
    const float* b1   = (const float*)d_in[12];
    const float* W2   = (const float*)d_in[13];
    const float* b2   = (const float*)d_in[14];
    const float* g1   = (const float*)d_in[15];
    const float* be1  = (const float*)d_in[16];
    const float* g2   = (const float*)d_in[17];
    const float* be2  = (const float*)d_in[18];
    const float* Wc   = (const float*)d_in[19];
    const float* bc   = (const float*)d_in[20];

    float* out = (float*)d_out;
    float* logits = out;
    float* attn_base = out + (size_t)BB * NC;

    static bool attr_set = false;
    if (!attr_set) {
        cudaFuncSetAttribute(gemm_mma, cudaFuncAttributeMaxDynamicSharedMemorySize, GEMM_SMEM);
        cudaFuncSetAttribute(attn_tc, cudaFuncAttributeMaxDynamicSharedMemorySize, ATTN_SMEM);
        attr_set = true;
    }

    float *p_h;
    fp16 *p_xn, *p_qkv, *p_ao, *p_ff, *p_wqkv, *p_wo, *p_w1, *p_w2;
    cudaGetSymbolAddress((void**)&p_h, g_h);
    cudaGetSymbolAddress((void**)&p_xn, g_xn);
    cudaGetSymbolAddress((void**)&p_qkv, g_qkv);
    cudaGetSymbolAddress((void**)&p_ao, g_ao);
    cudaGetSymbolAddress((void**)&p_ff, g_ff);
    cudaGetSymbolAddress((void**)&p_wqkv, g_wqkv);
    cudaGetSymbolAddress((void**)&p_wo, g_wo);
    cudaGetSymbolAddress((void**)&p_w1, g_w1);
    cudaGetSymbolAddress((void**)&p_w2, g_w2);

    dim3 tb(32, 8);
    size_t olsQKV = (size_t)NQKV * DD;

    dim3 gD(DD/64, MM/128);
    dim3 gQKV(NQKV/64, MM/128);
    dim3 gF(FF/64, MM/128);
    dim3 gAttn(LL/32, HH, BB);

    tsplit_qkv<<<dim3(DD/32, DD/32, NL*3), tb>>>(Wq, Wk, Wv, p_wqkv);
    embed_kernel<<<MM, 256>>>(x, emb, p_h);

    for (int l = 0; l < NL; l++) {
        size_t wD = (size_t)l * DD * DD;
        size_t wF = (size_t)l * DD * FF;
        size_t wQ = (size_t)l * olsQKV;
        ln_kernel<<<MM, 256>>>(p_h, g1 + l*DD, be1 + l*DD, p_xn);
        gemm_mma<<<gQKV, 256, GEMM_SMEM>>>(p_xn, p_wqkv + wQ,
                                           bq + l*DD, bk + l*DD, bv + l*DD,
                                           nullptr, p_qkv, NQKV, DD, 3);
        if (l == 0) {
            tsplit_kernel<<<dim3(DD/32, DD/32, NL), tb>>>(Wo, p_wo, DD, DD, 0, (size_t)DD*DD);
            tsplit_kernel<<<dim3(FF/32, DD/32, NL), tb>>>(W1, p_w1, DD, FF, 0, (size_t)DD*FF);
            tsplit_kernel<<<dim3(DD/32, FF/32, NL), tb>>>(W2, p_w2, FF, DD, 0, (size_t)FF*DD);
        }
        attn_tc<<<gAttn, 256, ATTN_SMEM>>>(p_qkv, mask,
                                           attn_base + (size_t)l * BB * HH * LL * LL, p_ao);
        gemm_mma<<<gD, 256, GEMM_SMEM>>>(p_ao, p_wo + wD,
                                         bo + l*DD, nullptr, nullptr,
                                         p_h, nullptr, DD, DD, 2);
        ln_kernel<<<MM, 256>>>(p_h, g2 + l*DD, be2 + l*DD, p_xn);
        gemm_mma<<<gF, 256, GEMM_SMEM>>>(p_xn, p_w1 + wF,
                                         b1 + l*FF, nullptr, nullptr,
                                         nullptr, p_ff, FF, DD, 1);
        gemm_mma<<<gD, 256, GEMM_SMEM>>>(p_ff, p_w2 + wF,
                                         b2 + l*DD, nullptr, nullptr,
                                         p_h, nullptr, DD, FF, 2);
    }

    logits_kernel<<<BB, 256>>>(p_h, Wc, bc, logits);
}

// round 15
// speedup vs baseline: 2.2454x; 1.0031x over previous
#include <cuda_runtime.h>
#include <cuda_fp16.h>
#include <math.h>
#include <stdint.h>

#define BB 8
#define LL 512
#define DD 768
#define HH 12
#define DH 64
#define FF 3072
#define NL 6
#define NC 1
#define MM (BB*LL)   // 4096
#define NQKV 2304
#define NPERS 456    // 152 SMs x 3 CTAs

typedef __half fp16;

// ---------------- scratch ----------------
__device__ float g_h[MM*DD];
__device__ fp16 g_xn[MM*DD];
__device__ fp16 g_qkv[MM*NQKV];
__device__ fp16 g_ao[MM*DD];
__device__ fp16 g_ff[MM*FF];
__device__ fp16 g_wqkv[NL*NQKV*DD];
__device__ fp16 g_wo[NL*DD*DD];
__device__ fp16 g_w1[NL*DD*FF];
__device__ fp16 g_w2[NL*FF*DD];

// ---------------- PTX helpers ----------------
__device__ __forceinline__ uint32_t smem_to_u32(const void* p) {
    uint32_t a;
    asm("{ .reg .u64 t; cvta.to.shared.u64 t, %1; cvt.u32.u64 %0, t; }" : "=r"(a) : "l"(p));
    return a;
}
__device__ __forceinline__ void cp_async16(uint32_t saddr, const void* gaddr) {
    asm volatile("cp.async.cg.shared.global [%0], [%1], 16;" :: "r"(saddr), "l"(gaddr) : "memory");
}
#define CP_COMMIT() asm volatile("cp.async.commit_group;" ::: "memory")
#define CP_WAIT1()  asm volatile("cp.async.wait_group 1;"  ::: "memory")
__device__ __forceinline__ void ldsm4(uint32_t* r, uint32_t a) {
    asm volatile("ldmatrix.sync.aligned.m8n8.x4.shared.b16 {%0,%1,%2,%3}, [%4];"
        : "=r"(r[0]), "=r"(r[1]), "=r"(r[2]), "=r"(r[3]) : "r"(a));
}
__device__ __forceinline__ void ldsm4t(uint32_t* r, uint32_t a) {
    asm volatile("ldmatrix.sync.aligned.m8n8.x4.trans.shared.b16 {%0,%1,%2,%3}, [%4];"
        : "=r"(r[0]), "=r"(r[1]), "=r"(r[2]), "=r"(r[3]) : "r"(a));
}
__device__ __forceinline__ void mma_f16(float* c, const uint32_t* a, const uint32_t* b) {
    asm volatile("mma.sync.aligned.m16n8k16.row.col.f32.f16.f16.f32 "
        "{%0,%1,%2,%3}, {%4,%5,%6,%7}, {%8,%9}, {%0,%1,%2,%3};"
        : "+f"(c[0]), "+f"(c[1]), "+f"(c[2]), "+f"(c[3])
        : "r"(a[0]), "r"(a[1]), "r"(a[2]), "r"(a[3]), "r"(b[0]), "r"(b[1]));
}
__device__ __forceinline__ uint32_t packh(fp16 a, fp16 b) {
    __half2 t; t.x = a; t.y = b; return *(uint32_t*)&t;
}

// ---------------- weight transpose -> fp16 (generic) ----------------
__global__ void tsplit_kernel(const float* __restrict__ W, fp16* __restrict__ T,
                              int K, int N, int roff, size_t out_ls) {
    __shared__ float s[32][33];
    int l = blockIdx.z;
    const float* Wl = W + (size_t)l * K * N;
    fp16* Tl = T + (size_t)l * out_ls;
    int n0 = blockIdx.x * 32, k0 = blockIdx.y * 32;
    int tx = threadIdx.x, ty = threadIdx.y;
    #pragma unroll
    for (int j = 0; j < 4; j++)
        s[ty + 8*j][tx] = Wl[(size_t)(k0 + ty + 8*j) * N + n0 + tx];
    __syncthreads();
    #pragma unroll
    for (int j = 0; j < 4; j++) {
        int row = ty + 8*j;
        Tl[(size_t)(roff + n0 + row) * K + k0 + tx] = __float2half_rn(s[tx][row]);
    }
}

// merged QKV transpose
__global__ void tsplit_qkv(const float* __restrict__ Wq, const float* __restrict__ Wk,
                           const float* __restrict__ Wv, fp16* __restrict__ T) {
    __shared__ float s[32][33];
    int z = blockIdx.z;
    int l = z / 3, which = z % 3;
    const float* W = (which == 0) ? Wq : (which == 1) ? Wk : Wv;
    const float* Wl = W + (size_t)l * DD * DD;
    fp16* Tl = T + (size_t)l * NQKV * DD;
    int roff = which * DD;
    int n0 = blockIdx.x * 32, k0 = blockIdx.y * 32;
    int tx = threadIdx.x, ty = threadIdx.y;
    #pragma unroll
    for (int j = 0; j < 4; j++)
        s[ty + 8*j][tx] = Wl[(size_t)(k0 + ty + 8*j) * DD + n0 + tx];
    __syncthreads();
    #pragma unroll
    for (int j = 0; j < 4; j++) {
        int row = ty + 8*j;
        Tl[(size_t)(roff + n0 + row) * DD + k0 + tx] = __float2half_rn(s[tx][row]);
    }
}

// ---------------- embedding + positional encoding ----------------
__global__ void embed_kernel(const int* __restrict__ x, const float* __restrict__ emb,
                             float* __restrict__ out) {
    int r = blockIdx.x;
    int b = r / LL;
    int tok = x[r];
    const float* erow = emb + (size_t)tok * DD;
    float* orow = out + (size_t)r * DD;
    const float neg_log = -logf(10000.0f) / (float)DD;
    for (int j = 0; j < 3; j++) {
        int d = threadIdx.x + j * 256;
        int i2 = (d >> 1) << 1;
        float div = expf((float)i2 * neg_log);
        float ang = (float)b * div;
        float pe = (d & 1) ? cosf(ang) : sinf(ang);
        orow[d] = erow[d] + pe;
    }
}

// ---------------- layernorm: warp-per-row -> fp16 ----------------
__global__ void ln_kernel(const float* __restrict__ in, const float* __restrict__ g,
                          const float* __restrict__ be, fp16* __restrict__ o) {
    int warp = threadIdx.x >> 5, lane = threadIdx.x & 31;
    int r = blockIdx.x * 8 + warp;
    const float* xr = in + (size_t)r * DD;
    float4 v[6];
    float s = 0.0f;
    #pragma unroll
    for (int i = 0; i < 6; i++) {
        v[i] = *(const float4*)(xr + lane*4 + i*128);
        s += v[i].x + v[i].y + v[i].z + v[i].w;
    }
    #pragma unroll
    for (int oo = 16; oo > 0; oo >>= 1) s += __shfl_xor_sync(0xFFFFFFFFu, s, oo);
    float mean = s * (1.0f / (float)DD);
    float vs = 0.0f;
    #pragma unroll
    for (int i = 0; i < 6; i++) {
        v[i].x -= mean; v[i].y -= mean; v[i].z -= mean; v[i].w -= mean;
        vs += v[i].x*v[i].x + v[i].y*v[i].y + v[i].z*v[i].z + v[i].w*v[i].w;
    }
    #pragma unroll
    for (int oo = 16; oo > 0; oo >>= 1) vs += __shfl_xor_sync(0xFFFFFFFFu, vs, oo);
    float rs = rsqrtf(vs * (1.0f / (float)DD) + 1e-5f);
    fp16* orow = o + (size_t)r * DD;
    #pragma unroll
    for (int i = 0; i < 6; i++) {
        int c = lane*4 + i*128;
        float4 gg = *(const float4*)(g + c);
        float4 bb = *(const float4*)(be + c);
        uint2 pk;
        pk.x = packh(__float2half(v[i].x * rs * gg.x + bb.x),
                     __float2half(v[i].y * rs * gg.y + bb.y));
        pk.y = packh(__float2half(v[i].z * rs * gg.z + bb.z),
                     __float2half(v[i].w * rs * gg.w + bb.w));
        *(uint2*)(orow + c) = pk;
    }
}

// ---------------- persistent HMMA GEMM: 128x64 tile, K=64/stage, 2-stage, 3 CTAs/SM ----------------
#define A_OFF 0
#define B_OFF 18432
#define STG_BYTES 27648
#define GEMM_SMEM (2*STG_BYTES)

__global__ __launch_bounds__(256, 3) void gemm_mma(
    const fp16* __restrict__ A, const fp16* __restrict__ B,
    const float* __restrict__ bias0, const float* __restrict__ bias1,
    const float* __restrict__ bias2,
    float* __restrict__ C, fp16* __restrict__ O,
    int Ntot, int Ktot, int Nn, int ntiles, int op)
{
    extern __shared__ char dsmem[];
    uint32_t smem_u = smem_to_u32(dsmem);
    int tid = threadIdx.x;
    int lane = tid & 31;
    int wid = tid >> 5;
    int wm = wid & 3;
    int wn = wid >> 2;

    uint32_t a_off = (uint32_t)((wm*32 + (lane & 15)) * 144 + 16 * (lane >> 4));
    uint32_t b_off = (uint32_t)((wn*32 + 8*((lane >> 4) & 1) + (lane & 7)) * 144
                                + 16 * ((lane >> 3) & 1));

    int iters = Ktot >> 6;

    #define LOAD_STAGE(itv, buf, bmv, bnv) do { \
        int k0 = (itv) << 6; \
        uint32_t sb = smem_u + (buf) * STG_BYTES; \
        _Pragma("unroll") \
        for (int j = 0; j < 4; j++) { \
            int ci = tid + j * 256; \
            int row = ci >> 3, col = ci & 7; \
            cp_async16(sb + A_OFF + row*144 + col*16, A + (size_t)((bmv) + row) * Ktot + k0 + col*8); \
        } \
        _Pragma("unroll") \
        for (int j = 0; j < 2; j++) { \
            int ci = tid + j * 256; \
            int row = ci >> 3, col = ci & 7; \
            cp_async16(sb + B_OFF + row*144 + col*16, B + (size_t)((bnv) + row) * Ktot + k0 + col*8); \
        } \
    } while (0)

    // prologue for first tile
    {
        int t0 = blockIdx.x;
        int bm0 = (t0 / Nn) * 128, bn0 = (t0 % Nn) * 64;
        LOAD_STAGE(0, 0, bm0, bn0); CP_COMMIT();
        LOAD_STAGE(1, 1, bm0, bn0); CP_COMMIT();
    }

    for (int tile = blockIdx.x; tile < ntiles; tile += gridDim.x) {
        int bm = (tile / Nn) * 128, bn = (tile % Nn) * 64;
        int ntile = tile + gridDim.x;
        int hasnext = (ntile < ntiles);
        int bmn = 0, bnn = 0;
        if (hasnext) { bmn = (ntile / Nn) * 128; bnn = (ntile % Nn) * 64; }

        float acc[2][4][4];
        #pragma unroll
        for (int i = 0; i < 2; i++)
            #pragma unroll
            for (int j = 0; j < 4; j++)
                #pragma unroll
                for (int q = 0; q < 4; q++) acc[i][j][q] = 0.0f;

        for (int it = 0; it < iters; it++) {
            CP_WAIT1();
            __syncthreads();
            int buf = it & 1;
            uint32_t sA = smem_u + buf * STG_BYTES + A_OFF;
            uint32_t sB = smem_u + buf * STG_BYTES + B_OFF;
            #pragma unroll
            for (int ks = 0; ks < 4; ks++) {
                uint32_t a[2][4], b[2][4];
                #pragma unroll
                for (int tm = 0; tm < 2; tm++)
                    ldsm4(a[tm], sA + a_off + tm*2304 + ks*32);
                #pragma unroll
                for (int p = 0; p < 2; p++)
                    ldsm4(b[p], sB + b_off + p*2304 + ks*32);
                #pragma unroll
                for (int tm = 0; tm < 2; tm++)
                    #pragma unroll
                    for (int p = 0; p < 2; p++) {
                        mma_f16(acc[tm][2*p],   a[tm], &b[p][0]);
                        mma_f16(acc[tm][2*p+1], a[tm], &b[p][2]);
                    }
            }
            __syncthreads();
            int nit = it + 2;
            if (nit < iters)       LOAD_STAGE(nit, buf, bm, bn);
            else if (hasnext)      LOAD_STAGE(nit - iters, buf, bmn, bnn);
            CP_COMMIT();
        }

        // epilogue (no smem use)
        const float* beff = bias0;
        int boff = 0;
        if (bias1 != nullptr) {
            if (bn >= 1536)      { beff = bias2; boff = 1536; }
            else if (bn >= 768)  { beff = bias1; boff = 768;  }
        }
        int m_base = bm + wm*32 + (lane >> 2);
        int n_base = bn + wn*32 + (lane & 3)*2;
        #pragma unroll
        for (int tm = 0; tm < 2; tm++) {
            #pragma unroll
            for (int tn = 0; tn < 4; tn++) {
                #pragma unroll
                for (int half = 0; half < 2; half++) {
                    int m = m_base + tm*16 + half*8;
                    int n = n_base + tn*8;
                    float v0 = acc[tm][tn][2*half]     + beff[n - boff];
                    float v1 = acc[tm][tn][2*half + 1] + beff[n + 1 - boff];
                    size_t idx = (size_t)m * Ntot + n;
                    if (op == 1) {
                        float gv0 = 0.5f * v0 * (1.0f + erff(v0 * 0.70710678118654752f));
                        float gv1 = 0.5f * v1 * (1.0f + erff(v1 * 0.70710678118654752f));
                        *(uint32_t*)(O + idx) = packh(__float2half(gv0), __float2half(gv1));
                    } else if (op == 2) {
                        C[idx]     += v0;
                        C[idx + 1] += v1;
                    } else {
                        *(uint32_t*)(O + idx) = packh(__float2half(v0), __float2half(v1));
                    }
                }
            }
        }
    }
    #undef LOAD_STAGE
}

// ---------------- tensor-core fused attention: 32-row Q tiles, 2 CTAs/SM ----------------
#define SSTR 520
#define OFF_Q  (32*SSTR*4)
#define OFF_K  (OFF_Q + 32*144)
#define ATTN_SMEM (OFF_K + 128*144)

__global__ __launch_bounds__(256, 2) void attn_tc(
    const fp16* __restrict__ QKV, const int* __restrict__ mask,
    float* __restrict__ attn_out, fp16* __restrict__ ao)
{
    extern __shared__ char sm[];
    float* S = (float*)sm;
    uint32_t su = smem_to_u32(sm);
    int tid = threadIdx.x, lane = tid & 31, wid = tid >> 5;
    int q0 = blockIdx.x * 32;
    int h = blockIdx.y, b = blockIdx.z;

    {
        int r = tid >> 3, c = tid & 7;
        size_t g = ((size_t)(b*LL + q0 + r)) * NQKV + h*DH;
        *(uint4*)(sm + OFF_Q + r*144 + c*16) = ((const uint4*)(QKV + g))[c];
    }

    for (int kc = 0; kc < 4; kc++) {
        {
            int r = tid >> 1, c0 = (tid & 1) * 4;
            size_t g = ((size_t)(b*LL + kc*128 + r)) * NQKV + 768 + h*DH;
            const uint4* gk = (const uint4*)(QKV + g);
            #pragma unroll
            for (int c = 0; c < 4; c++)
                *(uint4*)(sm + OFF_K + r*144 + (c0+c)*16) = gk[c0+c];
        }
        __syncthreads();
        float acc[2][2][4];
        #pragma unroll
        for (int i = 0; i < 2; i++)
            #pragma unroll
            for (int j = 0; j < 2; j++)
                #pragma unroll
                for (int q = 0; q < 4; q++) acc[i][j][q] = 0.0f;
        uint32_t aoff = (uint32_t)((lane & 15) * 144 + 16 * (lane >> 4));
        uint32_t boff = (uint32_t)((wid*16 + 8*((lane >> 4) & 1) + (lane & 7)) * 144
                                   + 16 * ((lane >> 3) & 1));
        #pragma unroll
        for (int ki = 0; ki < 4; ki++) {
            uint32_t a[2][4], bmat[4];
            ldsm4(a[0], su + OFF_Q + aoff + ki*32);
            ldsm4(a[1], su + OFF_Q + aoff + 2304 + ki*32);
            ldsm4(bmat, su + OFF_K + boff + ki*32);
            #pragma unroll
            for (int tm = 0; tm < 2; tm++) {
                mma_f16(acc[tm][0], a[tm], &bmat[0]);
                mma_f16(acc[tm][1], a[tm], &bmat[2]);
            }
        }
        #pragma unroll
        for (int tm = 0; tm < 2; tm++) {
            #pragma unroll
            for (int tn = 0; tn < 2; tn++) {
                int row = tm*16 + (lane >> 2);
                int col = kc*128 + wid*16 + tn*8 + (lane & 3)*2;
                int m0 = mask[b*LL + col], m1 = mask[b*LL + col + 1];
                #pragma unroll
                for (int half = 0; half < 2; half++) {
                    int rr = row + half*8;
                    float v0 = acc[tm][tn][2*half]   * 0.125f - 0.01f * (float)((q0 + rr) - col);
                    float v1 = acc[tm][tn][2*half+1] * 0.125f - 0.01f * (float)((q0 + rr) - (col+1));
                    if (m0 == 0) v0 = -INFINITY;
                    if (m1 == 0) v1 = -INFINITY;
                    S[rr*SSTR + col]     = v0;
                    S[rr*SSTR + col + 1] = v1;
                }
            }
        }
        __syncthreads();
    }

    {
        size_t gbase0 = ((size_t)(b*HH + h) * LL + q0) * LL;
        #pragma unroll
        for (int j = 0; j < 4; j++) {
            int r = wid*4 + j;
            float4 e[4];
            #pragma unroll
            for (int i = 0; i < 4; i++) e[i] = *(float4*)&S[r*SSTR + i*128 + lane*4];
            float mx = -1e30f;
            #pragma unroll
            for (int i = 0; i < 4; i++)
                mx = fmaxf(mx, fmaxf(fmaxf(e[i].x, e[i].y), fmaxf(e[i].z, e[i].w)));
            #pragma unroll
            for (int o = 16; o > 0; o >>= 1) mx = fmaxf(mx, __shfl_xor_sync(0xFFFFFFFFu, mx, o));
            float sum = 0.0f;
            #pragma unroll
            for (int i = 0; i < 4; i++) {
                e[i].x = __expf(e[i].x - mx); e[i].y = __expf(e[i].y - mx);
                e[i].z = __expf(e[i].z - mx); e[i].w = __expf(e[i].w - mx);
                sum += e[i].x + e[i].y + e[i].z + e[i].w;
            }
            #pragma unroll
            for (int o = 16; o > 0; o >>= 1) sum += __shfl_xor_sync(0xFFFFFFFFu, sum, o);
            float inv = 1.0f / sum;
            float* gp = attn_out + gbase0 + (size_t)r * LL;
            #pragma unroll
            for (int i = 0; i < 4; i++) {
                e[i].x *= inv; e[i].y *= inv; e[i].z *= inv; e[i].w *= inv;
                *(float4*)&S[r*SSTR + i*128 + lane*4] = e[i];
                *(float4*)(gp + i*128 + lane*4) = e[i];
            }
        }
    }
    __syncthreads();

    int wn4 = wid & 3, wk2 = wid >> 2;
    float oa[2][2][4];
    #pragma unroll
    for (int i = 0; i < 2; i++)
        #pragma unroll
        for (int j = 0; j < 2; j++)
            #pragma unroll
            for (int q = 0; q < 4; q++) oa[i][j][q] = 0.0f;

    uint32_t poff = (uint32_t)((lane & 15) * 144 + 16 * (lane >> 4));
    uint32_t voff = (uint32_t)((lane & 15) * 144 + wn4*32 + 16 * (lane >> 4));

    for (int kc = 0; kc < 8; kc++) {
        {
            int r = tid >> 3, c0 = (tid & 7) * 8;
            const float* sp = &S[r*SSTR + kc*64 + c0];
            float v[8];
            *(float4*)&v[0] = *(const float4*)sp;
            *(float4*)&v[4] = *(const float4*)(sp + 4);
            uint32_t hw[4];
            #pragma unroll
            for (int q = 0; q < 4; q++)
                hw[q] = packh(__float2half_rn(v[2*q]), __float2half_rn(v[2*q+1]));
            *(uint4*)(sm + OFF_Q + r*144 + c0*2) = *(uint4*)hw;
        }
        {
            int r = tid >> 2, c = tid & 3;
            size_t g = ((size_t)(b*LL + kc*64 + r)) * NQKV + 1536 + h*DH;
            const uint4* gv = (const uint4*)(QKV + g);
            *(uint4*)(sm + OFF_K + r*144 + c*16)     = gv[c];
            *(uint4*)(sm + OFF_K + r*144 + (c+4)*16) = gv[c+4];
        }
        __syncthreads();
        #pragma unroll
        for (int kj = 0; kj < 2; kj++) {
            int ki = wk2*2 + kj;
            uint32_t p[2][4], v[4];
            ldsm4(p[0], su + OFF_Q + poff + ki*32);
            ldsm4(p[1], su + OFF_Q + poff + 2304 + ki*32);
            ldsm4t(v, su + OFF_K + voff + ki*2304);
            #pragma unroll
            for (int tm = 0; tm < 2; tm++) {
                mma_f16(oa[tm][0], p[tm], &v[0]);
                mma_f16(oa[tm][1], p[tm], &v[2]);
            }
        }
        __syncthreads();
    }

    if (wk2 == 0) {
        #pragma unroll
        for (int tm = 0; tm < 2; tm++)
            #pragma unroll
            for (int tn = 0; tn < 2; tn++)
                #pragma unroll
                for (int half = 0; half < 2; half++) {
                    int row = tm*16 + (lane >> 2) + half*8;
                    int col = wn4*16 + tn*8 + (lane & 3)*2;
                    S[row*64 + col]     = oa[tm][tn][2*half];
                    S[row*64 + col + 1] = oa[tm][tn][2*half+1];
                }
    }
    __syncthreads();
    if (wk2 == 1) {
        #pragma unroll
        for (int tm = 0; tm < 2; tm++)
            #pragma unroll
            for (int tn = 0; tn < 2; tn++)
                #pragma unroll
                for (int half = 0; half < 2; half++) {
                    int row = tm*16 + (lane >> 2) + half*8;
                    int col = wn4*16 + tn*8 + (lane & 3)*2;
                    float v0 = oa[tm][tn][2*half]   + S[row*64 + col];
                    float v1 = oa[tm][tn][2*half+1] + S[row*64 + col + 1];
                    size_t g = ((size_t)(b*LL + q0 + row)) * DD + h*DH + col;
                    *(uint32_t*)(ao + g) = packh(__float2half(v0), __float2half(v1));
                }
    }
}

// ---------------- classifier head ----------------
__global__ void logits_kernel(const float* __restrict__ h, const float* __restrict__ Wc,
                              const float* __restrict__ bc, float* __restrict__ out) {
    __shared__ float red[256];
    int b = blockIdx.x;
    int t = threadIdx.x;
    float s = 0.0f;
    for (int d = t; d < DD; d += 256) s += h[(size_t)b * LL * DD + d] * Wc[d * NC];
    red[t] = s; __syncthreads();
    for (int o = 128; o > 0; o >>= 1) { if (t < o) red[t] += red[t + o]; __syncthreads(); }
    if (t == 0) out[b * NC] = red[0] + bc[0];
}

// ---------------- launcher ----------------
extern "C" void kernel_launch(void* const* d_in, const int* in_sizes, int n_in,
                              void* d_out, int out_size) {
    const int*   x    = (const int*)  d_in[0];
    const int*   mask = (const int*)  d_in[1];
    const float* emb  = (const float*)d_in[2];
    const float* Wq   = (const float*)d_in[3];
    const float* bq   = (const float*)d_in[4];
    const float* Wk   = (const float*)d_in[5];
    const float* bk   = (const float*)d_in[6];
    const float* Wv   = (const float*)d_in[7];
    const float* bv   = (const float*)d_in[8];
    const float* Wo   = (const float*)d_in[9];
    const float* bo   = (const float*)d_in[10];
    const float* W1   = (const float*)d_in[11];
    const float* b1   = (const float*)d_in[12];
    const float* W2   = (const float*)d_in[13];
    const float* b2   = (const float*)d_in[14];
    const float* g1   = (const float*)d_in[15];
    const float* be1  = (const float*)d_in[16];
    const float* g2   = (const float*)d_in[17];
    const float* be2  = (const float*)d_in[18];
    const float* Wc   = (const float*)d_in[19];
    const float* bc   = (const float*)d_in[20];

    float* out = (float*)d_out;
    float* logits = out;
    float* attn_base = out + (size_t)BB * NC;

    static bool attr_set = false;
    if (!attr_set) {
        cudaFuncSetAttribute(gemm_mma, cudaFuncAttributeMaxDynamicSharedMemorySize, GEMM_SMEM);
        cudaFuncSetAttribute(attn_tc, cudaFuncAttributeMaxDynamicSharedMemorySize, ATTN_SMEM);
        attr_set = true;
    }

    float *p_h;
    fp16 *p_xn, *p_qkv, *p_ao, *p_ff, *p_wqkv, *p_wo, *p_w1, *p_w2;
    cudaGetSymbolAddress((void**)&p_h, g_h);
    cudaGetSymbolAddress((void**)&p_xn, g_xn);
    cudaGetSymbolAddress((void**)&p_qkv, g_qkv);
    cudaGetSymbolAddress((void**)&p_ao, g_ao);
    cudaGetSymbolAddress((void**)&p_ff, g_ff);
    cudaGetSymbolAddress((void**)&p_wqkv, g_wqkv);
    cudaGetSymbolAddress((void**)&p_wo, g_wo);
    cudaGetSymbolAddress((void**)&p_w1, g_w1);
    cudaGetSymbolAddress((void**)&p_w2, g_w2);

    dim3 tb(32, 8);
    size_t olsQKV = (size_t)NQKV * DD;

    // persistent grids
    int ntQKV = (NQKV/64) * (MM/128);   // 1152
    int ntD   = (DD/64)   * (MM/128);   // 384
    int ntF   = (FF/64)   * (MM/128);   // 1536
    int gQKVp = ntQKV < NPERS ? ntQKV : NPERS;
    int gDp   = ntD   < NPERS ? ntD   : NPERS;
    int gFp   = ntF   < NPERS ? ntF   : NPERS;
    dim3 gAttn(LL/32, HH, BB);

    tsplit_qkv<<<dim3(DD/32, DD/32, NL*3), tb>>>(Wq, Wk, Wv, p_wqkv);
    embed_kernel<<<MM, 256>>>(x, emb, p_h);

    for (int l = 0; l < NL; l++) {
        size_t wD = (size_t)l * DD * DD;
        size_t wF = (size_t)l * DD * FF;
        size_t wQ = (size_t)l * olsQKV;
        ln_kernel<<<MM/8, 256>>>(p_h, g1 + l*DD, be1 + l*DD, p_xn);
        gemm_mma<<<gQKVp, 256, GEMM_SMEM>>>(p_xn, p_wqkv + wQ,
                                            bq + l*DD, bk + l*DD, bv + l*DD,
                                            nullptr, p_qkv, NQKV, DD, NQKV/64, ntQKV, 3);
        if (l == 0) {
            tsplit_kernel<<<dim3(DD/32, DD/32, NL), tb>>>(Wo, p_wo, DD, DD, 0, (size_t)DD*DD);
            tsplit_kernel<<<dim3(FF/32, DD/32, NL), tb>>>(W1, p_w1, DD, FF, 0, (size_t)DD*FF);
            tsplit_kernel<<<dim3(DD/32, FF/32, NL), tb>>>(W2, p_w2, FF, DD, 0, (size_t)FF*DD);
        }
        attn_tc<<<gAttn, 256, ATTN_SMEM>>>(p_qkv, mask,
                                           attn_base + (size_t)l * BB * HH * LL * LL, p_ao);
        gemm_mma<<<gDp, 256, GEMM_SMEM>>>(p_ao, p_wo + wD,
                                          bo + l*DD, nullptr, nullptr,
                                          p_h, nullptr, DD, DD, DD/64, ntD, 2);
        ln_kernel<<<MM/8, 256>>>(p_h, g2 + l*DD, be2 + l*DD, p_xn);
        gemm_mma<<<gFp, 256, GEMM_SMEM>>>(p_xn, p_w1 + wF,
                                          b1 + l*FF, nullptr, nullptr,
                                          nullptr, p_ff, FF, DD, FF/64, ntF, 1);
        gemm_mma<<<gDp, 256, GEMM_SMEM>>>(p_ff, p_w2 + wF,
                                          b2 + l*DD, nullptr, nullptr,
                                          p_h, nullptr, DD, FF, DD/64, ntD, 2);
    }

    logits_kernel<<<BB, 256>>>(p_h, Wc, bc, logits);
}

// round 16
// speedup vs baseline: 2.3152x; 1.0311x over previous
#include <cuda_runtime.h>
#include <cuda_fp16.h>
#include <math.h>
#include <stdint.h>

#define BB 8
#define LL 512
#define DD 768
#define HH 12
#define DH 64
#define FF 3072
#define NL 6
#define NC 1
#define MM (BB*LL)   // 4096
#define NQKV 2304

typedef __half fp16;

// ---------------- scratch ----------------
__device__ float g_h[MM*DD];
__device__ fp16 g_xn[MM*DD];
__device__ fp16 g_qkv[MM*NQKV];
__device__ fp16 g_ao[MM*DD];
__device__ fp16 g_ff[MM*FF];
__device__ fp16 g_wqkv[NL*NQKV*DD];
__device__ fp16 g_wo[NL*DD*DD];
__device__ fp16 g_w1[NL*DD*FF];
__device__ fp16 g_w2[NL*FF*DD];

// ---------------- PTX helpers ----------------
__device__ __forceinline__ uint32_t smem_to_u32(const void* p) {
    uint32_t a;
    asm("{ .reg .u64 t; cvta.to.shared.u64 t, %1; cvt.u32.u64 %0, t; }" : "=r"(a) : "l"(p));
    return a;
}
__device__ __forceinline__ void cp_async16(uint32_t saddr, const void* gaddr) {
    asm volatile("cp.async.cg.shared.global [%0], [%1], 16;" :: "r"(saddr), "l"(gaddr) : "memory");
}
#define CP_COMMIT() asm volatile("cp.async.commit_group;" ::: "memory")
#define CP_WAIT1()  asm volatile("cp.async.wait_group 1;"  ::: "memory")
__device__ __forceinline__ void ldsm4(uint32_t* r, uint32_t a) {
    asm volatile("ldmatrix.sync.aligned.m8n8.x4.shared.b16 {%0,%1,%2,%3}, [%4];"
        : "=r"(r[0]), "=r"(r[1]), "=r"(r[2]), "=r"(r[3]) : "r"(a));
}
__device__ __forceinline__ void ldsm4t(uint32_t* r, uint32_t a) {
    asm volatile("ldmatrix.sync.aligned.m8n8.x4.trans.shared.b16 {%0,%1,%2,%3}, [%4];"
        : "=r"(r[0]), "=r"(r[1]), "=r"(r[2]), "=r"(r[3]) : "r"(a));
}
__device__ __forceinline__ void mma_f16(float* c, const uint32_t* a, const uint32_t* b) {
    asm volatile("mma.sync.aligned.m16n8k16.row.col.f32.f16.f16.f32 "
        "{%0,%1,%2,%3}, {%4,%5,%6,%7}, {%8,%9}, {%0,%1,%2,%3};"
        : "+f"(c[0]), "+f"(c[1]), "+f"(c[2]), "+f"(c[3])
        : "r"(a[0]), "r"(a[1]), "r"(a[2]), "r"(a[3]), "r"(b[0]), "r"(b[1]));
}
__device__ __forceinline__ uint32_t packh(fp16 a, fp16 b) {
    __half2 t; t.x = a; t.y = b; return *(uint32_t*)&t;
}

// ---------------- weight transpose -> fp16 (generic) ----------------
__global__ void tsplit_kernel(const float* __restrict__ W, fp16* __restrict__ T,
                              int K, int N, int roff, size_t out_ls) {
    __shared__ float s[32][33];
    int l = blockIdx.z;
    const float* Wl = W + (size_t)l * K * N;
    fp16* Tl = T + (size_t)l * out_ls;
    int n0 = blockIdx.x * 32, k0 = blockIdx.y * 32;
    int tx = threadIdx.x, ty = threadIdx.y;
    #pragma unroll
    for (int j = 0; j < 4; j++)
        s[ty + 8*j][tx] = Wl[(size_t)(k0 + ty + 8*j) * N + n0 + tx];
    __syncthreads();
    #pragma unroll
    for (int j = 0; j < 4; j++) {
        int row = ty + 8*j;
        Tl[(size_t)(roff + n0 + row) * K + k0 + tx] = __float2half_rn(s[tx][row]);
    }
}

// merged QKV transpose
__global__ void tsplit_qkv(const float* __restrict__ Wq, const float* __restrict__ Wk,
                           const float* __restrict__ Wv, fp16* __restrict__ T) {
    __shared__ float s[32][33];
    int z = blockIdx.z;
    int l = z / 3, which = z % 3;
    const float* W = (which == 0) ? Wq : (which == 1) ? Wk : Wv;
    const float* Wl = W + (size_t)l * DD * DD;
    fp16* Tl = T + (size_t)l * NQKV * DD;
    int roff = which * DD;
    int n0 = blockIdx.x * 32, k0 = blockIdx.y * 32;
    int tx = threadIdx.x, ty = threadIdx.y;
    #pragma unroll
    for (int j = 0; j < 4; j++)
        s[ty + 8*j][tx] = Wl[(size_t)(k0 + ty + 8*j) * DD + n0 + tx];
    __syncthreads();
    #pragma unroll
    for (int j = 0; j < 4; j++) {
        int row = ty + 8*j;
        Tl[(size_t)(roff + n0 + row) * DD + k0 + tx] = __float2half_rn(s[tx][row]);
    }
}

// ---------------- embedding + positional encoding ----------------
__global__ void embed_kernel(const int* __restrict__ x, const float* __restrict__ emb,
                             float* __restrict__ out) {
    int r = blockIdx.x;
    int b = r / LL;
    int tok = x[r];
    const float* erow = emb + (size_t)tok * DD;
    float* orow = out + (size_t)r * DD;
    const float neg_log = -logf(10000.0f) / (float)DD;
    for (int j = 0; j < 3; j++) {
        int d = threadIdx.x + j * 256;
        int i2 = (d >> 1) << 1;
        float div = expf((float)i2 * neg_log);
        float ang = (float)b * div;
        float pe = (d & 1) ? cosf(ang) : sinf(ang);
        orow[d] = erow[d] + pe;
    }
}

// ---------------- layernorm: warp-per-row -> fp16 ----------------
__global__ void ln_kernel(const float* __restrict__ in, const float* __restrict__ g,
                          const float* __restrict__ be, fp16* __restrict__ o) {
    int warp = threadIdx.x >> 5, lane = threadIdx.x & 31;
    int r = blockIdx.x * 8 + warp;
    const float* xr = in + (size_t)r * DD;
    float4 v[6];
    float s = 0.0f;
    #pragma unroll
    for (int i = 0; i < 6; i++) {
        v[i] = *(const float4*)(xr + lane*4 + i*128);
        s += v[i].x + v[i].y + v[i].z + v[i].w;
    }
    #pragma unroll
    for (int oo = 16; oo > 0; oo >>= 1) s += __shfl_xor_sync(0xFFFFFFFFu, s, oo);
    float mean = s * (1.0f / (float)DD);
    float vs = 0.0f;
    #pragma unroll
    for (int i = 0; i < 6; i++) {
        v[i].x -= mean; v[i].y -= mean; v[i].z -= mean; v[i].w -= mean;
        vs += v[i].x*v[i].x + v[i].y*v[i].y + v[i].z*v[i].z + v[i].w*v[i].w;
    }
    #pragma unroll
    for (int oo = 16; oo > 0; oo >>= 1) vs += __shfl_xor_sync(0xFFFFFFFFu, vs, oo);
    float rs = rsqrtf(vs * (1.0f / (float)DD) + 1e-5f);
    fp16* orow = o + (size_t)r * DD;
    #pragma unroll
    for (int i = 0; i < 6; i++) {
        int c = lane*4 + i*128;
        float4 gg = *(const float4*)(g + c);
        float4 bb = *(const float4*)(be + c);
        uint2 pk;
        pk.x = packh(__float2half(v[i].x * rs * gg.x + bb.x),
                     __float2half(v[i].y * rs * gg.y + bb.y));
        pk.y = packh(__float2half(v[i].z * rs * gg.z + bb.z),
                     __float2half(v[i].w * rs * gg.w + bb.w));
        *(uint2*)(orow + c) = pk;
    }
}

// ---------------- HMMA GEMM: 128x64 tile, K=64 per stage, 2-stage, 3 CTAs/SM ----------------
#define A_OFF 0
#define B_OFF 18432
#define STG_BYTES 27648
#define NSTG 2
#define GEMM_SMEM (NSTG*STG_BYTES)

__global__ __launch_bounds__(256, 3) void gemm_mma(
    const fp16* __restrict__ A, const fp16* __restrict__ B,
    const float* __restrict__ bias0, const float* __restrict__ bias1,
    const float* __restrict__ bias2,
    float* __restrict__ C, fp16* __restrict__ O,
    int Ntot, int Ktot, int op)
{
    extern __shared__ char dsmem[];
    uint32_t smem_u = smem_to_u32(dsmem);
    int tid = threadIdx.x;
    int lane = tid & 31;
    int wid = tid >> 5;
    int wm = wid & 3;
    int wn = wid >> 2;
    int bm = blockIdx.y * 128, bn = blockIdx.x * 64;

    uint32_t a_off = (uint32_t)((wm*32 + (lane & 15)) * 144 + 16 * (lane >> 4));
    uint32_t b_off = (uint32_t)((wn*32 + 8*((lane >> 4) & 1) + (lane & 7)) * 144
                                + 16 * ((lane >> 3) & 1));

    float acc[2][4][4];
    #pragma unroll
    for (int i = 0; i < 2; i++)
        #pragma unroll
        for (int j = 0; j < 4; j++)
            #pragma unroll
            for (int q = 0; q < 4; q++) acc[i][j][q] = 0.0f;

    int iters = Ktot >> 6;

    #define LOAD_STAGE(it, buf) do { \
        int k0 = (it) << 6; \
        uint32_t sb = smem_u + (buf) * STG_BYTES; \
        _Pragma("unroll") \
        for (int j = 0; j < 4; j++) { \
            int ci = tid + j * 256; \
            int row = ci >> 3, col = ci & 7; \
            cp_async16(sb + A_OFF + row*144 + col*16, A + (size_t)(bm + row) * Ktot + k0 + col*8); \
        } \
        _Pragma("unroll") \
        for (int j = 0; j < 2; j++) { \
            int ci = tid + j * 256; \
            int row = ci >> 3, col = ci & 7; \
            cp_async16(sb + B_OFF + row*144 + col*16, B + (size_t)(bn + row) * Ktot + k0 + col*8); \
        } \
    } while (0)

    LOAD_STAGE(0, 0); CP_COMMIT();
    if (iters > 1) { LOAD_STAGE(1, 1); } CP_COMMIT();

    for (int it = 0; it < iters; it++) {
        CP_WAIT1();
        __syncthreads();
        int buf = it & 1;
        uint32_t sA = smem_u + buf * STG_BYTES + A_OFF;
        uint32_t sB = smem_u + buf * STG_BYTES + B_OFF;
        #pragma unroll
        for (int ks = 0; ks < 4; ks++) {
            uint32_t a[2][4], b[2][4];
            #pragma unroll
            for (int tm = 0; tm < 2; tm++)
                ldsm4(a[tm], sA + a_off + tm*2304 + ks*32);
            #pragma unroll
            for (int p = 0; p < 2; p++)
                ldsm4(b[p], sB + b_off + p*2304 + ks*32);
            #pragma unroll
            for (int tm = 0; tm < 2; tm++)
                #pragma unroll
                for (int p = 0; p < 2; p++) {
                    mma_f16(acc[tm][2*p],   a[tm], &b[p][0]);
                    mma_f16(acc[tm][2*p+1], a[tm], &b[p][2]);
                }
        }
        __syncthreads();
        if (it + 2 < iters) LOAD_STAGE(it + 2, buf);
        CP_COMMIT();
    }
    #undef LOAD_STAGE

    const float* beff = bias0;
    int boff = 0;
    if (bias1 != nullptr) {
        if (bn >= 1536)      { beff = bias2; boff = 1536; }
        else if (bn >= 768)  { beff = bias1; boff = 768;  }
    }

    int m_base = bm + wm*32 + (lane >> 2);
    int n_base = bn + wn*32 + (lane & 3)*2;
    #pragma unroll
    for (int tm = 0; tm < 2; tm++) {
        #pragma unroll
        for (int tn = 0; tn < 4; tn++) {
            #pragma unroll
            for (int half = 0; half < 2; half++) {
                int m = m_base + tm*16 + half*8;
                int n = n_base + tn*8;
                float v0 = acc[tm][tn][2*half]     + beff[n - boff];
                float v1 = acc[tm][tn][2*half + 1] + beff[n + 1 - boff];
                size_t idx = (size_t)m * Ntot + n;
                if (op == 1) {
                    float gv0 = 0.5f * v0 * (1.0f + erff(v0 * 0.70710678118654752f));
                    float gv1 = 0.5f * v1 * (1.0f + erff(v1 * 0.70710678118654752f));
                    *(uint32_t*)(O + idx) = packh(__float2half(gv0), __float2half(gv1));
                } else if (op == 2) {
                    C[idx]     += v0;
                    C[idx + 1] += v1;
                } else {
                    *(uint32_t*)(O + idx) = packh(__float2half(v0), __float2half(v1));
                }
            }
        }
    }
}

// ---------------- tensor-core fused attention: 32-row Q tiles, 2 CTAs/SM ----------------
#define SSTR 520
#define OFF_Q  (32*SSTR*4)
#define OFF_K  (OFF_Q + 32*144)
#define ATTN_SMEM (OFF_K + 128*144)

__global__ __launch_bounds__(256, 2) void attn_tc(
    const fp16* __restrict__ QKV, const int* __restrict__ mask,
    float* __restrict__ attn_out, fp16* __restrict__ ao)
{
    extern __shared__ char sm[];
    float* S = (float*)sm;
    uint32_t su = smem_to_u32(sm);
    int tid = threadIdx.x, lane = tid & 31, wid = tid >> 5;
    int q0 = blockIdx.x * 32;
    int h = blockIdx.y, b = blockIdx.z;

    {
        int r = tid >> 3, c = tid & 7;
        size_t g = ((size_t)(b*LL + q0 + r)) * NQKV + h*DH;
        *(uint4*)(sm + OFF_Q + r*144 + c*16) = ((const uint4*)(QKV + g))[c];
    }

    for (int kc = 0; kc < 4; kc++) {
        {
            int r = tid >> 1, c0 = (tid & 1) * 4;
            size_t g = ((size_t)(b*LL + kc*128 + r)) * NQKV + 768 + h*DH;
            const uint4* gk = (const uint4*)(QKV + g);
            #pragma unroll
            for (int c = 0; c < 4; c++)
                *(uint4*)(sm + OFF_K + r*144 + (c0+c)*16) = gk[c0+c];
        }
        __syncthreads();
        float acc[2][2][4];
        #pragma unroll
        for (int i = 0; i < 2; i++)
            #pragma unroll
            for (int j = 0; j < 2; j++)
                #pragma unroll
                for (int q = 0; q < 4; q++) acc[i][j][q] = 0.0f;
        uint32_t aoff = (uint32_t)((lane & 15) * 144 + 16 * (lane >> 4));
        uint32_t boff = (uint32_t)((wid*16 + 8*((lane >> 4) & 1) + (lane & 7)) * 144
                                   + 16 * ((lane >> 3) & 1));
        #pragma unroll
        for (int ki = 0; ki < 4; ki++) {
            uint32_t a[2][4], bmat[4];
            ldsm4(a[0], su + OFF_Q + aoff + ki*32);
            ldsm4(a[1], su + OFF_Q + aoff + 2304 + ki*32);
            ldsm4(bmat, su + OFF_K + boff + ki*32);
            #pragma unroll
            for (int tm = 0; tm < 2; tm++) {
                mma_f16(acc[tm][0], a[tm], &bmat[0]);
                mma_f16(acc[tm][1], a[tm], &bmat[2]);
            }
        }
        #pragma unroll
        for (int tm = 0; tm < 2; tm++) {
            #pragma unroll
            for (int tn = 0; tn < 2; tn++) {
                int row = tm*16 + (lane >> 2);
                int col = kc*128 + wid*16 + tn*8 + (lane & 3)*2;
                int m0 = mask[b*LL + col], m1 = mask[b*LL + col + 1];
                #pragma unroll
                for (int half = 0; half < 2; half++) {
                    int rr = row + half*8;
                    float v0 = acc[tm][tn][2*half]   * 0.125f - 0.01f * (float)((q0 + rr) - col);
                    float v1 = acc[tm][tn][2*half+1] * 0.125f - 0.01f * (float)((q0 + rr) - (col+1));
                    if (m0 == 0) v0 = -INFINITY;
                    if (m1 == 0) v1 = -INFINITY;
                    S[rr*SSTR + col]     = v0;
                    S[rr*SSTR + col + 1] = v1;
                }
            }
        }
        __syncthreads();
    }

    {
        size_t gbase0 = ((size_t)(b*HH + h) * LL + q0) * LL;
        #pragma unroll
        for (int j = 0; j < 4; j++) {
            int r = wid*4 + j;
            float4 e[4];
            #pragma unroll
            for (int i = 0; i < 4; i++) e[i] = *(float4*)&S[r*SSTR + i*128 + lane*4];
            float mx = -1e30f;
            #pragma unroll
            for (int i = 0; i < 4; i++)
                mx = fmaxf(mx, fmaxf(fmaxf(e[i].x, e[i].y), fmaxf(e[i].z, e[i].w)));
            #pragma unroll
            for (int o = 16; o > 0; o >>= 1) mx = fmaxf(mx, __shfl_xor_sync(0xFFFFFFFFu, mx, o));
            float sum = 0.0f;
            #pragma unroll
            for (int i = 0; i < 4; i++) {
                e[i].x = __expf(e[i].x - mx); e[i].y = __expf(e[i].y - mx);
                e[i].z = __expf(e[i].z - mx); e[i].w = __expf(e[i].w - mx);
                sum += e[i].x + e[i].y + e[i].z + e[i].w;
            }
            #pragma unroll
            for (int o = 16; o > 0; o >>= 1) sum += __shfl_xor_sync(0xFFFFFFFFu, sum, o);
            float inv = 1.0f / sum;
            float* gp = attn_out + gbase0 + (size_t)r * LL;
            #pragma unroll
            for (int i = 0; i < 4; i++) {
                e[i].x *= inv; e[i].y *= inv; e[i].z *= inv; e[i].w *= inv;
                *(float4*)&S[r*SSTR + i*128 + lane*4] = e[i];
                *(float4*)(gp + i*128 + lane*4) = e[i];
            }
        }
    }
    __syncthreads();

    int wn4 = wid & 3, wk2 = wid >> 2;
    float oa[2][2][4];
    #pragma unroll
    for (int i = 0; i < 2; i++)
        #pragma unroll
        for (int j = 0; j < 2; j++)
            #pragma unroll
            for (int q = 0; q < 4; q++) oa[i][j][q] = 0.0f;

    uint32_t poff = (uint32_t)((lane & 15) * 144 + 16 * (lane >> 4));
    uint32_t voff = (uint32_t)((lane & 15) * 144 + wn4*32 + 16 * (lane >> 4));

    for (int kc = 0; kc < 8; kc++) {
        {
            int r = tid >> 3, c0 = (tid & 7) * 8;
            const float* sp = &S[r*SSTR + kc*64 + c0];
            float v[8];
            *(float4*)&v[0] = *(const float4*)sp;
            *(float4*)&v[4] = *(const float4*)(sp + 4);
            uint32_t hw[4];
            #pragma unroll
            for (int q = 0; q < 4; q++)
                hw[q] = packh(__float2half_rn(v[2*q]), __float2half_rn(v[2*q+1]));
            *(uint4*)(sm + OFF_Q + r*144 + c0*2) = *(uint4*)hw;
        }
        {
            int r = tid >> 2, c = tid & 3;
            size_t g = ((size_t)(b*LL + kc*64 + r)) * NQKV + 1536 + h*DH;
            const uint4* gv = (const uint4*)(QKV + g);
            *(uint4*)(sm + OFF_K + r*144 + c*16)     = gv[c];
            *(uint4*)(sm + OFF_K + r*144 + (c+4)*16) = gv[c+4];
        }
        __syncthreads();
        #pragma unroll
        for (int kj = 0; kj < 2; kj++) {
            int ki = wk2*2 + kj;
            uint32_t p[2][4], v[4];
            ldsm4(p[0], su + OFF_Q + poff + ki*32);
            ldsm4(p[1], su + OFF_Q + poff + 2304 + ki*32);
            ldsm4t(v, su + OFF_K + voff + ki*2304);
            #pragma unroll
            for (int tm = 0; tm < 2; tm++) {
                mma_f16(oa[tm][0], p[tm], &v[0]);
                mma_f16(oa[tm][1], p[tm], &v[2]);
            }
        }
        __syncthreads();
    }

    if (wk2 == 0) {
        #pragma unroll
        for (int tm = 0; tm < 2; tm++)
            #pragma unroll
            for (int tn = 0; tn < 2; tn++)
                #pragma unroll
                for (int half = 0; half < 2; half++) {
                    int row = tm*16 + (lane >> 2) + half*8;
                    int col = wn4*16 + tn*8 + (lane & 3)*2;
                    S[row*64 + col]     = oa[tm][tn][2*half];
                    S[row*64 + col + 1] = oa[tm][tn][2*half+1];
                }
    }
    __syncthreads();
    if (wk2 == 1) {
        #pragma unroll
        for (int tm = 0; tm < 2; tm++)
            #pragma unroll
            for (int tn = 0; tn < 2; tn++)
                #pragma unroll
                for (int half = 0; half < 2; half++) {
                    int row = tm*16 + (lane >> 2) + half*8;
                    int col = wn4*16 + tn*8 + (lane & 3)*2;
                    float v0 = oa[tm][tn][2*half]   + S[row*64 + col];
                    float v1 = oa[tm][tn][2*half+1] + S[row*64 + col + 1];
                    size_t g = ((size_t)(b*LL + q0 + row)) * DD + h*DH + col;
                    *(uint32_t*)(ao + g) = packh(__float2half(v0), __float2half(v1));
                }
    }
}

// ---------------- classifier head ----------------
__global__ void logits_kernel(const float* __restrict__ h, const float* __restrict__ Wc,
                              const float* __restrict__ bc, float* __restrict__ out) {
    __shared__ float red[256];
    int b = blockIdx.x;
    int t = threadIdx.x;
    float s = 0.0f;
    for (int d = t; d < DD; d += 256) s += h[(size_t)b * LL * DD + d] * Wc[d * NC];
    red[t] = s; __syncthreads();
    for (int o = 128; o > 0; o >>= 1) { if (t < o) red[t] += red[t + o]; __syncthreads(); }
    if (t == 0) out[b * NC] = red[0] + bc[0];
}

// ---------------- launcher ----------------
extern "C" void kernel_launch(void* const* d_in, const int* in_sizes, int n_in,
                              void* d_out, int out_size) {
    const int*   x    = (const int*)  d_in[0];
    const int*   mask = (const int*)  d_in[1];
    const float* emb  = (const float*)d_in[2];
    const float* Wq   = (const float*)d_in[3];
    const float* bq   = (const float*)d_in[4];
    const float* Wk   = (const float*)d_in[5];
    const float* bk   = (const float*)d_in[6];
    const float* Wv   = (const float*)d_in[7];
    const float* bv   = (const float*)d_in[8];
    const float* Wo   = (const float*)d_in[9];
    const float* bo   = (const float*)d_in[10];
    const float* W1   = (const float*)d_in[11];
    const float* b1   = (const float*)d_in[12];
    const float* W2   = (const float*)d_in[13];
    const float* b2   = (const float*)d_in[14];
    const float* g1   = (const float*)d_in[15];
    const float* be1  = (const float*)d_in[16];
    const float* g2   = (const float*)d_in[17];
    const float* be2  = (const float*)d_in[18];
    const float* Wc   = (const float*)d_in[19];
    const float* bc   = (const float*)d_in[20];

    float* out = (float*)d_out;
    float* logits = out;
    float* attn_base = out + (size_t)BB * NC;

    static bool attr_set = false;
    if (!attr_set) {
        cudaFuncSetAttribute(gemm_mma, cudaFuncAttributeMaxDynamicSharedMemorySize, GEMM_SMEM);
        cudaFuncSetAttribute(attn_tc, cudaFuncAttributeMaxDynamicSharedMemorySize, ATTN_SMEM);
        attr_set = true;
    }

    float *p_h;
    fp16 *p_xn, *p_qkv, *p_ao, *p_ff, *p_wqkv, *p_wo, *p_w1, *p_w2;
    cudaGetSymbolAddress((void**)&p_h, g_h);
    cudaGetSymbolAddress((void**)&p_xn, g_xn);
    cudaGetSymbolAddress((void**)&p_qkv, g_qkv);
    cudaGetSymbolAddress((void**)&p_ao, g_ao);
    cudaGetSymbolAddress((void**)&p_ff, g_ff);
    cudaGetSymbolAddress((void**)&p_wqkv, g_wqkv);
    cudaGetSymbolAddress((void**)&p_wo, g_wo);
    cudaGetSymbolAddress((void**)&p_w1, g_w1);
    cudaGetSymbolAddress((void**)&p_w2, g_w2);

    dim3 tb(32, 8);
    size_t olsQKV = (size_t)NQKV * DD;

    dim3 gD(DD/64, MM/128);
    dim3 gQKV(NQKV/64, MM/128);
    dim3 gF(FF/64, MM/128);
    dim3 gAttn(LL/32, HH, BB);

    tsplit_qkv<<<dim3(DD/32, DD/32, NL*3), tb>>>(Wq, Wk, Wv, p_wqkv);
    embed_kernel<<<MM, 256>>>(x, emb, p_h);

    for (int l = 0; l < NL; l++) {
        size_t wD = (size_t)l * DD * DD;
        size_t wF = (size_t)l * DD * FF;
        size_t wQ = (size_t)l * olsQKV;
        ln_kernel<<<MM/8, 256>>>(p_h, g1 + l*DD, be1 + l*DD, p_xn);
        gemm_mma<<<gQKV, 256, GEMM_SMEM>>>(p_xn, p_wqkv + wQ,
                                           bq + l*DD, bk + l*DD, bv + l*DD,
                                           nullptr, p_qkv, NQKV, DD, 3);
        if (l == 0) {
            tsplit_kernel<<<dim3(DD/32, DD/32, NL), tb>>>(Wo, p_wo, DD, DD, 0, (size_t)DD*DD);
            tsplit_kernel<<<dim3(FF/32, DD/32, NL), tb>>>(W1, p_w1, DD, FF, 0, (size_t)DD*FF);
            tsplit_kernel<<<dim3(DD/32, FF/32, NL), tb>>>(W2, p_w2, FF, DD, 0, (size_t)FF*DD);
        }
        attn_tc<<<gAttn, 256, ATTN_SMEM>>>(p_qkv, mask,
                                           attn_base + (size_t)l * BB * HH * LL * LL, p_ao);
        gemm_mma<<<gD, 256, GEMM_SMEM>>>(p_ao, p_wo + wD,
                                         bo + l*DD, nullptr, nullptr,
                                         p_h, nullptr, DD, DD, 2);
        ln_kernel<<<MM/8, 256>>>(p_h, g2 + l*DD, be2 + l*DD, p_xn);
        gemm_mma<<<gF, 256, GEMM_SMEM>>>(p_xn, p_w1 + wF,
                                         b1 + l*FF, nullptr, nullptr,
                                         nullptr, p_ff, FF, DD, 1);
        gemm_mma<<<gD, 256, GEMM_SMEM>>>(p_ff, p_w2 + wF,
                                         b2 + l*DD, nullptr, nullptr,
                                         p_h, nullptr, DD, FF, 2);
    }

    logits_kernel<<<BB, 256>>>(p_h, Wc, bc, logits);
}